// round 6
// baseline (speedup 1.0000x reference)
#include <cuda_runtime.h>
#include <cstdint>

#define BB  4
#define QQ  512
#define MM  512
#define PPQ 128
#define HID 1024
#define HH  16
#define SS  64
#define RR  1024
#define RP  1536

// -------- scratch --------
__device__ float g_ctx[BB*RR*HID];
__device__ float g_kc [BB*RR*HID];
__device__ float g_v  [BB*RR*HID];
__device__ float g_kp [BB*RP*HID];
__device__ float g_qc [BB*QQ*HID];
__device__ float g_qq [BB*PPQ*HID];
__device__ float g_ac [BB*QQ*HID];
__device__ float g_aq [BB*PPQ*HID];
__device__ int   g_tpos[BB*PPQ];

// ================= helpers =================
__device__ __forceinline__ uint32_t smem_u32(const void* p){
    uint32_t a;
    asm("{ .reg .u64 t; cvta.to.shared.u64 t, %1; cvt.u32.u64 %0, t; }" : "=r"(a) : "l"(p));
    return a;
}
__device__ __forceinline__ void cpasync16(uint32_t s, const void* g){
    asm volatile("cp.async.cg.shared.global [%0], [%1], 16;" :: "r"(s), "l"(g));
}
__device__ __forceinline__ void cpasync_commit(){ asm volatile("cp.async.commit_group;" ::: "memory"); }
__device__ __forceinline__ void cpasync_wait0(){ asm volatile("cp.async.wait_group 0;" ::: "memory"); }
__device__ __forceinline__ void split_tf32(float x, uint32_t& hi, uint32_t& lo){
    uint32_t h;
    asm("cvt.rna.tf32.f32 %0, %1;" : "=r"(h) : "f"(x));
    float r = x - __uint_as_float(h);
    uint32_t l;
    asm("cvt.rna.tf32.f32 %0, %1;" : "=r"(l) : "f"(r));
    hi = h; lo = l;
}
__device__ __forceinline__ void mma_tf32(float* c, const uint32_t* a, const uint32_t* b){
    asm volatile("mma.sync.aligned.m16n8k8.row.col.f32.tf32.tf32.f32 "
        "{%0,%1,%2,%3}, {%4,%5,%6,%7}, {%8,%9}, {%0,%1,%2,%3};"
        : "+f"(c[0]),"+f"(c[1]),"+f"(c[2]),"+f"(c[3])
        : "r"(a[0]),"r"(a[1]),"r"(a[2]),"r"(a[3]), "r"(b[0]),"r"(b[1]));
}
__device__ __forceinline__ void mma3(float* c, const uint32_t* ah, const uint32_t* al,
                                     const uint32_t* bh, const uint32_t* bl){
    mma_tf32(c, ah, bh);
    mma_tf32(c, ah, bl);
    mma_tf32(c, al, bh);
}

// ================= misc kernels =================
__global__ void build_ctx(const float* __restrict__ mems, const float* __restrict__ content)
{
    int idx = blockIdx.x * blockDim.x + threadIdx.x;
    const int total = BB*RR*HID/4;
    if (idx >= total) return;
    int d4  = idx & (HID/4 - 1);
    int row = idx / (HID/4);
    int n = row >> 10, r = row & 1023;
    const float* src = (r < MM) ? (mems + ((size_t)n*MM + r)*HID)
                                : (content + ((size_t)n*QQ + (r-MM))*HID);
    ((float4*)g_ctx)[idx] = ((const float4*)src)[d4];
}

__global__ void find_tpos(const float* __restrict__ tm)
{
    int i = threadIdx.x;
    const float* row = tm + (size_t)i * QQ;
    int q = 0;
    for (int j = 0; j < QQ; j++) if (row[j] > 0.5f) q = j;
    g_tpos[i] = q;
}

// ================= 3xTF32 mma GEMM =================
// C[m,1024] = A[m,1024] @ W[1024,1024] (W row-major [k][n])
__global__ __launch_bounds__(256, 2) void gemm_mma(const float* __restrict__ A,
                                                   const float* __restrict__ W,
                                                   float* __restrict__ C)
{
    __shared__ float As[2][128][20];
    __shared__ float Bs[2][16][136];

    const int tid  = threadIdx.x;
    const int wid  = tid >> 5, lane = tid & 31;
    const int wm   = wid & 3,  wn   = wid >> 2;
    const int g    = lane >> 2, t   = lane & 3;
    const int m0   = blockIdx.y * 128;
    const int n0   = blockIdx.x * 128;

    const uint32_t sA = smem_u32(As);
    const uint32_t sB = smem_u32(Bs);

    float c[2][8][4];
#pragma unroll
    for (int i = 0; i < 2; i++)
#pragma unroll
        for (int j = 0; j < 8; j++)
#pragma unroll
            for (int l = 0; l < 4; l++) c[i][j][l] = 0.f;

    auto load_tile = [&](int kt, int buf){
#pragma unroll
        for (int i = 0; i < 2; i++) {
            int idx = tid + i*256;
            int row = idx >> 2, k4 = idx & 3;
            cpasync16(sA + (uint32_t)buf*10240u + row*80u + k4*16u,
                      A + (size_t)(m0 + row)*1024 + kt + k4*4);
        }
#pragma unroll
        for (int i = 0; i < 2; i++) {
            int idx = tid + i*256;
            int kk = idx >> 5, n4 = idx & 31;
            cpasync16(sB + (uint32_t)buf*8704u + kk*544u + n4*16u,
                      W + (size_t)(kt + kk)*1024 + n0 + n4*4);
        }
        cpasync_commit();
    };

    load_tile(0, 0);
    cpasync_wait0();
    __syncthreads();

    for (int kt = 0; kt < 64; kt++) {
        int buf = kt & 1;
        if (kt + 1 < 64) load_tile((kt + 1)*16, buf ^ 1);

#pragma unroll
        for (int ks = 0; ks < 16; ks += 8) {
            uint32_t ah[2][4], al[2][4];
#pragma unroll
            for (int mt = 0; mt < 2; mt++) {
                int mr = wm*32 + mt*16 + g;
                split_tf32(As[buf][mr    ][ks + t    ], ah[mt][0], al[mt][0]);
                split_tf32(As[buf][mr + 8][ks + t    ], ah[mt][1], al[mt][1]);
                split_tf32(As[buf][mr    ][ks + t + 4], ah[mt][2], al[mt][2]);
                split_tf32(As[buf][mr + 8][ks + t + 4], ah[mt][3], al[mt][3]);
            }
#pragma unroll
            for (int nt = 0; nt < 8; nt++) {
                int nc = wn*64 + nt*8 + g;
                uint32_t bh[2], bl[2];
                split_tf32(Bs[buf][ks + t    ][nc], bh[0], bl[0]);
                split_tf32(Bs[buf][ks + t + 4][nc], bh[1], bl[1]);
#pragma unroll
                for (int mt = 0; mt < 2; mt++)
                    mma3(c[mt][nt], ah[mt], al[mt], bh, bl);
            }
        }

        cpasync_wait0();
        __syncthreads();
    }

#pragma unroll
    for (int mt = 0; mt < 2; mt++) {
        int row = m0 + wm*32 + mt*16 + g;
#pragma unroll
        for (int nt = 0; nt < 8; nt++) {
            int col = n0 + wn*64 + nt*8 + 2*t;
            *(float2*)(C + (size_t)row*1024 + col)       = make_float2(c[mt][nt][0], c[mt][nt][1]);
            *(float2*)(C + (size_t)(row + 8)*1024 + col) = make_float2(c[mt][nt][2], c[mt][nt][3]);
        }
    }
}

// ================= tensor-core fused attention =================
// pitches chosen for conflict-free fragment LDS
#define LP  1044
#define KTP 68
#define QP  68
#define ATTN_SMEM_FLOATS (16*LP + 128*KTP + 2*16*QP + 48)
#define ATTN_SMEM_BYTES  (ATTN_SMEM_FLOATS*4)

__global__ __launch_bounds__(256) void attn_kernel(
                            const float* __restrict__ Qp, int NQ,
                            const float* __restrict__ KC, const float* __restrict__ V,
                            const float* __restrict__ KP,
                            const float* __restrict__ segenc,
                            const int* __restrict__ segmat,
                            const float* __restrict__ mask,
                            const float* __restrict__ cb, const float* __restrict__ pb,
                            const float* __restrict__ sb,
                            const int* __restrict__ tpos,
                            float* __restrict__ Out)
{
    extern __shared__ float sm[];
    float* logits = sm;                  // 16 x LP
    float* kt     = sm + 16*LP;          // 128 x KTP
    float* qcs    = kt + 128*KTP;        // 16 x QP
    float* qps    = qcs + 16*QP;         // 16 x QP
    float* seg0   = qps + 16*QP;         // 16
    float* seg1   = seg0 + 16;           // 16
    int*   qrow   = (int*)(seg1 + 16);   // 16

    const int n  = blockIdx.z, h = blockIdx.y;
    const int q0 = blockIdx.x * 16;
    const int tid = threadIdx.x;
    const int wid = tid >> 5, lane = tid & 31;
    const int g = lane >> 2, t = lane & 3;

    for (int u = tid; u < 16*64; u += 256) {
        int l = u >> 6, s = u & 63;
        float qv = Qp[(((size_t)n*NQ + q0 + l)*HH + h)*SS + s];
        qcs[l*QP + s] = qv + cb[h*SS + s];
        qps[l*QP + s] = qv + pb[h*SS + s];
    }
    if (tid < 16) qrow[tid] = tpos ? tpos[n*PPQ + q0 + tid] : (q0 + tid);
    if (tid >= 32 && tid < 64) {
        int i = tid - 32;
        int l = i >> 1, gg = i & 1;
        float acc = 0.f;
        const float* qr = Qp + (((size_t)n*NQ + q0 + l)*HH + h)*SS;
        const float* se = segenc + ((size_t)gg*HH + h)*SS;
        for (int s = 0; s < SS; s++) acc += (qr[s] + sb[h*SS + s]) * se[s];
        if (gg) seg1[l] = acc; else seg0[l] = acc;
    }
    __syncthreads();

    // ---- Phase A1: content logits via mma; warp wid covers r in [wid*16, wid*16+16) of tile ----
    for (int rt = 0; rt < 8; rt++) {
        for (int u = tid; u < 128*16; u += 256) {
            int rl = u >> 4, s4 = u & 15;
            float4 v = *(const float4*)(KC + ((((size_t)n*RR + rt*128 + rl)*HH + h) << 6) + s4*4);
            float* d = kt + rl*KTP + s4*4;
            d[0]=v.x; d[1]=v.y; d[2]=v.z; d[3]=v.w;
        }
        __syncthreads();
        float c[2][4] = {{0,0,0,0},{0,0,0,0}};
#pragma unroll
        for (int ks = 0; ks < 8; ks++) {
            int s0 = ks*8;
            uint32_t ah[4], al[4];
            split_tf32(qcs[g*QP       + s0 + t    ], ah[0], al[0]);
            split_tf32(qcs[(g+8)*QP   + s0 + t    ], ah[1], al[1]);
            split_tf32(qcs[g*QP       + s0 + t + 4], ah[2], al[2]);
            split_tf32(qcs[(g+8)*QP   + s0 + t + 4], ah[3], al[3]);
#pragma unroll
            for (int j = 0; j < 2; j++) {
                int r0 = wid*16 + j*8;
                uint32_t bh[2], bl[2];
                split_tf32(kt[(r0+g)*KTP + s0 + t    ], bh[0], bl[0]);
                split_tf32(kt[(r0+g)*KTP + s0 + t + 4], bh[1], bl[1]);
                mma3(c[j], ah, al, bh, bl);
            }
        }
#pragma unroll
        for (int j = 0; j < 2; j++) {
            int base = rt*128 + wid*16 + j*8 + 2*t;
            logits[g*LP     + base    ] = c[j][0];
            logits[g*LP     + base + 1] = c[j][1];
            logits[(g+8)*LP + base    ] = c[j][2];
            logits[(g+8)*LP + base + 1] = c[j][3];
        }
        __syncthreads();
    }

    // ---- Phase A2: position logits via mma, rel-shift scatter-add ----
    {
        int qp0 = qrow[g], qp1 = qrow[g+8];
        for (int pt = 0; pt < 12; pt++) {
            for (int u = tid; u < 128*16; u += 256) {
                int rl = u >> 4, s4 = u & 15;
                float4 v = *(const float4*)(KP + ((((size_t)n*RP + pt*128 + rl)*HH + h) << 6) + s4*4);
                float* d = kt + rl*KTP + s4*4;
                d[0]=v.x; d[1]=v.y; d[2]=v.z; d[3]=v.w;
            }
            __syncthreads();
            float c[2][4] = {{0,0,0,0},{0,0,0,0}};
#pragma unroll
            for (int ks = 0; ks < 8; ks++) {
                int s0 = ks*8;
                uint32_t ah[4], al[4];
                split_tf32(qps[g*QP     + s0 + t    ], ah[0], al[0]);
                split_tf32(qps[(g+8)*QP + s0 + t    ], ah[1], al[1]);
                split_tf32(qps[g*QP     + s0 + t + 4], ah[2], al[2]);
                split_tf32(qps[(g+8)*QP + s0 + t + 4], ah[3], al[3]);
#pragma unroll
                for (int j = 0; j < 2; j++) {
                    int r0 = wid*16 + j*8;
                    uint32_t bh[2], bl[2];
                    split_tf32(kt[(r0+g)*KTP + s0 + t    ], bh[0], bl[0]);
                    split_tf32(kt[(r0+g)*KTP + s0 + t + 4], bh[1], bl[1]);
                    mma3(c[j], ah, al, bh, bl);
                }
            }
#pragma unroll
            for (int j = 0; j < 2; j++) {
                int pp = pt*128 + wid*16 + j*8 + 2*t;
                int r;
                r = pp     - 512 + qp0; if (r >= 0 && r < RR) logits[g*LP + r]     += c[j][0];
                r = pp + 1 - 512 + qp0; if (r >= 0 && r < RR) logits[g*LP + r]     += c[j][1];
                r = pp     - 512 + qp1; if (r >= 0 && r < RR) logits[(g+8)*LP + r] += c[j][2];
                r = pp + 1 - 512 + qp1; if (r >= 0 && r < RR) logits[(g+8)*LP + r] += c[j][3];
            }
            __syncthreads();
        }
    }

    // ---- Phase A3: segment + mask + scale + softmax ----
    {
        int lq = tid >> 4, lane16 = tid & 15;
        int qq = qrow[lq];
        const float* mrow = mask + ((size_t)n*QQ + qq)*RR;
        const int* srow = segmat + ((size_t)n*QQ + qq)*RR;
        float s1v = seg1[lq], s0v = seg0[lq];
        float* lrow = logits + lq*LP;
        float mx = -3.4e38f;
        for (int i = 0; i < 64; i++) {
            int cc = lane16 + 16*i;
            float lg = lrow[cc] + (srow[cc] ? s1v : s0v);
            lg = lg * 0.125f + mrow[cc] * (-1e9f);
            lrow[cc] = lg;
            mx = fmaxf(mx, lg);
        }
        for (int o = 8; o; o >>= 1) mx = fmaxf(mx, __shfl_xor_sync(0xffffffffu, mx, o, 16));
        float sum = 0.f;
        for (int i = 0; i < 64; i++) {
            int cc = lane16 + 16*i;
            float e = __expf(lrow[cc] - mx);
            lrow[cc] = e;
            sum += e;
        }
        for (int o = 8; o; o >>= 1) sum += __shfl_xor_sync(0xffffffffu, sum, o, 16);
        float inv = __fdividef(1.f, sum);
        for (int i = 0; i < 64; i++) lrow[lane16 + 16*i] *= inv;
    }

    // ---- Phase B: out = weights @ V via mma; warp wid covers s in [wid*8, wid*8+8) ----
    {
        float cacc[4] = {0,0,0,0};
        for (int rt = 0; rt < 8; rt++) {
            __syncthreads();
            for (int u = tid; u < 128*16; u += 256) {
                int rl = u >> 4, s4 = u & 15;
                float4 v = *(const float4*)(V + ((((size_t)n*RR + rt*128 + rl)*HH + h) << 6) + s4*4);
                float* d = kt + rl*KTP + s4*4;
                d[0]=v.x; d[1]=v.y; d[2]=v.z; d[3]=v.w;
            }
            __syncthreads();
#pragma unroll
            for (int ks = 0; ks < 16; ks++) {
                int k0 = ks*8;
                int col0 = rt*128 + k0;
                uint32_t ah[4], al[4];
                split_tf32(logits[g*LP     + col0 + t    ], ah[0], al[0]);
                split_tf32(logits[(g+8)*LP + col0 + t    ], ah[1], al[1]);
                split_tf32(logits[g*LP     + col0 + t + 4], ah[2], al[2]);
                split_tf32(logits[(g+8)*LP + col0 + t + 4], ah[3], al[3]);
                uint32_t bh[2], bl[2];
                split_tf32(kt[(k0+t)*KTP   + wid*8 + g], bh[0], bl[0]);
                split_tf32(kt[(k0+t+4)*KTP + wid*8 + g], bh[1], bl[1]);
                mma3(cacc, ah, al, bh, bl);
            }
        }
        size_t ob0 = (((size_t)n*NQ + q0 + g)*HH + h)*SS + wid*8 + 2*t;
        size_t ob1 = (((size_t)n*NQ + q0 + g + 8)*HH + h)*SS + wid*8 + 2*t;
        *(float2*)(Out + ob0) = make_float2(cacc[0], cacc[1]);
        *(float2*)(Out + ob1) = make_float2(cacc[2], cacc[3]);
    }
}

// -------------------- launch --------------------
extern "C" void kernel_launch(void* const* d_in, const int* in_sizes, int n_in,
                              void* d_out, int out_size)
{
    const float* content = (const float*)d_in[0];
    const float* query   = (const float*)d_in[1];
    const float* posenc  = (const float*)d_in[2];
    const float* segenc  = (const float*)d_in[3];
    const int*   segmat  = (const int*)d_in[4];
    const float* tmap    = (const float*)d_in[5];
    const float* cmask   = (const float*)d_in[6];
    const float* qmask   = (const float*)d_in[7];
    const float* cb      = (const float*)d_in[8];
    const float* pb      = (const float*)d_in[9];
    const float* sb      = (const float*)d_in[10];
    const float* mems    = (const float*)d_in[11];
    const float* Wq      = (const float*)d_in[12];
    const float* Wkc     = (const float*)d_in[13];
    const float* Wv      = (const float*)d_in[14];
    const float* Wkp     = (const float*)d_in[15];
    const float* Wo      = (const float*)d_in[16];
    float* out = (float*)d_out;

    float *p_ctx, *p_kc, *p_v, *p_kp, *p_qc, *p_qq, *p_ac, *p_aq;
    int* p_tpos;
    cudaGetSymbolAddress((void**)&p_ctx, g_ctx);
    cudaGetSymbolAddress((void**)&p_kc,  g_kc);
    cudaGetSymbolAddress((void**)&p_v,   g_v);
    cudaGetSymbolAddress((void**)&p_kp,  g_kp);
    cudaGetSymbolAddress((void**)&p_qc,  g_qc);
    cudaGetSymbolAddress((void**)&p_qq,  g_qq);
    cudaGetSymbolAddress((void**)&p_ac,  g_ac);
    cudaGetSymbolAddress((void**)&p_aq,  g_aq);
    cudaGetSymbolAddress((void**)&p_tpos, g_tpos);

    cudaFuncSetAttribute(attn_kernel, cudaFuncAttributeMaxDynamicSharedMemorySize, ATTN_SMEM_BYTES);

    build_ctx<<<(BB*RR*HID/4 + 255)/256, 256>>>(mems, content);
    find_tpos<<<1, 512>>>(tmap);

    gemm_mma<<<dim3(8, 32), 256>>>(p_ctx,   Wkc, p_kc);
    gemm_mma<<<dim3(8, 32), 256>>>(p_ctx,   Wv,  p_v);
    gemm_mma<<<dim3(8, 48), 256>>>(posenc,  Wkp, p_kp);
    gemm_mma<<<dim3(8, 16), 256>>>(content, Wq,  p_qc);
    gemm_mma<<<dim3(8, 4),  256>>>(query,   Wq,  p_qq);

    dim3 gac(QQ/16, HH, BB);
    attn_kernel<<<gac, 256, ATTN_SMEM_BYTES>>>(p_qc, QQ, p_kc, p_v, p_kp, segenc, segmat,
                                               cmask, cb, pb, sb, nullptr, p_ac);
    dim3 gaq(PPQ/16, HH, BB);
    attn_kernel<<<gaq, 256, ATTN_SMEM_BYTES>>>(p_qq, PPQ, p_kc, p_v, p_kp, segenc, segmat,
                                               qmask, cb, pb, sb, p_tpos, p_aq);

    gemm_mma<<<dim3(8, 16), 256>>>(p_ac, Wo, out);
    gemm_mma<<<dim3(8, 4),  256>>>(p_aq, Wo, out + (size_t)BB*QQ*HID);
}

// round 7
// speedup vs baseline: 1.0408x; 1.0408x over previous
#include <cuda_runtime.h>
#include <cstdint>

#define BB  4
#define QQ  512
#define MM  512
#define PPQ 128
#define HID 1024
#define HH  16
#define SS  64
#define RR  1024
#define RP  1536
#define QT  32

// -------- scratch --------
__device__ float g_ctx[BB*RR*HID];
__device__ float g_kc [BB*RR*HID];   // [n][h][r][64]
__device__ float g_v  [BB*RR*HID];   // [n][h][r][64]
__device__ float g_kp [BB*RP*HID];   // [n][h][p][64]
__device__ float g_qc [BB*QQ*HID];   // [n][h][q][64]
__device__ float g_qq [BB*PPQ*HID];  // [n][h][q][64]
__device__ float g_ac [BB*QQ*HID];   // [n][q][h][64]
__device__ float g_aq [BB*PPQ*HID];
__device__ int   g_tpos[BB*PPQ];

// ================= helpers =================
__device__ __forceinline__ void cpasync16(uint32_t s, const void* g){
    asm volatile("cp.async.cg.shared.global [%0], [%1], 16;" :: "r"(s), "l"(g));
}
__device__ __forceinline__ uint32_t smem_u32(const void* p){
    uint32_t a;
    asm("{ .reg .u64 t; cvta.to.shared.u64 t, %1; cvt.u32.u64 %0, t; }" : "=r"(a) : "l"(p));
    return a;
}
__device__ __forceinline__ void cpasync_commit(){ asm volatile("cp.async.commit_group;" ::: "memory"); }
__device__ __forceinline__ void cpasync_wait0(){ asm volatile("cp.async.wait_group 0;" ::: "memory"); }
__device__ __forceinline__ uint32_t f2tf32(float x){
    uint32_t r;
    asm("cvt.rna.tf32.f32 %0, %1;" : "=r"(r) : "f"(x));
    return r;
}
__device__ __forceinline__ void split_tf32(float x, uint32_t& hi, uint32_t& lo){
    uint32_t h;
    asm("cvt.rna.tf32.f32 %0, %1;" : "=r"(h) : "f"(x));
    float r = x - __uint_as_float(h);
    uint32_t l;
    asm("cvt.rna.tf32.f32 %0, %1;" : "=r"(l) : "f"(r));
    hi = h; lo = l;
}
__device__ __forceinline__ void mma_tf32(float* c, const uint32_t* a, const uint32_t* b){
    asm volatile("mma.sync.aligned.m16n8k8.row.col.f32.tf32.tf32.f32 "
        "{%0,%1,%2,%3}, {%4,%5,%6,%7}, {%8,%9}, {%0,%1,%2,%3};"
        : "+f"(c[0]),"+f"(c[1]),"+f"(c[2]),"+f"(c[3])
        : "r"(a[0]),"r"(a[1]),"r"(a[2]),"r"(a[3]), "r"(b[0]),"r"(b[1]));
}
__device__ __forceinline__ void mma3(float* c, const uint32_t* ah, const uint32_t* al,
                                     const uint32_t* bh, const uint32_t* bl){
    mma_tf32(c, ah, bh);
    mma_tf32(c, ah, bl);
    mma_tf32(c, al, bh);
}

// ================= misc kernels =================
__global__ void build_ctx(const float* __restrict__ mems, const float* __restrict__ content)
{
    int idx = blockIdx.x * blockDim.x + threadIdx.x;
    const int total = BB*RR*HID/4;
    if (idx >= total) return;
    int d4  = idx & (HID/4 - 1);
    int row = idx / (HID/4);
    int n = row >> 10, r = row & 1023;
    const float* src = (r < MM) ? (mems + ((size_t)n*MM + r)*HID)
                                : (content + ((size_t)n*QQ + (r-MM))*HID);
    ((float4*)g_ctx)[idx] = ((const float4*)src)[d4];
}

__global__ void find_tpos(const float* __restrict__ tm)
{
    int i = threadIdx.x;
    const float* row = tm + (size_t)i * QQ;
    int q = 0;
    for (int j = 0; j < QQ; j++) if (row[j] > 0.5f) q = j;
    g_tpos[i] = q;
}

// ================= 3xTF32 mma GEMM =================
// C = A[rows,1024] @ W[1024,1024]; if relayout: C[((n*16+h)*rowsPB + r)*64 + s]
__global__ __launch_bounds__(256, 2) void gemm_mma(const float* __restrict__ A,
                                                   const float* __restrict__ W,
                                                   float* __restrict__ C,
                                                   int rowsPB, int relayout)
{
    __shared__ float As[2][128][20];
    __shared__ float Bs[2][16][136];

    const int tid  = threadIdx.x;
    const int wid  = tid >> 5, lane = tid & 31;
    const int wm   = wid & 3,  wn   = wid >> 2;
    const int g    = lane >> 2, t   = lane & 3;
    const int m0   = blockIdx.y * 128;
    const int n0   = blockIdx.x * 128;

    const uint32_t sA = smem_u32(As);
    const uint32_t sB = smem_u32(Bs);

    float c[2][8][4];
#pragma unroll
    for (int i = 0; i < 2; i++)
#pragma unroll
        for (int j = 0; j < 8; j++)
#pragma unroll
            for (int l = 0; l < 4; l++) c[i][j][l] = 0.f;

    auto load_tile = [&](int kt, int buf){
#pragma unroll
        for (int i = 0; i < 2; i++) {
            int idx = tid + i*256;
            int row = idx >> 2, k4 = idx & 3;
            cpasync16(sA + (uint32_t)buf*10240u + row*80u + k4*16u,
                      A + (size_t)(m0 + row)*1024 + kt + k4*4);
        }
#pragma unroll
        for (int i = 0; i < 2; i++) {
            int idx = tid + i*256;
            int kk = idx >> 5, n4 = idx & 31;
            cpasync16(sB + (uint32_t)buf*8704u + kk*544u + n4*16u,
                      W + (size_t)(kt + kk)*1024 + n0 + n4*4);
        }
        cpasync_commit();
    };

    load_tile(0, 0);
    cpasync_wait0();
    __syncthreads();

    for (int kt = 0; kt < 64; kt++) {
        int buf = kt & 1;
        if (kt + 1 < 64) load_tile((kt + 1)*16, buf ^ 1);

#pragma unroll
        for (int ks = 0; ks < 16; ks += 8) {
            uint32_t ah[2][4], al[2][4];
#pragma unroll
            for (int mt = 0; mt < 2; mt++) {
                int mr = wm*32 + mt*16 + g;
                split_tf32(As[buf][mr    ][ks + t    ], ah[mt][0], al[mt][0]);
                split_tf32(As[buf][mr + 8][ks + t    ], ah[mt][1], al[mt][1]);
                split_tf32(As[buf][mr    ][ks + t + 4], ah[mt][2], al[mt][2]);
                split_tf32(As[buf][mr + 8][ks + t + 4], ah[mt][3], al[mt][3]);
            }
#pragma unroll
            for (int nt = 0; nt < 8; nt++) {
                int nc = wn*64 + nt*8 + g;
                uint32_t bh[2], bl[2];
                split_tf32(Bs[buf][ks + t    ][nc], bh[0], bl[0]);
                split_tf32(Bs[buf][ks + t + 4][nc], bh[1], bl[1]);
#pragma unroll
                for (int mt = 0; mt < 2; mt++)
                    mma3(c[mt][nt], ah[mt], al[mt], bh, bl);
            }
        }

        cpasync_wait0();
        __syncthreads();
    }

#pragma unroll
    for (int mt = 0; mt < 2; mt++) {
        int rowg = m0 + wm*32 + mt*16 + g;
#pragma unroll
        for (int nt = 0; nt < 8; nt++) {
            int col = n0 + wn*64 + nt*8 + 2*t;
            if (relayout) {
                int nn = rowg / rowsPB, r = rowg % rowsPB;
                int hh = col >> 6, ss = col & 63;
                float* d0 = C + ((size_t)(nn*HH + hh)*rowsPB + r)*64 + ss;
                float* d1 = C + ((size_t)(nn*HH + hh)*rowsPB + r + 8)*64 + ss;
                *(float2*)d0 = make_float2(c[mt][nt][0], c[mt][nt][1]);
                *(float2*)d1 = make_float2(c[mt][nt][2], c[mt][nt][3]);
            } else {
                *(float2*)(C + (size_t)rowg*1024 + col)       = make_float2(c[mt][nt][0], c[mt][nt][1]);
                *(float2*)(C + (size_t)(rowg + 8)*1024 + col) = make_float2(c[mt][nt][2], c[mt][nt][3]);
            }
        }
    }
}

// ================= tensor-core fused attention, 32-q tiles =================
#define LP  1044
#define KTP 68
#define QP  68
#define ATTN_SMEM_FLOATS (QT*LP + 128*KTP + 2*QT*QP + 96)
#define ATTN_SMEM_BYTES  (ATTN_SMEM_FLOATS*4)

__global__ __launch_bounds__(256) void attn_kernel(
                            const float* __restrict__ Qp, int NQ,
                            const float* __restrict__ KC, const float* __restrict__ V,
                            const float* __restrict__ KP,
                            const float* __restrict__ segenc,
                            const int* __restrict__ segmat,
                            const float* __restrict__ mask,
                            const float* __restrict__ cb, const float* __restrict__ pb,
                            const float* __restrict__ sb,
                            const int* __restrict__ tpos,
                            float* __restrict__ Out)
{
    extern __shared__ float sm[];
    float* logits = sm;                  // QT x LP
    float* kt     = sm + QT*LP;          // 128 x KTP
    float* qcs    = kt + 128*KTP;        // QT x QP
    float* qps    = qcs + QT*QP;         // QT x QP
    float* seg0   = qps + QT*QP;         // QT
    float* seg1   = seg0 + QT;           // QT
    int*   qrow   = (int*)(seg1 + QT);   // QT

    const int n  = blockIdx.z, h = blockIdx.y;
    const int q0 = blockIdx.x * QT;
    const int tid = threadIdx.x;
    const int wid = tid >> 5, lane = tid & 31;
    const int g = lane >> 2, t = lane & 3;
    const int wq = wid >> 2, wr = wid & 3;

    const float* qbase = Qp + ((size_t)(n*HH + h)*NQ + q0)*64;
    for (int u = tid; u < QT*64; u += 256) {
        int l = u >> 6, s = u & 63;
        float qv = qbase[l*64 + s];
        qcs[l*QP + s] = qv + cb[h*SS + s];
        qps[l*QP + s] = qv + pb[h*SS + s];
    }
    if (tid < QT) qrow[tid] = tpos ? tpos[n*PPQ + q0 + tid] : (q0 + tid);
    if (tid >= 64 && tid < 64 + 2*QT) {
        int i = tid - 64;
        int l = i >> 1, gg = i & 1;
        float acc = 0.f;
        const float* qr = qbase + l*64;
        const float* se = segenc + ((size_t)gg*HH + h)*SS;
        for (int s = 0; s < SS; s++) acc += (qr[s] + sb[h*SS + s]) * se[s];
        if (gg) seg1[l] = acc; else seg0[l] = acc;
    }
    __syncthreads();

    // ---- Phase A1: content logits (1xTF32) ----
    const float* kcb = KC + ((size_t)(n*HH + h)*RR)*64;
    for (int rt = 0; rt < 8; rt++) {
        for (int u = tid; u < 128*16; u += 256) {
            int rl = u >> 4, s4 = u & 15;
            float4 v = *(const float4*)(kcb + (size_t)(rt*128 + rl)*64 + s4*4);
            float* d = kt + rl*KTP + s4*4;
            d[0]=v.x; d[1]=v.y; d[2]=v.z; d[3]=v.w;
        }
        __syncthreads();
        float c[4][4] = {{0,0,0,0},{0,0,0,0},{0,0,0,0},{0,0,0,0}};
#pragma unroll
        for (int ks = 0; ks < 8; ks++) {
            int s0 = ks*8;
            uint32_t af[4];
            af[0] = f2tf32(qcs[(wq*16 + g    )*QP + s0 + t    ]);
            af[1] = f2tf32(qcs[(wq*16 + g + 8)*QP + s0 + t    ]);
            af[2] = f2tf32(qcs[(wq*16 + g    )*QP + s0 + t + 4]);
            af[3] = f2tf32(qcs[(wq*16 + g + 8)*QP + s0 + t + 4]);
#pragma unroll
            for (int j = 0; j < 4; j++) {
                int r0 = wr*32 + j*8;
                uint32_t bf[2];
                bf[0] = f2tf32(kt[(r0+g)*KTP + s0 + t    ]);
                bf[1] = f2tf32(kt[(r0+g)*KTP + s0 + t + 4]);
                mma_tf32(c[j], af, bf);
            }
        }
#pragma unroll
        for (int j = 0; j < 4; j++) {
            int base = rt*128 + wr*32 + j*8 + 2*t;
            logits[(wq*16 + g    )*LP + base    ] = c[j][0];
            logits[(wq*16 + g    )*LP + base + 1] = c[j][1];
            logits[(wq*16 + g + 8)*LP + base    ] = c[j][2];
            logits[(wq*16 + g + 8)*LP + base + 1] = c[j][3];
        }
        __syncthreads();
    }

    // ---- Phase A2: position logits (1xTF32), rel-shift scatter ----
    {
        const float* kpb = KP + ((size_t)(n*HH + h)*RP)*64;
        int qp0 = qrow[wq*16 + g], qp1 = qrow[wq*16 + g + 8];
        for (int pt = 0; pt < 12; pt++) {
            for (int u = tid; u < 128*16; u += 256) {
                int rl = u >> 4, s4 = u & 15;
                float4 v = *(const float4*)(kpb + (size_t)(pt*128 + rl)*64 + s4*4);
                float* d = kt + rl*KTP + s4*4;
                d[0]=v.x; d[1]=v.y; d[2]=v.z; d[3]=v.w;
            }
            __syncthreads();
            float c[4][4] = {{0,0,0,0},{0,0,0,0},{0,0,0,0},{0,0,0,0}};
#pragma unroll
            for (int ks = 0; ks < 8; ks++) {
                int s0 = ks*8;
                uint32_t af[4];
                af[0] = f2tf32(qps[(wq*16 + g    )*QP + s0 + t    ]);
                af[1] = f2tf32(qps[(wq*16 + g + 8)*QP + s0 + t    ]);
                af[2] = f2tf32(qps[(wq*16 + g    )*QP + s0 + t + 4]);
                af[3] = f2tf32(qps[(wq*16 + g + 8)*QP + s0 + t + 4]);
#pragma unroll
                for (int j = 0; j < 4; j++) {
                    int r0 = wr*32 + j*8;
                    uint32_t bf[2];
                    bf[0] = f2tf32(kt[(r0+g)*KTP + s0 + t    ]);
                    bf[1] = f2tf32(kt[(r0+g)*KTP + s0 + t + 4]);
                    mma_tf32(c[j], af, bf);
                }
            }
#pragma unroll
            for (int j = 0; j < 4; j++) {
                int pp = pt*128 + wr*32 + j*8 + 2*t;
                int r;
                r = pp     - 512 + qp0; if (r >= 0 && r < RR) logits[(wq*16 + g    )*LP + r] += c[j][0];
                r = pp + 1 - 512 + qp0; if (r >= 0 && r < RR) logits[(wq*16 + g    )*LP + r] += c[j][1];
                r = pp     - 512 + qp1; if (r >= 0 && r < RR) logits[(wq*16 + g + 8)*LP + r] += c[j][2];
                r = pp + 1 - 512 + qp1; if (r >= 0 && r < RR) logits[(wq*16 + g + 8)*LP + r] += c[j][3];
            }
            __syncthreads();
        }
    }

    // ---- Phase A3: segment + mask + scale + softmax (8 threads/row) ----
    {
        int row = tid >> 3, l8 = tid & 7;
        int qq = qrow[row];
        const float* mrow = mask + ((size_t)n*QQ + qq)*RR;
        const int* srow = segmat + ((size_t)n*QQ + qq)*RR;
        float s1v = seg1[row], s0v = seg0[row];
        float* lrow = logits + row*LP;
        float mx = -3.4e38f;
        for (int i = 0; i < 128; i++) {
            int cc = l8 + 8*i;
            float lg = lrow[cc] + (srow[cc] ? s1v : s0v);
            lg = lg * 0.125f + mrow[cc] * (-1e9f);
            lrow[cc] = lg;
            mx = fmaxf(mx, lg);
        }
        for (int o = 4; o; o >>= 1) mx = fmaxf(mx, __shfl_xor_sync(0xffffffffu, mx, o, 8));
        float sum = 0.f;
        for (int i = 0; i < 128; i++) {
            int cc = l8 + 8*i;
            float e = __expf(lrow[cc] - mx);
            lrow[cc] = e;
            sum += e;
        }
        for (int o = 4; o; o >>= 1) sum += __shfl_xor_sync(0xffffffffu, sum, o, 8);
        float inv = __fdividef(1.f, sum);
        for (int i = 0; i < 128; i++) lrow[l8 + 8*i] *= inv;
    }
    __syncthreads();

    // ---- Phase B: out = weights @ V (3xTF32); warp wid -> s-range [wid*8, wid*8+8) ----
    {
        const float* vb = V + ((size_t)(n*HH + h)*RR)*64;
        float acc0[4] = {0,0,0,0}, acc1[4] = {0,0,0,0};
        for (int rt = 0; rt < 8; rt++) {
            for (int u = tid; u < 128*16; u += 256) {
                int rl = u >> 4, s4 = u & 15;
                float4 v = *(const float4*)(vb + (size_t)(rt*128 + rl)*64 + s4*4);
                float* d = kt + rl*KTP + s4*4;
                d[0]=v.x; d[1]=v.y; d[2]=v.z; d[3]=v.w;
            }
            __syncthreads();
#pragma unroll
            for (int ks = 0; ks < 16; ks++) {
                int k0 = ks*8;
                int col0 = rt*128 + k0;
                uint32_t ah0[4], al0[4], ah1[4], al1[4];
                split_tf32(logits[(g    )*LP + col0 + t    ], ah0[0], al0[0]);
                split_tf32(logits[(g + 8)*LP + col0 + t    ], ah0[1], al0[1]);
                split_tf32(logits[(g    )*LP + col0 + t + 4], ah0[2], al0[2]);
                split_tf32(logits[(g + 8)*LP + col0 + t + 4], ah0[3], al0[3]);
                split_tf32(logits[(16 + g    )*LP + col0 + t    ], ah1[0], al1[0]);
                split_tf32(logits[(16 + g + 8)*LP + col0 + t    ], ah1[1], al1[1]);
                split_tf32(logits[(16 + g    )*LP + col0 + t + 4], ah1[2], al1[2]);
                split_tf32(logits[(16 + g + 8)*LP + col0 + t + 4], ah1[3], al1[3]);
                uint32_t bh[2], bl[2];
                split_tf32(kt[(k0 + t    )*KTP + wid*8 + g], bh[0], bl[0]);
                split_tf32(kt[(k0 + t + 4)*KTP + wid*8 + g], bh[1], bl[1]);
                mma3(acc0, ah0, al0, bh, bl);
                mma3(acc1, ah1, al1, bh, bl);
            }
            __syncthreads();
        }
        size_t o00 = ((size_t)(n*NQ + q0 + g     )*HH + h)*SS + wid*8 + 2*t;
        size_t o01 = ((size_t)(n*NQ + q0 + g + 8 )*HH + h)*SS + wid*8 + 2*t;
        size_t o10 = ((size_t)(n*NQ + q0 + 16 + g    )*HH + h)*SS + wid*8 + 2*t;
        size_t o11 = ((size_t)(n*NQ + q0 + 16 + g + 8)*HH + h)*SS + wid*8 + 2*t;
        *(float2*)(Out + o00) = make_float2(acc0[0], acc0[1]);
        *(float2*)(Out + o01) = make_float2(acc0[2], acc0[3]);
        *(float2*)(Out + o10) = make_float2(acc1[0], acc1[1]);
        *(float2*)(Out + o11) = make_float2(acc1[2], acc1[3]);
    }
}

// -------------------- launch --------------------
extern "C" void kernel_launch(void* const* d_in, const int* in_sizes, int n_in,
                              void* d_out, int out_size)
{
    const float* content = (const float*)d_in[0];
    const float* query   = (const float*)d_in[1];
    const float* posenc  = (const float*)d_in[2];
    const float* segenc  = (const float*)d_in[3];
    const int*   segmat  = (const int*)d_in[4];
    const float* tmap    = (const float*)d_in[5];
    const float* cmask   = (const float*)d_in[6];
    const float* qmask   = (const float*)d_in[7];
    const float* cb      = (const float*)d_in[8];
    const float* pb      = (const float*)d_in[9];
    const float* sb      = (const float*)d_in[10];
    const float* mems    = (const float*)d_in[11];
    const float* Wq      = (const float*)d_in[12];
    const float* Wkc     = (const float*)d_in[13];
    const float* Wv      = (const float*)d_in[14];
    const float* Wkp     = (const float*)d_in[15];
    const float* Wo      = (const float*)d_in[16];
    float* out = (float*)d_out;

    float *p_ctx, *p_kc, *p_v, *p_kp, *p_qc, *p_qq, *p_ac, *p_aq;
    int* p_tpos;
    cudaGetSymbolAddress((void**)&p_ctx, g_ctx);
    cudaGetSymbolAddress((void**)&p_kc,  g_kc);
    cudaGetSymbolAddress((void**)&p_v,   g_v);
    cudaGetSymbolAddress((void**)&p_kp,  g_kp);
    cudaGetSymbolAddress((void**)&p_qc,  g_qc);
    cudaGetSymbolAddress((void**)&p_qq,  g_qq);
    cudaGetSymbolAddress((void**)&p_ac,  g_ac);
    cudaGetSymbolAddress((void**)&p_aq,  g_aq);
    cudaGetSymbolAddress((void**)&p_tpos, g_tpos);

    cudaFuncSetAttribute(attn_kernel, cudaFuncAttributeMaxDynamicSharedMemorySize, ATTN_SMEM_BYTES);

    build_ctx<<<(BB*RR*HID/4 + 255)/256, 256>>>(mems, content);
    find_tpos<<<1, 512>>>(tmap);

    gemm_mma<<<dim3(8, 32), 256>>>(p_ctx,   Wkc, p_kc, RR,  1);
    gemm_mma<<<dim3(8, 32), 256>>>(p_ctx,   Wv,  p_v,  RR,  1);
    gemm_mma<<<dim3(8, 48), 256>>>(posenc,  Wkp, p_kp, RP,  1);
    gemm_mma<<<dim3(8, 16), 256>>>(content, Wq,  p_qc, QQ,  1);
    gemm_mma<<<dim3(8, 4),  256>>>(query,   Wq,  p_qq, PPQ, 1);

    dim3 gac(QQ/QT, HH, BB);
    attn_kernel<<<gac, 256, ATTN_SMEM_BYTES>>>(p_qc, QQ, p_kc, p_v, p_kp, segenc, segmat,
                                               cmask, cb, pb, sb, nullptr, p_ac);
    dim3 gaq(PPQ/QT, HH, BB);
    attn_kernel<<<gaq, 256, ATTN_SMEM_BYTES>>>(p_qq, PPQ, p_kc, p_v, p_kp, segenc, segmat,
                                               qmask, cb, pb, sb, p_tpos, p_aq);

    gemm_mma<<<dim3(8, 16), 256>>>(p_ac, Wo, out, 0, 0);
    gemm_mma<<<dim3(8, 4),  256>>>(p_aq, Wo, out + (size_t)BB*QQ*HID, 0, 0);
}

// round 8
// speedup vs baseline: 1.0912x; 1.0484x over previous
#include <cuda_runtime.h>
#include <cuda_fp16.h>
#include <cstdint>

#define BB  4
#define QQ  512
#define MM  512
#define PPQ 128
#define HID 1024
#define HH  16
#define SS  64
#define RR  1024
#define RP  1536
#define QT  16

// -------- scratch --------
__device__ float g_ctx[BB*RR*HID];
__device__ float g_kc [BB*RR*HID];   // [n][h][r][64]
__device__ float g_v  [BB*RR*HID];
__device__ float g_kp [BB*RP*HID];
__device__ float g_qc [BB*QQ*HID];   // [n][h][q][64]
__device__ float g_qq [BB*PPQ*HID];
__device__ float g_ac [BB*QQ*HID];   // [n][q][h][64]
__device__ float g_aq [BB*PPQ*HID];
__device__ int   g_tpos[BB*PPQ];

// ================= helpers =================
__device__ __forceinline__ void split_h(float x, __half& h, __half& l){
    h = __float2half_rn(x);
    l = __float2half_rn(x - __half2float(h));
}
__device__ __forceinline__ uint32_t pack2(float a, float b, bool lo){
    __half ha, la, hb, lb;
    split_h(a, ha, la); split_h(b, hb, lb);
    __half2 v = lo ? __halves2half2(la, lb) : __halves2half2(ha, hb);
    return *(uint32_t*)&v;
}
__device__ __forceinline__ void mma_h(float* c, const uint32_t* a, const uint32_t* b){
    asm volatile("mma.sync.aligned.m16n8k16.row.col.f32.f16.f16.f32 "
        "{%0,%1,%2,%3}, {%4,%5,%6,%7}, {%8,%9}, {%0,%1,%2,%3};"
        : "+f"(c[0]),"+f"(c[1]),"+f"(c[2]),"+f"(c[3])
        : "r"(a[0]),"r"(a[1]),"r"(a[2]),"r"(a[3]), "r"(b[0]),"r"(b[1]));
}
__device__ __forceinline__ void mma3h(float* c, const uint32_t* aH, const uint32_t* aL,
                                      const uint32_t* bH, const uint32_t* bL){
    mma_h(c, aH, bH);
    mma_h(c, aH, bL);
    mma_h(c, aL, bH);
}

// ================= misc kernels =================
__global__ void build_ctx(const float* __restrict__ mems, const float* __restrict__ content)
{
    int idx = blockIdx.x * blockDim.x + threadIdx.x;
    const int total = BB*RR*HID/4;
    if (idx >= total) return;
    int d4  = idx & (HID/4 - 1);
    int row = idx / (HID/4);
    int n = row >> 10, r = row & 1023;
    const float* src = (r < MM) ? (mems + ((size_t)n*MM + r)*HID)
                                : (content + ((size_t)n*QQ + (r-MM))*HID);
    ((float4*)g_ctx)[idx] = ((const float4*)src)[d4];
}

__global__ void find_tpos(const float* __restrict__ tm)
{
    int i = threadIdx.x;
    const float* row = tm + (size_t)i * QQ;
    int q = 0;
    for (int j = 0; j < QQ; j++) if (row[j] > 0.5f) q = j;
    g_tpos[i] = q;
}

// ================= fp16x2-split mma GEMM =================
// C = A[rows,1024] @ W[1024,1024]; halves tiles, reg-staged loads.
// AH/AL: [2][128][26] halves (pitch 26 -> 13 words/row, odd => store-clean)
// BH/BL: [2][128][26] halves, transposed (n-major, k pairs adjacent)
#define GP 26
#define GEMM_SMEM (4 * 2 * 128 * GP * 2)   // 4 arrays x 2 buf x 128 x 26 halves x 2B = 53248

__global__ __launch_bounds__(256, 2) void gemm_mma(const float* __restrict__ A,
                                                   const float* __restrict__ W,
                                                   float* __restrict__ C,
                                                   int rowsPB, int relayout)
{
    extern __shared__ __half gsm[];
    __half* AH = gsm;
    __half* AL = AH + 2*128*GP;
    __half* BH = AL + 2*128*GP;
    __half* BL = BH + 2*128*GP;

    const int tid  = threadIdx.x;
    const int wid  = tid >> 5, lane = tid & 31;
    const int wm   = wid & 3,  wn   = wid >> 2;
    const int g    = lane >> 2, t   = lane & 3;
    const int m0   = blockIdx.y * 128;
    const int n0   = blockIdx.x * 128;

    // stage mapping
    const int arow = tid & 127, ak8 = (tid >> 7) * 8;        // A: row, k-half
    const int bkp  = tid >> 5,  bl  = tid & 31;              // B: k-pair, n-quad

    float c[2][8][4];
#pragma unroll
    for (int i = 0; i < 2; i++)
#pragma unroll
        for (int j = 0; j < 8; j++)
#pragma unroll
            for (int l = 0; l < 4; l++) c[i][j][l] = 0.f;

    float4 ra0, ra1, rb0, rb1;
    auto ldg_tile = [&](int kt){
        ra0 = *(const float4*)(A + (size_t)(m0 + arow)*1024 + kt + ak8);
        ra1 = *(const float4*)(A + (size_t)(m0 + arow)*1024 + kt + ak8 + 4);
        rb0 = *(const float4*)(W + (size_t)(kt + 2*bkp)*1024 + n0 + bl*4);
        rb1 = *(const float4*)(W + (size_t)(kt + 2*bkp + 1)*1024 + n0 + bl*4);
    };
    auto sts_tile = [&](int buf){
        __half* ah = AH + buf*128*GP + arow*GP;
        __half* al = AL + buf*128*GP + arow*GP;
        float av[8] = {ra0.x, ra0.y, ra0.z, ra0.w, ra1.x, ra1.y, ra1.z, ra1.w};
#pragma unroll
        for (int i = 0; i < 4; i++) {
            ((uint32_t*)ah)[(ak8>>1) + i] = pack2(av[2*i], av[2*i+1], false);
            ((uint32_t*)al)[(ak8>>1) + i] = pack2(av[2*i], av[2*i+1], true);
        }
        float b0[4] = {rb0.x, rb0.y, rb0.z, rb0.w};
        float b1[4] = {rb1.x, rb1.y, rb1.z, rb1.w};
#pragma unroll
        for (int j = 0; j < 4; j++) {
            int n = bl*4 + j;
            ((uint32_t*)(BH + buf*128*GP + n*GP))[bkp] = pack2(b0[j], b1[j], false);
            ((uint32_t*)(BL + buf*128*GP + n*GP))[bkp] = pack2(b0[j], b1[j], true);
        }
    };

    ldg_tile(0);
    sts_tile(0);
    __syncthreads();

    for (int kt = 0; kt < 64; kt++) {
        int buf = kt & 1;
        if (kt + 1 < 64) ldg_tile((kt + 1) * 16);

        // fragments + mma
        uint32_t aH[2][4], aL2[2][4];
#pragma unroll
        for (int mt = 0; mt < 2; mt++) {
            int mr = wm*32 + mt*16 + g;
            const uint32_t* ph0 = (const uint32_t*)(AH + buf*128*GP + mr*GP);
            const uint32_t* ph1 = (const uint32_t*)(AH + buf*128*GP + (mr+8)*GP);
            const uint32_t* pl0 = (const uint32_t*)(AL + buf*128*GP + mr*GP);
            const uint32_t* pl1 = (const uint32_t*)(AL + buf*128*GP + (mr+8)*GP);
            aH[mt][0] = ph0[t]; aH[mt][1] = ph1[t]; aH[mt][2] = ph0[t+4]; aH[mt][3] = ph1[t+4];
            aL2[mt][0] = pl0[t]; aL2[mt][1] = pl1[t]; aL2[mt][2] = pl0[t+4]; aL2[mt][3] = pl1[t+4];
        }
#pragma unroll
        for (int nt = 0; nt < 8; nt++) {
            int nc = wn*64 + nt*8 + g;
            const uint32_t* pbh = (const uint32_t*)(BH + buf*128*GP + nc*GP);
            const uint32_t* pbl = (const uint32_t*)(BL + buf*128*GP + nc*GP);
            uint32_t bH[2] = {pbh[t], pbh[t+4]};
            uint32_t bL[2] = {pbl[t], pbl[t+4]};
#pragma unroll
            for (int mt = 0; mt < 2; mt++)
                mma3h(c[mt][nt], aH[mt], aL2[mt], bH, bL);
        }

        if (kt + 1 < 64) sts_tile(buf ^ 1);
        __syncthreads();
    }

#pragma unroll
    for (int mt = 0; mt < 2; mt++) {
        int rowg = m0 + wm*32 + mt*16 + g;
#pragma unroll
        for (int nt = 0; nt < 8; nt++) {
            int col = n0 + wn*64 + nt*8 + 2*t;
            if (relayout) {
                int nn = rowg / rowsPB, r = rowg % rowsPB;
                int hh = col >> 6, ss = col & 63;
                float* d0 = C + ((size_t)(nn*HH + hh)*rowsPB + r)*64 + ss;
                float* d1 = C + ((size_t)(nn*HH + hh)*rowsPB + r + 8)*64 + ss;
                *(float2*)d0 = make_float2(c[mt][nt][0], c[mt][nt][1]);
                *(float2*)d1 = make_float2(c[mt][nt][2], c[mt][nt][3]);
            } else {
                *(float2*)(C + (size_t)rowg*1024 + col)       = make_float2(c[mt][nt][0], c[mt][nt][1]);
                *(float2*)(C + (size_t)(rowg + 8)*1024 + col) = make_float2(c[mt][nt][2], c[mt][nt][3]);
            }
        }
    }
}

// ================= fp16-split tensor-core attention, QT=16 =================
// smem bytes: logits fp32 16x1044 (in-place halves after softmax) | ktH/ktL 128x72 (vt overlays) | q tiles | misc
#define LPF   1044                 // fp32 logits pitch (floats); row bytes 4176
#define KTPH  72                   // kt pitch (halves)
#define VTPH  136                  // vt pitch (halves)
#define OFF_LOG  0
#define OFF_KT   (16*LPF*4)                        // 66816
#define OFF_KTL  (OFF_KT + 128*KTPH*2)             // +18432
#define OFF_QCH  (OFF_KTL + 128*KTPH*2)            // 103680
#define OFF_QCL  (OFF_QCH + 16*KTPH*2)
#define OFF_QPH  (OFF_QCL + 16*KTPH*2)
#define OFF_QPL  (OFF_QPH + 16*KTPH*2)
#define OFF_MISC (OFF_QPL + 16*KTPH*2)             // 112896
#define ATTN_SMEM_BYTES (OFF_MISC + 256)

__global__ __launch_bounds__(256) void attn_kernel(
                            const float* __restrict__ Qp, int NQ,
                            const float* __restrict__ KC, const float* __restrict__ V,
                            const float* __restrict__ KP,
                            const float* __restrict__ segenc,
                            const int* __restrict__ segmat,
                            const float* __restrict__ mask,
                            const float* __restrict__ cb, const float* __restrict__ pb,
                            const float* __restrict__ sb,
                            const int* __restrict__ tpos,
                            float* __restrict__ Out)
{
    extern __shared__ char asm_[];
    float* logitsF = (float*)(asm_ + OFF_LOG);
    __half* ktH = (__half*)(asm_ + OFF_KT);
    __half* ktL = (__half*)(asm_ + OFF_KTL);
    __half* vtH = (__half*)(asm_ + OFF_KT);    // overlay
    __half* vtL = (__half*)(asm_ + OFF_KTL);
    __half* qcH = (__half*)(asm_ + OFF_QCH);
    __half* qcL = (__half*)(asm_ + OFF_QCL);
    __half* qpH = (__half*)(asm_ + OFF_QPH);
    __half* qpL = (__half*)(asm_ + OFF_QPL);
    float* seg0 = (float*)(asm_ + OFF_MISC);
    float* seg1 = seg0 + 16;
    int*   qrow = (int*)(seg1 + 16);

    const int n  = blockIdx.z, h = blockIdx.y;
    const int q0 = blockIdx.x * QT;
    const int tid = threadIdx.x;
    const int wid = tid >> 5, lane = tid & 31;
    const int g = lane >> 2, t = lane & 3;

    // ---- init: q tiles -> halves; seg dots; qrow ----
    const float* qbase = Qp + ((size_t)(n*HH + h)*NQ + q0)*64;
    {
        int l = tid >> 4, s4 = tid & 15;          // 256 threads: 16 rows x 16 float4
        float4 qv = *(const float4*)(qbase + l*64 + s4*4);
        float cbv[4] = {cb[h*SS + s4*4], cb[h*SS + s4*4+1], cb[h*SS + s4*4+2], cb[h*SS + s4*4+3]};
        float pbv[4] = {pb[h*SS + s4*4], pb[h*SS + s4*4+1], pb[h*SS + s4*4+2], pb[h*SS + s4*4+3]};
        float qa[4] = {qv.x, qv.y, qv.z, qv.w};
        uint32_t* wqch = (uint32_t*)(qcH + l*KTPH);
        uint32_t* wqcl = (uint32_t*)(qcL + l*KTPH);
        uint32_t* wqph = (uint32_t*)(qpH + l*KTPH);
        uint32_t* wqpl = (uint32_t*)(qpL + l*KTPH);
#pragma unroll
        for (int i = 0; i < 2; i++) {
            float a0 = qa[2*i] + cbv[2*i],   a1 = qa[2*i+1] + cbv[2*i+1];
            float p0 = qa[2*i] + pbv[2*i],   p1 = qa[2*i+1] + pbv[2*i+1];
            wqch[s4*2 + i] = pack2(a0, a1, false);
            wqcl[s4*2 + i] = pack2(a0, a1, true);
            wqph[s4*2 + i] = pack2(p0, p1, false);
            wqpl[s4*2 + i] = pack2(p0, p1, true);
        }
    }
    if (tid < QT) qrow[tid] = tpos ? tpos[n*PPQ + q0 + tid] : (q0 + tid);
    if (tid >= 64 && tid < 64 + 2*QT) {
        int i = tid - 64;
        int l = i >> 1, gg = i & 1;
        float acc = 0.f;
        const float* qr = qbase + l*64;
        const float* se = segenc + ((size_t)gg*HH + h)*SS;
        for (int s = 0; s < SS; s++) acc += (qr[s] + sb[h*SS + s]) * se[s];
        if (gg) seg1[l] = acc; else seg0[l] = acc;
    }
    __syncthreads();

    // K-type tile load: fp32 global -> half hi/lo, pitch KTPH
    auto load_ktile = [&](const float* src){
#pragma unroll
        for (int i = 0; i < 8; i++) {
            int idx = tid + i*256;
            int rl = idx >> 4, s4 = idx & 15;
            float4 v = *(const float4*)(src + (size_t)rl*64 + s4*4);
            uint32_t* wh = (uint32_t*)(ktH + rl*KTPH);
            uint32_t* wl = (uint32_t*)(ktL + rl*KTPH);
            wh[s4*2    ] = pack2(v.x, v.y, false);
            wh[s4*2 + 1] = pack2(v.z, v.w, false);
            wl[s4*2    ] = pack2(v.x, v.y, true);
            wl[s4*2 + 1] = pack2(v.z, v.w, true);
        }
    };

    // QK-type mma on current kt tile; qsrc = qc or qp halves. Warp wid covers r [wid*16, +16).
    // Results: cres[j][4] for j=0..1 (n8 tiles)
    auto qk_tile = [&](const __half* qh, const __half* ql, float cres[2][4]){
        uint32_t aH[4], aL[4];
#pragma unroll
        for (int ch = 0; ch < 4; ch++) {
            const uint32_t* pa0 = (const uint32_t*)(qh + g*KTPH);
            const uint32_t* pa1 = (const uint32_t*)(qh + (g+8)*KTPH);
            const uint32_t* pl0 = (const uint32_t*)(ql + g*KTPH);
            const uint32_t* pl1 = (const uint32_t*)(ql + (g+8)*KTPH);
            aH[0] = pa0[ch*8 + t]; aH[1] = pa1[ch*8 + t];
            aH[2] = pa0[ch*8 + t + 4]; aH[3] = pa1[ch*8 + t + 4];
            aL[0] = pl0[ch*8 + t]; aL[1] = pl1[ch*8 + t];
            aL[2] = pl0[ch*8 + t + 4]; aL[3] = pl1[ch*8 + t + 4];
#pragma unroll
            for (int j = 0; j < 2; j++) {
                int r = wid*16 + j*8 + g;
                const uint32_t* pbh = (const uint32_t*)(ktH + r*KTPH);
                const uint32_t* pbl = (const uint32_t*)(ktL + r*KTPH);
                uint32_t bH[2] = {pbh[ch*8 + t], pbh[ch*8 + t + 4]};
                uint32_t bL[2] = {pbl[ch*8 + t], pbl[ch*8 + t + 4]};
                mma3h(cres[j], aH, aL, bH, bL);
            }
        }
    };

    // ---- Phase A1: content logits ----
    const float* kcb = KC + ((size_t)(n*HH + h)*RR)*64;
    for (int rt = 0; rt < 8; rt++) {
        load_ktile(kcb + (size_t)rt*128*64);
        __syncthreads();
        float cres[2][4] = {{0,0,0,0},{0,0,0,0}};
        qk_tile(qcH, qcL, cres);
#pragma unroll
        for (int j = 0; j < 2; j++) {
            int base = rt*128 + wid*16 + j*8 + 2*t;
            logitsF[g*LPF + base] = cres[j][0];
            logitsF[g*LPF + base + 1] = cres[j][1];
            logitsF[(g+8)*LPF + base] = cres[j][2];
            logitsF[(g+8)*LPF + base + 1] = cres[j][3];
        }
        __syncthreads();
    }

    // ---- Phase A2: position logits, rel-shift scatter ----
    {
        const float* kpb = KP + ((size_t)(n*HH + h)*RP)*64;
        int qp0 = qrow[g], qp1 = qrow[g+8];
        for (int pt = 0; pt < 12; pt++) {
            load_ktile(kpb + (size_t)pt*128*64);
            __syncthreads();
            float cres[2][4] = {{0,0,0,0},{0,0,0,0}};
            qk_tile(qpH, qpL, cres);
#pragma unroll
            for (int j = 0; j < 2; j++) {
                int pp = pt*128 + wid*16 + j*8 + 2*t;
                int r;
                r = pp     - 512 + qp0; if (r >= 0 && r < RR) logitsF[g*LPF + r]     += cres[j][0];
                r = pp + 1 - 512 + qp0; if (r >= 0 && r < RR) logitsF[g*LPF + r]     += cres[j][1];
                r = pp     - 512 + qp1; if (r >= 0 && r < RR) logitsF[(g+8)*LPF + r] += cres[j][2];
                r = pp + 1 - 512 + qp1; if (r >= 0 && r < RR) logitsF[(g+8)*LPF + r] += cres[j][3];
            }
            __syncthreads();
        }
    }

    // ---- Phase A3: segment + mask + softmax (16 threads/row) ----
    {
        int row = tid >> 4, l16 = tid & 15;
        int qq = qrow[row];
        const float* mrow = mask + ((size_t)n*QQ + qq)*RR;
        const int* srow = segmat + ((size_t)n*QQ + qq)*RR;
        float s1v = seg1[row], s0v = seg0[row];
        float* lrow = logitsF + row*LPF;
        float mx = -3.4e38f;
        for (int i = 0; i < 64; i++) {
            int cc = l16 + 16*i;
            float lg = lrow[cc] + (srow[cc] ? s1v : s0v);
            lg = lg * 0.125f + mrow[cc] * (-1e9f);
            lrow[cc] = lg;
            mx = fmaxf(mx, lg);
        }
        for (int o = 8; o; o >>= 1) mx = fmaxf(mx, __shfl_xor_sync(0xffffffffu, mx, o, 16));
        float sum = 0.f;
        for (int i = 0; i < 64; i++) {
            int cc = l16 + 16*i;
            float e = __expf(lrow[cc] - mx);
            lrow[cc] = e;
            sum += e;
        }
        for (int o = 8; o; o >>= 1) sum += __shfl_xor_sync(0xffffffffu, sum, o, 16);
        float inv = __fdividef(1.f, sum);
        for (int i = 0; i < 64; i++) lrow[l16 + 16*i] *= inv;
    }
    __syncthreads();

    // ---- convert logits fp32 -> halves in place (row q: hi at +0, lo at half-idx 1044) ----
    {
        int rsub = tid >> 6;            // 0..3
        int c0 = (tid & 63) * 16;
        for (int p = 0; p < 4; p++) {
            int row = p*4 + rsub;
            const float* src = logitsF + row*LPF;
            float v[16];
#pragma unroll
            for (int i = 0; i < 4; i++) {
                float4 f = *(const float4*)(src + c0 + i*4);
                v[4*i] = f.x; v[4*i+1] = f.y; v[4*i+2] = f.z; v[4*i+3] = f.w;
            }
            __syncthreads();
            uint32_t* wh = (uint32_t*)(asm_ + OFF_LOG + row*4176);
            uint32_t* wl = (uint32_t*)(asm_ + OFF_LOG + row*4176 + 2088);
#pragma unroll
            for (int i = 0; i < 8; i++) {
                wh[c0/2 + i] = pack2(v[2*i], v[2*i+1], false);
                wl[c0/2 + i] = pack2(v[2*i], v[2*i+1], true);
            }
            __syncthreads();
        }
    }

    // ---- Phase B: out = weights @ V; V store-transposed to half pairs ----
    {
        const float* vb = V + ((size_t)(n*HH + h)*RR)*64;
        float cacc[4] = {0,0,0,0};
        for (int rt = 0; rt < 8; rt++) {
            // load V tile [128 r][64 s] -> vt[s][r-pairs]
#pragma unroll
            for (int it = 0; it < 2; it++) {
                int r2 = ((tid >> 3) + it*32) * 2;
                int s8 = (tid & 7) * 8;
                const float* r0p = vb + (size_t)(rt*128 + r2)*64 + s8;
                const float* r1p = r0p + 64;
                float a[8], b[8];
                *(float4*)(a)   = *(const float4*)(r0p);
                *(float4*)(a+4) = *(const float4*)(r0p + 4);
                *(float4*)(b)   = *(const float4*)(r1p);
                *(float4*)(b+4) = *(const float4*)(r1p + 4);
#pragma unroll
                for (int j = 0; j < 8; j++) {
                    int jj = (j + (tid & 7)) & 7;        // stagger to avoid bank conflicts
                    int s = s8 + jj;
                    ((uint32_t*)(vtH + s*VTPH))[r2 >> 1] = pack2(a[jj], b[jj], false);
                    ((uint32_t*)(vtL + s*VTPH))[r2 >> 1] = pack2(a[jj], b[jj], true);
                }
            }
            __syncthreads();
            // mma: A = logits halves rows g/g+8, k = r; B = vt[n = wid*8+g][k pairs]
#pragma unroll
            for (int ch = 0; ch < 8; ch++) {
                int kw = rt*64 + ch*8;    // word offset within logits row for this rt,chunk
                const uint32_t* ah0 = (const uint32_t*)(asm_ + OFF_LOG + g*4176);
                const uint32_t* ah1 = (const uint32_t*)(asm_ + OFF_LOG + (g+8)*4176);
                const uint32_t* al0 = (const uint32_t*)(asm_ + OFF_LOG + g*4176 + 2088);
                const uint32_t* al1 = (const uint32_t*)(asm_ + OFF_LOG + (g+8)*4176 + 2088);
                uint32_t aH[4] = {ah0[kw + t], ah1[kw + t], ah0[kw + t + 4], ah1[kw + t + 4]};
                uint32_t aL[4] = {al0[kw + t], al1[kw + t], al0[kw + t + 4], al1[kw + t + 4]};
                const uint32_t* pbh = (const uint32_t*)(vtH + (wid*8 + g)*VTPH);
                const uint32_t* pbl = (const uint32_t*)(vtL + (wid*8 + g)*VTPH);
                uint32_t bH[2] = {pbh[ch*8 + t], pbh[ch*8 + t + 4]};
                uint32_t bL[2] = {pbl[ch*8 + t], pbl[ch*8 + t + 4]};
                mma3h(cacc, aH, aL, bH, bL);
            }
            __syncthreads();
        }
        size_t o0 = ((size_t)(n*NQ + q0 + g    )*HH + h)*SS + wid*8 + 2*t;
        size_t o1 = ((size_t)(n*NQ + q0 + g + 8)*HH + h)*SS + wid*8 + 2*t;
        *(float2*)(Out + o0) = make_float2(cacc[0], cacc[1]);
        *(float2*)(Out + o1) = make_float2(cacc[2], cacc[3]);
    }
}

// -------------------- launch --------------------
extern "C" void kernel_launch(void* const* d_in, const int* in_sizes, int n_in,
                              void* d_out, int out_size)
{
    const float* content = (const float*)d_in[0];
    const float* query   = (const float*)d_in[1];
    const float* posenc  = (const float*)d_in[2];
    const float* segenc  = (const float*)d_in[3];
    const int*   segmat  = (const int*)d_in[4];
    const float* tmap    = (const float*)d_in[5];
    const float* cmask   = (const float*)d_in[6];
    const float* qmask   = (const float*)d_in[7];
    const float* cb      = (const float*)d_in[8];
    const float* pb      = (const float*)d_in[9];
    const float* sb      = (const float*)d_in[10];
    const float* mems    = (const float*)d_in[11];
    const float* Wq      = (const float*)d_in[12];
    const float* Wkc     = (const float*)d_in[13];
    const float* Wv      = (const float*)d_in[14];
    const float* Wkp     = (const float*)d_in[15];
    const float* Wo      = (const float*)d_in[16];
    float* out = (float*)d_out;

    float *p_ctx, *p_kc, *p_v, *p_kp, *p_qc, *p_qq, *p_ac, *p_aq;
    int* p_tpos;
    cudaGetSymbolAddress((void**)&p_ctx, g_ctx);
    cudaGetSymbolAddress((void**)&p_kc,  g_kc);
    cudaGetSymbolAddress((void**)&p_v,   g_v);
    cudaGetSymbolAddress((void**)&p_kp,  g_kp);
    cudaGetSymbolAddress((void**)&p_qc,  g_qc);
    cudaGetSymbolAddress((void**)&p_qq,  g_qq);
    cudaGetSymbolAddress((void**)&p_ac,  g_ac);
    cudaGetSymbolAddress((void**)&p_aq,  g_aq);
    cudaGetSymbolAddress((void**)&p_tpos, g_tpos);

    cudaFuncSetAttribute(attn_kernel, cudaFuncAttributeMaxDynamicSharedMemorySize, ATTN_SMEM_BYTES);
    cudaFuncSetAttribute(gemm_mma, cudaFuncAttributeMaxDynamicSharedMemorySize, GEMM_SMEM);

    build_ctx<<<(BB*RR*HID/4 + 255)/256, 256>>>(mems, content);
    find_tpos<<<1, 512>>>(tmap);

    gemm_mma<<<dim3(8, 32), 256, GEMM_SMEM>>>(p_ctx,   Wkc, p_kc, RR,  1);
    gemm_mma<<<dim3(8, 32), 256, GEMM_SMEM>>>(p_ctx,   Wv,  p_v,  RR,  1);
    gemm_mma<<<dim3(8, 48), 256, GEMM_SMEM>>>(posenc,  Wkp, p_kp, RP,  1);
    gemm_mma<<<dim3(8, 16), 256, GEMM_SMEM>>>(content, Wq,  p_qc, QQ,  1);
    gemm_mma<<<dim3(8, 4),  256, GEMM_SMEM>>>(query,   Wq,  p_qq, PPQ, 1);

    dim3 gac(QQ/QT, HH, BB);
    attn_kernel<<<gac, 256, ATTN_SMEM_BYTES>>>(p_qc, QQ, p_kc, p_v, p_kp, segenc, segmat,
                                               cmask, cb, pb, sb, nullptr, p_ac);
    dim3 gaq(PPQ/QT, HH, BB);
    attn_kernel<<<gaq, 256, ATTN_SMEM_BYTES>>>(p_qq, PPQ, p_kc, p_v, p_kp, segenc, segmat,
                                               qmask, cb, pb, sb, p_tpos, p_aq);

    gemm_mma<<<dim3(8, 16), 256, GEMM_SMEM>>>(p_ac, Wo, out, 0, 0);
    gemm_mma<<<dim3(8, 4),  256, GEMM_SMEM>>>(p_aq, Wo, out + (size_t)BB*QQ*HID, 0, 0);
}

// round 9
// speedup vs baseline: 1.3795x; 1.2642x over previous
#include <cuda_runtime.h>
#include <cuda_fp16.h>
#include <cstdint>

#define BB  4
#define QQ  512
#define MM  512
#define PPQ 128
#define HID 1024
#define HH  16
#define SS  64
#define RR  1024
#define RP  1536
#define QT  16
#define NHDIM (BB*HH)

// ---------------- global scratch (halves pre-split hi/lo) ----------------
__device__ __align__(16) __half g_ctxH[BB*RR*HID],  g_ctxL[BB*RR*HID];
__device__ __align__(16) __half g_posH[BB*RP*HID],  g_posL[BB*RP*HID];
__device__ __align__(16) __half g_conH[BB*QQ*HID],  g_conL[BB*QQ*HID];
__device__ __align__(16) __half g_qryH[BB*PPQ*HID], g_qryL[BB*PPQ*HID];
__device__ __align__(16) __half g_wH[5*HID*HID],    g_wL[5*HID*HID];   // transposed [n][k-pairs]
__device__ __align__(16) __half g_kcH[BB*RR*HID],   g_kcL[BB*RR*HID];  // [nh][r][64]
__device__ __align__(16) __half g_kpH[BB*RP*HID],   g_kpL[BB*RP*HID];  // [nh][p][64]
__device__ __align__(16) __half g_vtH[BB*RR*HID],   g_vtL[BB*RR*HID];  // [nh][s][r-pairs]
__device__ __align__(16) __half g_acH[BB*QQ*HID],   g_acL[BB*QQ*HID];
__device__ __align__(16) __half g_aqH[BB*PPQ*HID],  g_aqL[BB*PPQ*HID];
__device__ float g_v [BB*RR*HID];    // fp32 [nh][r][64] (for V transpose)
__device__ float g_qc[BB*QQ*HID];    // fp32 [nh][q][64]
__device__ float g_qq[BB*PPQ*HID];
__device__ int   g_tpos[BB*PPQ];

// ---------------- helpers ----------------
__device__ __forceinline__ uint32_t smem_u32(const void* p){
    uint32_t a;
    asm("{ .reg .u64 t; cvta.to.shared.u64 t, %1; cvt.u32.u64 %0, t; }" : "=r"(a) : "l"(p));
    return a;
}
__device__ __forceinline__ void cpasync16(uint32_t s, const void* g){
    asm volatile("cp.async.cg.shared.global [%0], [%1], 16;" :: "r"(s), "l"(g));
}
__device__ __forceinline__ void cpcommit(){ asm volatile("cp.async.commit_group;" ::: "memory"); }
template<int N> __device__ __forceinline__ void cpwait(){ asm volatile("cp.async.wait_group %0;" :: "n"(N) : "memory"); }

__device__ __forceinline__ void split_h(float x, __half& h, __half& l){
    h = __float2half_rn(x);
    l = __float2half_rn(x - __half2float(h));
}
__device__ __forceinline__ uint32_t pack2(float a, float b, bool lo){
    __half ha, la, hb, lb;
    split_h(a, ha, la); split_h(b, hb, lb);
    __half2 v = lo ? __halves2half2(la, lb) : __halves2half2(ha, hb);
    return *(uint32_t*)&v;
}
__device__ __forceinline__ void mma_h(float* c, const uint32_t* a, const uint32_t* b){
    asm volatile("mma.sync.aligned.m16n8k16.row.col.f32.f16.f16.f32 "
        "{%0,%1,%2,%3}, {%4,%5,%6,%7}, {%8,%9}, {%0,%1,%2,%3};"
        : "+f"(c[0]),"+f"(c[1]),"+f"(c[2]),"+f"(c[3])
        : "r"(a[0]),"r"(a[1]),"r"(a[2]),"r"(a[3]), "r"(b[0]),"r"(b[1]));
}
__device__ __forceinline__ void mma3h(float* c, const uint32_t* aH, const uint32_t* aL,
                                      const uint32_t* bH, const uint32_t* bL){
    mma_h(c, aH, bH);
    mma_h(c, aH, bL);
    mma_h(c, aL, bH);
}

// ---------------- converts ----------------
__global__ void build_ctx_split(const float* __restrict__ mems, const float* __restrict__ content)
{
    int idx = blockIdx.x * blockDim.x + threadIdx.x;      // float4 index
    const int total = BB*RR*HID/4;
    if (idx >= total) return;
    int d4  = idx & 255;
    int row = idx >> 8;
    int n = row >> 10, r = row & 1023;
    const float* src = (r < MM) ? (mems + ((size_t)n*MM + r)*HID)
                                : (content + ((size_t)n*QQ + (r-MM))*HID);
    float4 v = ((const float4*)src)[d4];
    uint32_t* wh = (uint32_t*)g_ctxH;
    uint32_t* wl = (uint32_t*)g_ctxL;
    wh[idx*2]   = pack2(v.x, v.y, false);
    wh[idx*2+1] = pack2(v.z, v.w, false);
    wl[idx*2]   = pack2(v.x, v.y, true);
    wl[idx*2+1] = pack2(v.z, v.w, true);
}

__global__ void split_k(const float* __restrict__ src, __half* dstH, __half* dstL, int n4)
{
    int idx = blockIdx.x * blockDim.x + threadIdx.x;
    if (idx >= n4) return;
    float4 v = ((const float4*)src)[idx];
    ((uint32_t*)dstH)[idx*2]   = pack2(v.x, v.y, false);
    ((uint32_t*)dstH)[idx*2+1] = pack2(v.z, v.w, false);
    ((uint32_t*)dstL)[idx*2]   = pack2(v.x, v.y, true);
    ((uint32_t*)dstL)[idx*2+1] = pack2(v.z, v.w, true);
}

// W [k][n] -> WT halves [n][k-pairs]: word w of row n = (W[2w][n], W[2w+1][n])
__global__ void wtrans(const float* __restrict__ W, __half* dstH, __half* dstL)
{
    __shared__ float sm[32][33];
    int n0 = blockIdx.x*32, k0 = blockIdx.y*32;
    int tx = threadIdx.x, ty = threadIdx.y;          // (32, 8)
#pragma unroll
    for (int i = 0; i < 4; i++)
        sm[ty + 8*i][tx] = W[(size_t)(k0 + ty + 8*i)*1024 + n0 + tx];
    __syncthreads();
    int tid = ty*32 + tx;
    int w = tid & 15;
#pragma unroll
    for (int p = 0; p < 2; p++) {
        int nn = p*16 + (tid >> 4);
        float a = sm[2*w][nn], b = sm[2*w+1][nn];
        size_t o = (size_t)(n0 + nn)*512 + (k0 >> 1) + w;
        ((uint32_t*)dstH)[o] = pack2(a, b, false);
        ((uint32_t*)dstL)[o] = pack2(a, b, true);
    }
}

// g_v fp32 [nh][r][64] -> vt halves [nh][s][r-pairs]
__global__ void vtrans()
{
    __shared__ float vs[128][65];
    int nh = blockIdx.x >> 3, rc = blockIdx.x & 7;
    int tid = threadIdx.x;
    const float* src = g_v + ((size_t)nh*1024 + rc*128)*64;
#pragma unroll
    for (int i = 0; i < 8; i++) {
        int idx = tid + i*256;
        int r = idx >> 4, f4 = idx & 15;
        float4 v = ((const float4*)(src + (size_t)r*64))[f4];
        vs[r][f4*4] = v.x; vs[r][f4*4+1] = v.y; vs[r][f4*4+2] = v.z; vs[r][f4*4+3] = v.w;
    }
    __syncthreads();
#pragma unroll
    for (int i = 0; i < 16; i++) {
        int idx = tid + i*256;
        int s = idx >> 6, w = idx & 63;
        float a = vs[2*w][s], b = vs[2*w+1][s];
        size_t o = ((size_t)nh*64 + s)*512 + rc*64 + w;
        ((uint32_t*)g_vtH)[o] = pack2(a, b, false);
        ((uint32_t*)g_vtL)[o] = pack2(a, b, true);
    }
}

__global__ void find_tpos(const float* __restrict__ tm)
{
    int i = threadIdx.x;
    const float* row = tm + (size_t)i * QQ;
    int q = 0;
    for (int j = 0; j < QQ; j++) if (row[j] > 0.5f) q = j;
    g_tpos[i] = q;
}

// ---------------- half-split GEMM, cp.async 3-stage ----------------
// C = A[m,1024] @ WT[n,1024]^T (both pre-split halves). pad-12-word rows.
#define GPW 12
#define G_AH 0
#define G_AL (3*128*GPW)
#define G_BH (2*3*128*GPW)
#define G_BL (3*3*128*GPW)
#define GEMM_SMEM (4*3*128*GPW*4)

__global__ __launch_bounds__(256, 2) void gemm_h(
        const __half* __restrict__ AHg, const __half* __restrict__ ALg,
        const __half* __restrict__ BHg, const __half* __restrict__ BLg,
        float* CF, __half* CHp, __half* CLp, int rowsPB, int mode)
{
    extern __shared__ uint32_t gsm[];
    const uint32_t sbase = smem_u32(gsm);
    const int tid  = threadIdx.x;
    const int wid  = tid >> 5, lane = tid & 31;
    const int wm   = wid & 3,  wn   = wid >> 2;
    const int g    = lane >> 2, t   = lane & 3;
    const int m0   = blockIdx.y * 128;
    const int n0   = blockIdx.x * 128;

    float c[2][8][4];
#pragma unroll
    for (int i = 0; i < 2; i++)
#pragma unroll
        for (int j = 0; j < 8; j++)
#pragma unroll
            for (int l = 0; l < 4; l++) c[i][j][l] = 0.f;

    const int lrow = tid >> 1, lc = tid & 1;
    auto ldtile = [&](int kt, int b){
        const char* srcs[4] = {
            (const char*)AHg + (size_t)(m0 + lrow)*2048 + kt*32 + lc*16,
            (const char*)ALg + (size_t)(m0 + lrow)*2048 + kt*32 + lc*16,
            (const char*)BHg + (size_t)(n0 + lrow)*2048 + kt*32 + lc*16,
            (const char*)BLg + (size_t)(n0 + lrow)*2048 + kt*32 + lc*16 };
        const int bases[4] = {G_AH, G_AL, G_BH, G_BL};
#pragma unroll
        for (int i = 0; i < 4; i++)
            cpasync16(sbase + (bases[i] + (b*128 + lrow)*GPW + lc*4)*4, srcs[i]);
        cpcommit();
    };

    ldtile(0, 0);
    ldtile(1, 1);

    for (int kt = 0; kt < 64; kt++) {
        int b = kt % 3;
        if (kt < 63) cpwait<1>(); else cpwait<0>();
        __syncthreads();
        if (kt + 2 < 64) ldtile(kt + 2, (kt + 2) % 3);

        uint32_t aH[2][4], aL[2][4];
#pragma unroll
        for (int mt = 0; mt < 2; mt++) {
            int mr = wm*32 + mt*16 + g;
            int b0 = (b*128 + mr)*GPW, b1 = (b*128 + mr + 8)*GPW;
            aH[mt][0] = gsm[G_AH + b0 + t];     aH[mt][1] = gsm[G_AH + b1 + t];
            aH[mt][2] = gsm[G_AH + b0 + t + 4]; aH[mt][3] = gsm[G_AH + b1 + t + 4];
            aL[mt][0] = gsm[G_AL + b0 + t];     aL[mt][1] = gsm[G_AL + b1 + t];
            aL[mt][2] = gsm[G_AL + b0 + t + 4]; aL[mt][3] = gsm[G_AL + b1 + t + 4];
        }
#pragma unroll
        for (int nt = 0; nt < 8; nt++) {
            int nc = wn*64 + nt*8 + g;
            int bb = (b*128 + nc)*GPW;
            uint32_t bH[2] = {gsm[G_BH + bb + t], gsm[G_BH + bb + t + 4]};
            uint32_t bL[2] = {gsm[G_BL + bb + t], gsm[G_BL + bb + t + 4]};
#pragma unroll
            for (int mt = 0; mt < 2; mt++)
                mma3h(c[mt][nt], aH[mt], aL[mt], bH, bL);
        }
    }

#pragma unroll
    for (int mt = 0; mt < 2; mt++) {
        int rowg = m0 + wm*32 + mt*16 + g;
#pragma unroll
        for (int nt = 0; nt < 8; nt++) {
            int col = n0 + wn*64 + nt*8 + 2*t;
            float c0 = c[mt][nt][0], c1 = c[mt][nt][1], c2 = c[mt][nt][2], c3 = c[mt][nt][3];
            if (mode == 2) {
                int nn = rowg / rowsPB, r = rowg % rowsPB;
                int hh = col >> 6, ss = col & 63;
                size_t w0 = ((size_t)(nn*HH + hh)*rowsPB + r)*32 + (ss >> 1);
                size_t w1 = w0 + 8*32;
                ((uint32_t*)CHp)[w0] = pack2(c0, c1, false);
                ((uint32_t*)CLp)[w0] = pack2(c0, c1, true);
                ((uint32_t*)CHp)[w1] = pack2(c2, c3, false);
                ((uint32_t*)CLp)[w1] = pack2(c2, c3, true);
            } else if (mode == 1) {
                int nn = rowg / rowsPB, r = rowg % rowsPB;
                int hh = col >> 6, ss = col & 63;
                float* d0 = CF + ((size_t)(nn*HH + hh)*rowsPB + r)*64 + ss;
                float* d1 = CF + ((size_t)(nn*HH + hh)*rowsPB + r + 8)*64 + ss;
                *(float2*)d0 = make_float2(c0, c1);
                *(float2*)d1 = make_float2(c2, c3);
            } else {
                *(float2*)(CF + (size_t)rowg*1024 + col)       = make_float2(c0, c1);
                *(float2*)(CF + (size_t)(rowg + 8)*1024 + col) = make_float2(c2, c3);
            }
        }
    }
}

// ---------------- attention: cp.async swizzled pipeline ----------------
// smem: logits fp32 16x1044 (bytes 4176/row, halves in-place after softmax)
//       tiles: hi [3][128][32w] + lo [3][128][32w]  (Phase B overlays [3][64][64w])
//       q halves: 4 arrays x [16][36w] ; misc
#define OFF_LOG  0
#define OFF_TILE 66816
#define OFF_Q    (OFF_TILE + 2*3*128*32*4)      // 165120
#define OFF_MISC (OFF_Q + 4*16*36*4)            // 174336
#define ATTN_SMEM_BYTES (OFF_MISC + 256)

__global__ __launch_bounds__(256) void attn_kernel(
                            const float* __restrict__ Qp, int NQ,
                            const __half* __restrict__ kcHg, const __half* __restrict__ kcLg,
                            const __half* __restrict__ kpHg, const __half* __restrict__ kpLg,
                            const __half* __restrict__ vtHg, const __half* __restrict__ vtLg,
                            const float* __restrict__ segenc,
                            const int* __restrict__ segmat,
                            const float* __restrict__ mask,
                            const float* __restrict__ cb, const float* __restrict__ pb,
                            const float* __restrict__ sb,
                            const int* __restrict__ tpos,
                            __half* outH, __half* outL)
{
    extern __shared__ char asm_[];
    float* logitsF = (float*)(asm_ + OFF_LOG);
    uint32_t* tw  = (uint32_t*)(asm_ + OFF_TILE);     // hi tiles; lo at +12288 words
    uint32_t* qw  = (uint32_t*)(asm_ + OFF_Q);        // qcH, qcL, qpH, qpL each 576 words
    float* seg0 = (float*)(asm_ + OFF_MISC);
    float* seg1 = seg0 + 16;
    int*   qrow = (int*)(seg1 + 16);

    const int n  = blockIdx.z, h = blockIdx.y;
    const int nh = n*HH + h;
    const int q0 = blockIdx.x * QT;
    const int tid = threadIdx.x;
    const int wid = tid >> 5, lane = tid & 31;
    const int g = lane >> 2, t = lane & 3;
    const uint32_t tbase = smem_u32(asm_ + OFF_TILE);
    const int xorv = g << 2;

    // ---- QK tile loader: 2048 chunks (hi 1024 + lo 1024), swizzle c ^= r&7 ----
    auto ld_qk = [&](int i, int b){
        const char *sH, *sL;
        if (i < 8) {
            size_t off = ((size_t)nh*1024 + (size_t)i*128) * 128;
            sH = (const char*)kcHg + off; sL = (const char*)kcLg + off;
        } else {
            size_t off = ((size_t)nh*1536 + (size_t)(i-8)*128) * 128;
            sH = (const char*)kpHg + off; sL = (const char*)kpLg + off;
        }
#pragma unroll
        for (int j = 0; j < 8; j++) {
            int grp = j >> 2;
            int c2 = (tid + j*256) & 1023;
            int row = c2 >> 3, c = c2 & 7;
            int cc = c ^ (row & 7);
            uint32_t dst = tbase + (grp*12288 + (b*128 + row)*32 + cc*4)*4;
            cpasync16(dst, (grp ? sL : sH) + row*128 + c*16);
        }
        cpcommit();
    };
    // ---- V tile loader: vt [nh][s][r-pairs]; tile rt -> [64 s][64 w], swizzle c ^= s&7 ----
    auto ld_vt = [&](int rt, int b){
#pragma unroll
        for (int j = 0; j < 8; j++) {
            int grp = j >> 2;
            int c2 = (tid + j*256) & 1023;
            int s = c2 >> 4, c = c2 & 15;
            int cc = c ^ (s & 7);
            uint32_t dst = tbase + (grp*12288 + (b*64 + s)*64 + cc*4)*4;
            const char* src = (grp ? (const char*)vtLg : (const char*)vtHg)
                              + ((size_t)nh*64 + s)*2048 + rt*256 + c*16;
            cpasync16(dst, src);
        }
        cpcommit();
    };

    // ---- init: q tiles -> halves in smem; seg dots; qrow ----
    const float* qbase = Qp + ((size_t)nh*NQ + q0)*64;
    {
        int l = tid >> 4, s4 = tid & 15;
        float4 qv = *(const float4*)(qbase + l*64 + s4*4);
        float qa[4] = {qv.x, qv.y, qv.z, qv.w};
        float cbv[4], pbv[4];
#pragma unroll
        for (int i = 0; i < 4; i++) { cbv[i] = cb[h*SS + s4*4 + i]; pbv[i] = pb[h*SS + s4*4 + i]; }
        uint32_t* qcH = qw;            uint32_t* qcL = qw + 576;
        uint32_t* qpH = qw + 1152;     uint32_t* qpL = qw + 1728;
#pragma unroll
        for (int i = 0; i < 2; i++) {
            float a0 = qa[2*i] + cbv[2*i], a1 = qa[2*i+1] + cbv[2*i+1];
            float p0 = qa[2*i] + pbv[2*i], p1 = qa[2*i+1] + pbv[2*i+1];
            qcH[l*36 + s4*2 + i] = pack2(a0, a1, false);
            qcL[l*36 + s4*2 + i] = pack2(a0, a1, true);
            qpH[l*36 + s4*2 + i] = pack2(p0, p1, false);
            qpL[l*36 + s4*2 + i] = pack2(p0, p1, true);
        }
    }
    if (tid < QT) qrow[tid] = tpos ? tpos[n*PPQ + q0 + tid] : (q0 + tid);
    if (tid >= 64 && tid < 64 + 2*QT) {
        int i = tid - 64;
        int l = i >> 1, gg = i & 1;
        float acc = 0.f;
        const float* qr = qbase + l*64;
        const float* se = segenc + ((size_t)gg*HH + h)*SS;
        for (int s = 0; s < SS; s++) acc += (qr[s] + sb[h*SS + s]) * se[s];
        if (gg) seg1[l] = acc; else seg0[l] = acc;
    }

    ld_qk(0, 0);
    ld_qk(1, 1);
    __syncthreads();    // q tiles + misc visible

    const int qp0 = qrow[g], qp1 = qrow[g + 8];

    // ---- QK pipeline: 20 tiles (8 content, 12 position) ----
    for (int i = 0; i < 20; i++) {
        int b = i % 3;
        if (i < 19) cpwait<1>(); else cpwait<0>();
        __syncthreads();
        if (i + 2 < 20) ld_qk(i + 2, (i + 2) % 3);

        const uint32_t* qh = (i < 8) ? qw        : qw + 1152;
        const uint32_t* ql = (i < 8) ? qw + 576  : qw + 1728;
        float cres[2][4] = {{0,0,0,0},{0,0,0,0}};
#pragma unroll
        for (int ch = 0; ch < 4; ch++) {
            int s0w = ch*8;
            uint32_t aH[4], aL[4];
            aH[0] = qh[g*36 + s0w + t];       aH[1] = qh[(g+8)*36 + s0w + t];
            aH[2] = qh[g*36 + s0w + t + 4];   aH[3] = qh[(g+8)*36 + s0w + t + 4];
            aL[0] = ql[g*36 + s0w + t];       aL[1] = ql[(g+8)*36 + s0w + t];
            aL[2] = ql[g*36 + s0w + t + 4];   aL[3] = ql[(g+8)*36 + s0w + t + 4];
#pragma unroll
            for (int j = 0; j < 2; j++) {
                int r = wid*16 + j*8 + g;
                int rb = (b*128 + r)*32;
                uint32_t bH[2] = {tw[rb + ((s0w + t) ^ xorv)],         tw[rb + ((s0w + t + 4) ^ xorv)]};
                uint32_t bL[2] = {tw[12288 + rb + ((s0w + t) ^ xorv)], tw[12288 + rb + ((s0w + t + 4) ^ xorv)]};
                mma3h(cres[j], aH, aL, bH, bL);
            }
        }
        if (i < 8) {
#pragma unroll
            for (int j = 0; j < 2; j++) {
                int base = i*128 + wid*16 + j*8 + 2*t;
                logitsF[g*1044 + base]         = cres[j][0];
                logitsF[g*1044 + base + 1]     = cres[j][1];
                logitsF[(g+8)*1044 + base]     = cres[j][2];
                logitsF[(g+8)*1044 + base + 1] = cres[j][3];
            }
        } else {
            int pt = i - 8;
#pragma unroll
            for (int j = 0; j < 2; j++) {
                int pp = pt*128 + wid*16 + j*8 + 2*t;
                int r;
                r = pp     - 512 + qp0; if (r >= 0 && r < RR) logitsF[g*1044 + r]     += cres[j][0];
                r = pp + 1 - 512 + qp0; if (r >= 0 && r < RR) logitsF[g*1044 + r]     += cres[j][1];
                r = pp     - 512 + qp1; if (r >= 0 && r < RR) logitsF[(g+8)*1044 + r] += cres[j][2];
                r = pp + 1 - 512 + qp1; if (r >= 0 && r < RR) logitsF[(g+8)*1044 + r] += cres[j][3];
            }
        }
    }
    __syncthreads();

    // prefetch first two V tiles under softmax/conversion
    ld_vt(0, 0);
    ld_vt(1, 1);

    // ---- softmax ----
    {
        int row = tid >> 4, l16 = tid & 15;
        int qq = qrow[row];
        const float* mrow = mask + ((size_t)n*QQ + qq)*RR;
        const int* srow = segmat + ((size_t)n*QQ + qq)*RR;
        float s1v = seg1[row], s0v = seg0[row];
        float* lrow = logitsF + row*1044;
        float mx = -3.4e38f;
        for (int i = 0; i < 64; i++) {
            int cc = l16 + 16*i;
            float lg = lrow[cc] + (srow[cc] ? s1v : s0v);
            lg = lg * 0.125f + mrow[cc] * (-1e9f);
            lrow[cc] = lg;
            mx = fmaxf(mx, lg);
        }
        for (int o = 8; o; o >>= 1) mx = fmaxf(mx, __shfl_xor_sync(0xffffffffu, mx, o, 16));
        float sum = 0.f;
        for (int i = 0; i < 64; i++) {
            int cc = l16 + 16*i;
            float e = __expf(lrow[cc] - mx);
            lrow[cc] = e;
            sum += e;
        }
        for (int o = 8; o; o >>= 1) sum += __shfl_xor_sync(0xffffffffu, sum, o, 16);
        float inv = __fdividef(1.f, sum);
        for (int i = 0; i < 64; i++) lrow[l16 + 16*i] *= inv;
    }
    __syncthreads();

    // ---- logits fp32 -> halves in place (hi at +0, lo at +2088 B per 4176 B row) ----
    {
        int rsub = tid >> 6;
        int c0 = (tid & 63) * 16;
        for (int p = 0; p < 4; p++) {
            int row = p*4 + rsub;
            const float* src = logitsF + row*1044;
            float v[16];
#pragma unroll
            for (int i = 0; i < 4; i++) {
                float4 f = *(const float4*)(src + c0 + i*4);
                v[4*i] = f.x; v[4*i+1] = f.y; v[4*i+2] = f.z; v[4*i+3] = f.w;
            }
            __syncthreads();
            uint32_t* wh = (uint32_t*)(asm_ + row*4176);
            uint32_t* wl = (uint32_t*)(asm_ + row*4176 + 2088);
#pragma unroll
            for (int i = 0; i < 8; i++) {
                wh[c0/2 + i] = pack2(v[2*i], v[2*i+1], false);
                wl[c0/2 + i] = pack2(v[2*i], v[2*i+1], true);
            }
            __syncthreads();
        }
    }

    // ---- Phase B: out = weights @ V, 3-stage over 8 tiles ----
    {
        float ca[4] = {0,0,0,0}, cbn[4] = {0,0,0,0};
        const uint32_t* ah0 = (const uint32_t*)(asm_ + g*4176);
        const uint32_t* ah1 = (const uint32_t*)(asm_ + (g+8)*4176);
        const uint32_t* al0 = (const uint32_t*)(asm_ + g*4176 + 2088);
        const uint32_t* al1 = (const uint32_t*)(asm_ + (g+8)*4176 + 2088);
        for (int rt = 0; rt < 8; rt++) {
            int b = rt % 3;
            if (rt < 7) cpwait<1>(); else cpwait<0>();
            __syncthreads();
            if (rt + 2 < 8) ld_vt(rt + 2, (rt + 2) % 3);
            int sb = (b*64 + wid*8 + g)*64;
#pragma unroll
            for (int ch = 0; ch < 8; ch++) {
                int kw = rt*64 + ch*8;
                uint32_t aH[4] = {ah0[kw + t], ah1[kw + t], ah0[kw + t + 4], ah1[kw + t + 4]};
                uint32_t aL[4] = {al0[kw + t], al1[kw + t], al0[kw + t + 4], al1[kw + t + 4]};
                uint32_t bH[2] = {tw[sb + ((ch*8 + t) ^ xorv)],         tw[sb + ((ch*8 + t + 4) ^ xorv)]};
                uint32_t bL[2] = {tw[12288 + sb + ((ch*8 + t) ^ xorv)], tw[12288 + sb + ((ch*8 + t + 4) ^ xorv)]};
                mma3h((ch & 1) ? cbn : ca, aH, aL, bH, bL);
            }
        }
#pragma unroll
        for (int l = 0; l < 4; l++) ca[l] += cbn[l];
        size_t w0 = ((size_t)(n*NQ + q0 + g    ))*512 + h*32 + wid*4 + t;
        size_t w1 = ((size_t)(n*NQ + q0 + g + 8))*512 + h*32 + wid*4 + t;
        ((uint32_t*)outH)[w0] = pack2(ca[0], ca[1], false);
        ((uint32_t*)outL)[w0] = pack2(ca[0], ca[1], true);
        ((uint32_t*)outH)[w1] = pack2(ca[2], ca[3], false);
        ((uint32_t*)outL)[w1] = pack2(ca[2], ca[3], true);
    }
}

// -------------------- launch --------------------
extern "C" void kernel_launch(void* const* d_in, const int* in_sizes, int n_in,
                              void* d_out, int out_size)
{
    const float* content = (const float*)d_in[0];
    const float* query   = (const float*)d_in[1];
    const float* posenc  = (const float*)d_in[2];
    const float* segenc  = (const float*)d_in[3];
    const int*   segmat  = (const int*)d_in[4];
    const float* tmap    = (const float*)d_in[5];
    const float* cmask   = (const float*)d_in[6];
    const float* qmask   = (const float*)d_in[7];
    const float* cb      = (const float*)d_in[8];
    const float* pb      = (const float*)d_in[9];
    const float* sb      = (const float*)d_in[10];
    const float* mems    = (const float*)d_in[11];
    const float* Wq      = (const float*)d_in[12];
    const float* Wkc     = (const float*)d_in[13];
    const float* Wv      = (const float*)d_in[14];
    const float* Wkp     = (const float*)d_in[15];
    const float* Wo      = (const float*)d_in[16];
    float* out = (float*)d_out;

    __half *ctxH, *ctxL, *posH, *posL, *conH, *conL, *qryH, *qryL, *wH, *wL;
    __half *kcH, *kcL, *kpH, *kpL, *vtH, *vtL, *acH, *acL, *aqH, *aqL;
    float *pv, *pqc, *pqq;
    int* ptpos;
    cudaGetSymbolAddress((void**)&ctxH, g_ctxH); cudaGetSymbolAddress((void**)&ctxL, g_ctxL);
    cudaGetSymbolAddress((void**)&posH, g_posH); cudaGetSymbolAddress((void**)&posL, g_posL);
    cudaGetSymbolAddress((void**)&conH, g_conH); cudaGetSymbolAddress((void**)&conL, g_conL);
    cudaGetSymbolAddress((void**)&qryH, g_qryH); cudaGetSymbolAddress((void**)&qryL, g_qryL);
    cudaGetSymbolAddress((void**)&wH,   g_wH);   cudaGetSymbolAddress((void**)&wL,   g_wL);
    cudaGetSymbolAddress((void**)&kcH,  g_kcH);  cudaGetSymbolAddress((void**)&kcL,  g_kcL);
    cudaGetSymbolAddress((void**)&kpH,  g_kpH);  cudaGetSymbolAddress((void**)&kpL,  g_kpL);
    cudaGetSymbolAddress((void**)&vtH,  g_vtH);  cudaGetSymbolAddress((void**)&vtL,  g_vtL);
    cudaGetSymbolAddress((void**)&acH,  g_acH);  cudaGetSymbolAddress((void**)&acL,  g_acL);
    cudaGetSymbolAddress((void**)&aqH,  g_aqH);  cudaGetSymbolAddress((void**)&aqL,  g_aqL);
    cudaGetSymbolAddress((void**)&pv,   g_v);
    cudaGetSymbolAddress((void**)&pqc,  g_qc);
    cudaGetSymbolAddress((void**)&pqq,  g_qq);
    cudaGetSymbolAddress((void**)&ptpos, g_tpos);

    cudaFuncSetAttribute(gemm_h, cudaFuncAttributeMaxDynamicSharedMemorySize, GEMM_SMEM);
    cudaFuncSetAttribute(attn_kernel, cudaFuncAttributeMaxDynamicSharedMemorySize, ATTN_SMEM_BYTES);

    // converts
    build_ctx_split<<<4096, 256>>>(mems, content);
    split_k<<<6144, 256>>>(posenc,  posH, posL, BB*RP*HID/4);
    split_k<<<2048, 256>>>(content, conH, conL, BB*QQ*HID/4);
    split_k<<<512,  256>>>(query,   qryH, qryL, BB*PPQ*HID/4);
    dim3 wtb(32, 8), wtg(32, 32);
    wtrans<<<wtg, wtb>>>(Wq,  wH + 0*(size_t)HID*HID, wL + 0*(size_t)HID*HID);
    wtrans<<<wtg, wtb>>>(Wkc, wH + 1*(size_t)HID*HID, wL + 1*(size_t)HID*HID);
    wtrans<<<wtg, wtb>>>(Wv,  wH + 2*(size_t)HID*HID, wL + 2*(size_t)HID*HID);
    wtrans<<<wtg, wtb>>>(Wkp, wH + 3*(size_t)HID*HID, wL + 3*(size_t)HID*HID);
    wtrans<<<wtg, wtb>>>(Wo,  wH + 4*(size_t)HID*HID, wL + 4*(size_t)HID*HID);
    find_tpos<<<1, 512>>>(tmap);

    // projections
    __half* wq_H = wH + 0*(size_t)HID*HID; __half* wq_L = wL + 0*(size_t)HID*HID;
    __half* wkcH = wH + 1*(size_t)HID*HID; __half* wkcL = wL + 1*(size_t)HID*HID;
    __half* wv_H = wH + 2*(size_t)HID*HID; __half* wv_L = wL + 2*(size_t)HID*HID;
    __half* wkpH = wH + 3*(size_t)HID*HID; __half* wkpL = wL + 3*(size_t)HID*HID;
    __half* wo_H = wH + 4*(size_t)HID*HID; __half* wo_L = wL + 4*(size_t)HID*HID;

    gemm_h<<<dim3(8, 32), 256, GEMM_SMEM>>>(ctxH, ctxL, wkcH, wkcL, nullptr, kcH, kcL, RR,  2);
    gemm_h<<<dim3(8, 32), 256, GEMM_SMEM>>>(ctxH, ctxL, wv_H, wv_L, pv, nullptr, nullptr, RR, 1);
    gemm_h<<<dim3(8, 48), 256, GEMM_SMEM>>>(posH, posL, wkpH, wkpL, nullptr, kpH, kpL, RP,  2);
    gemm_h<<<dim3(8, 16), 256, GEMM_SMEM>>>(conH, conL, wq_H, wq_L, pqc, nullptr, nullptr, QQ, 1);
    gemm_h<<<dim3(8, 4),  256, GEMM_SMEM>>>(qryH, qryL, wq_H, wq_L, pqq, nullptr, nullptr, PPQ, 1);
    vtrans<<<NHDIM*8, 256>>>();

    // attention
    dim3 gac(QQ/QT, HH, BB);
    attn_kernel<<<gac, 256, ATTN_SMEM_BYTES>>>(pqc, QQ, kcH, kcL, kpH, kpL, vtH, vtL,
                                               segenc, segmat, cmask, cb, pb, sb, nullptr, acH, acL);
    dim3 gaq(PPQ/QT, HH, BB);
    attn_kernel<<<gaq, 256, ATTN_SMEM_BYTES>>>(pqq, PPQ, kcH, kcL, kpH, kpL, vtH, vtL,
                                               segenc, segmat, qmask, cb, pb, sb, ptpos, aqH, aqL);

    // merges
    gemm_h<<<dim3(8, 16), 256, GEMM_SMEM>>>(acH, acL, wo_H, wo_L, out, nullptr, nullptr, 0, 0);
    gemm_h<<<dim3(8, 4),  256, GEMM_SMEM>>>(aqH, aqL, wo_H, wo_L, out + (size_t)BB*QQ*HID, nullptr, nullptr, 0, 0);
}

// round 13
// speedup vs baseline: 1.4314x; 1.0377x over previous
#include <cuda_runtime.h>
#include <cuda_fp16.h>
#include <cstdint>

#define BB  4
#define QQ  512
#define MM  512
#define PPQ 128
#define HID 1024
#define HH  16
#define SS  64
#define RR  1024
#define RP  1536
#define QT  16
#define NHDIM (BB*HH)

// ---------------- global scratch (halves pre-split hi/lo) ----------------
__device__ __align__(16) __half g_ctxH[BB*RR*HID],  g_ctxL[BB*RR*HID];
__device__ __align__(16) __half g_posH[BB*RP*HID],  g_posL[BB*RP*HID];
__device__ __align__(16) __half g_conH[BB*QQ*HID],  g_conL[BB*QQ*HID];
__device__ __align__(16) __half g_qryH[BB*PPQ*HID], g_qryL[BB*PPQ*HID];
__device__ __align__(16) __half g_wH[5*HID*HID],    g_wL[5*HID*HID];   // transposed [n][k-pairs]
__device__ __align__(16) __half g_kcH[BB*RR*HID],   g_kcL[BB*RR*HID];  // [nh][r][64]
__device__ __align__(16) __half g_kpH[BB*RP*HID],   g_kpL[BB*RP*HID];  // [nh][p][64]
__device__ __align__(16) __half g_vtH[BB*RR*HID],   g_vtL[BB*RR*HID];  // [nh][s][r-pairs]
__device__ __align__(16) __half g_acH[BB*QQ*HID],   g_acL[BB*QQ*HID];
__device__ __align__(16) __half g_aqH[BB*PPQ*HID],  g_aqL[BB*PPQ*HID];
__device__ float g_v [BB*RR*HID];    // fp32 [nh][r][64] (for V transpose)
__device__ float g_qc[BB*QQ*HID];    // fp32 [nh][q][64]
__device__ float g_qq[BB*PPQ*HID];
__device__ int   g_tpos[BB*PPQ];

// ---------------- helpers ----------------
__device__ __forceinline__ uint32_t smem_u32(const void* p){
    uint32_t a;
    asm("{ .reg .u64 t; cvta.to.shared.u64 t, %1; cvt.u32.u64 %0, t; }" : "=r"(a) : "l"(p));
    return a;
}
__device__ __forceinline__ void cpasync16(uint32_t s, const void* g){
    asm volatile("cp.async.cg.shared.global [%0], [%1], 16;" :: "r"(s), "l"(g));
}
__device__ __forceinline__ void cpcommit(){ asm volatile("cp.async.commit_group;" ::: "memory"); }
template<int N> __device__ __forceinline__ void cpwait(){ asm volatile("cp.async.wait_group %0;" :: "n"(N) : "memory"); }

__device__ __forceinline__ void ldsm4(uint32_t* r, uint32_t addr){
    asm volatile("ldmatrix.sync.aligned.m8n8.x4.shared.b16 {%0,%1,%2,%3}, [%4];"
        : "=r"(r[0]),"=r"(r[1]),"=r"(r[2]),"=r"(r[3]) : "r"(addr));
}
__device__ __forceinline__ void ldsm2(uint32_t* r, uint32_t addr){
    asm volatile("ldmatrix.sync.aligned.m8n8.x2.shared.b16 {%0,%1}, [%2];"
        : "=r"(r[0]),"=r"(r[1]) : "r"(addr));
}

__device__ __forceinline__ void split_h(float x, __half& h, __half& l){
    h = __float2half_rn(x);
    l = __float2half_rn(x - __half2float(h));
}
__device__ __forceinline__ uint32_t pack2(float a, float b, bool lo){
    __half ha, la, hb, lb;
    split_h(a, ha, la); split_h(b, hb, lb);
    __half2 v = lo ? __halves2half2(la, lb) : __halves2half2(ha, hb);
    return *(uint32_t*)&v;
}
__device__ __forceinline__ void mma_h(float* c, const uint32_t* a, const uint32_t* b){
    asm volatile("mma.sync.aligned.m16n8k16.row.col.f32.f16.f16.f32 "
        "{%0,%1,%2,%3}, {%4,%5,%6,%7}, {%8,%9}, {%0,%1,%2,%3};"
        : "+f"(c[0]),"+f"(c[1]),"+f"(c[2]),"+f"(c[3])
        : "r"(a[0]),"r"(a[1]),"r"(a[2]),"r"(a[3]), "r"(b[0]),"r"(b[1]));
}
__device__ __forceinline__ void mma3h(float* c, const uint32_t* aH, const uint32_t* aL,
                                      const uint32_t* bH, const uint32_t* bL){
    mma_h(c, aH, bH);
    mma_h(c, aH, bL);
    mma_h(c, aL, bH);
}

// ---------------- converts ----------------
__global__ void build_ctx_split(const float* __restrict__ mems, const float* __restrict__ content)
{
    int idx = blockIdx.x * blockDim.x + threadIdx.x;      // float4 index
    const int total = BB*RR*HID/4;
    if (idx >= total) return;
    int d4  = idx & 255;
    int row = idx >> 8;
    int n = row >> 10, r = row & 1023;
    const float* src = (r < MM) ? (mems + ((size_t)n*MM + r)*HID)
                                : (content + ((size_t)n*QQ + (r-MM))*HID);
    float4 v = ((const float4*)src)[d4];
    uint32_t* wh = (uint32_t*)g_ctxH;
    uint32_t* wl = (uint32_t*)g_ctxL;
    wh[idx*2]   = pack2(v.x, v.y, false);
    wh[idx*2+1] = pack2(v.z, v.w, false);
    wl[idx*2]   = pack2(v.x, v.y, true);
    wl[idx*2+1] = pack2(v.z, v.w, true);
}

__global__ void split_k(const float* __restrict__ src, __half* dstH, __half* dstL, int n4)
{
    int idx = blockIdx.x * blockDim.x + threadIdx.x;
    if (idx >= n4) return;
    float4 v = ((const float4*)src)[idx];
    ((uint32_t*)dstH)[idx*2]   = pack2(v.x, v.y, false);
    ((uint32_t*)dstH)[idx*2+1] = pack2(v.z, v.w, false);
    ((uint32_t*)dstL)[idx*2]   = pack2(v.x, v.y, true);
    ((uint32_t*)dstL)[idx*2+1] = pack2(v.z, v.w, true);
}

// W [k][n] -> WT halves [n][k-pairs]
__global__ void wtrans(const float* __restrict__ W, __half* dstH, __half* dstL)
{
    __shared__ float sm[32][33];
    int n0 = blockIdx.x*32, k0 = blockIdx.y*32;
    int tx = threadIdx.x, ty = threadIdx.y;          // (32, 8)
#pragma unroll
    for (int i = 0; i < 4; i++)
        sm[ty + 8*i][tx] = W[(size_t)(k0 + ty + 8*i)*1024 + n0 + tx];
    __syncthreads();
    int tid = ty*32 + tx;
    int w = tid & 15;
#pragma unroll
    for (int p = 0; p < 2; p++) {
        int nn = p*16 + (tid >> 4);
        float a = sm[2*w][nn], b = sm[2*w+1][nn];
        size_t o = (size_t)(n0 + nn)*512 + (k0 >> 1) + w;
        ((uint32_t*)dstH)[o] = pack2(a, b, false);
        ((uint32_t*)dstL)[o] = pack2(a, b, true);
    }
}

// g_v fp32 [nh][r][64] -> vt halves [nh][s][r-pairs]
__global__ void vtrans()
{
    __shared__ float vs[128][65];
    int nh = blockIdx.x >> 3, rc = blockIdx.x & 7;
    int tid = threadIdx.x;
    const float* src = g_v + ((size_t)nh*1024 + rc*128)*64;
#pragma unroll
    for (int i = 0; i < 8; i++) {
        int idx = tid + i*256;
        int r = idx >> 4, f4 = idx & 15;
        float4 v = ((const float4*)(src + (size_t)r*64))[f4];
        vs[r][f4*4] = v.x; vs[r][f4*4+1] = v.y; vs[r][f4*4+2] = v.z; vs[r][f4*4+3] = v.w;
    }
    __syncthreads();
#pragma unroll
    for (int i = 0; i < 16; i++) {
        int idx = tid + i*256;
        int s = idx >> 6, w = idx & 63;
        float a = vs[2*w][s], b = vs[2*w+1][s];
        size_t o = ((size_t)nh*64 + s)*512 + rc*64 + w;
        ((uint32_t*)g_vtH)[o] = pack2(a, b, false);
        ((uint32_t*)g_vtL)[o] = pack2(a, b, true);
    }
}

__global__ void find_tpos(const float* __restrict__ tm)
{
    int i = threadIdx.x;
    const float* row = tm + (size_t)i * QQ;
    int q = 0;
    for (int j = 0; j < QQ; j++) if (row[j] > 0.5f) q = j;
    g_tpos[i] = q;
}

// ---------------- half-split GEMM, cp.async 3-stage, ldmatrix frags ----------------
#define GPW 12
#define G_AH 0
#define G_AL (3*128*GPW)
#define G_BH (2*3*128*GPW)
#define G_BL (3*3*128*GPW)
#define GEMM_SMEM (4*3*128*GPW*4)

__global__ __launch_bounds__(256, 2) void gemm_h(
        const __half* __restrict__ AHg, const __half* __restrict__ ALg,
        const __half* __restrict__ BHg, const __half* __restrict__ BLg,
        float* CF, __half* CHp, __half* CLp, int rowsPB, int mode)
{
    extern __shared__ uint32_t gsm[];
    const uint32_t sbase = smem_u32(gsm);
    const int tid  = threadIdx.x;
    const int wid  = tid >> 5, lane = tid & 31;
    const int wm   = wid & 3,  wn   = wid >> 2;
    const int g    = lane >> 2, t   = lane & 3;
    const int m0   = blockIdx.y * 128;
    const int n0   = blockIdx.x * 128;
    const int m2   = lane >> 3, r8 = lane & 7;

    float c[2][8][4];
#pragma unroll
    for (int i = 0; i < 2; i++)
#pragma unroll
        for (int j = 0; j < 8; j++)
#pragma unroll
            for (int l = 0; l < 4; l++) c[i][j][l] = 0.f;

    const int lrow = tid >> 1, lc = tid & 1;
    auto ldtile = [&](int kt, int b){
        const char* srcs[4] = {
            (const char*)AHg + (size_t)(m0 + lrow)*2048 + kt*32 + lc*16,
            (const char*)ALg + (size_t)(m0 + lrow)*2048 + kt*32 + lc*16,
            (const char*)BHg + (size_t)(n0 + lrow)*2048 + kt*32 + lc*16,
            (const char*)BLg + (size_t)(n0 + lrow)*2048 + kt*32 + lc*16 };
        const int bases[4] = {G_AH, G_AL, G_BH, G_BL};
#pragma unroll
        for (int i = 0; i < 4; i++)
            cpasync16(sbase + (bases[i] + (b*128 + lrow)*GPW + lc*4)*4, srcs[i]);
        cpcommit();
    };

    ldtile(0, 0);
    ldtile(1, 1);

    for (int kt = 0; kt < 64; kt++) {
        int b = kt % 3;
        if (kt < 63) cpwait<1>(); else cpwait<0>();
        __syncthreads();
        if (kt + 2 < 64) ldtile(kt + 2, (kt + 2) % 3);

        uint32_t aH[2][4], aL[2][4];
#pragma unroll
        for (int mt = 0; mt < 2; mt++) {
            int row = wm*32 + mt*16 + (m2 & 1)*8 + r8;
            uint32_t ad = sbase + (uint32_t)(G_AH + (b*128 + row)*GPW)*4 + (m2 >> 1)*16;
            ldsm4(aH[mt], ad);
            ldsm4(aL[mt], ad + (uint32_t)(G_AL - G_AH)*4);
        }
#pragma unroll
        for (int p = 0; p < 4; p++) {
            int brow = wn*64 + p*16 + ((lane >> 4) & 1)*8 + r8;
            uint32_t bd = sbase + (uint32_t)(G_BH + (b*128 + brow)*GPW)*4 + ((lane >> 3) & 1)*16;
            uint32_t bf[4], bl[4];
            ldsm4(bf, bd);
            ldsm4(bl, bd + (uint32_t)(G_BL - G_BH)*4);
#pragma unroll
            for (int mt = 0; mt < 2; mt++) {
                mma3h(c[mt][2*p],     aH[mt], aL[mt], bf,     bl);
                mma3h(c[mt][2*p + 1], aH[mt], aL[mt], bf + 2, bl + 2);
            }
        }
    }

#pragma unroll
    for (int mt = 0; mt < 2; mt++) {
        int rowg = m0 + wm*32 + mt*16 + g;
#pragma unroll
        for (int nt = 0; nt < 8; nt++) {
            int col = n0 + wn*64 + nt*8 + 2*t;
            float c0 = c[mt][nt][0], c1 = c[mt][nt][1], c2 = c[mt][nt][2], c3 = c[mt][nt][3];
            if (mode == 2) {
                int nn = rowg / rowsPB, r = rowg % rowsPB;
                int hh = col >> 6, ss = col & 63;
                size_t w0 = ((size_t)(nn*HH + hh)*rowsPB + r)*32 + (ss >> 1);
                size_t w1 = w0 + 8*32;
                ((uint32_t*)CHp)[w0] = pack2(c0, c1, false);
                ((uint32_t*)CLp)[w0] = pack2(c0, c1, true);
                ((uint32_t*)CHp)[w1] = pack2(c2, c3, false);
                ((uint32_t*)CLp)[w1] = pack2(c2, c3, true);
            } else if (mode == 1) {
                int nn = rowg / rowsPB, r = rowg % rowsPB;
                int hh = col >> 6, ss = col & 63;
                float* d0 = CF + ((size_t)(nn*HH + hh)*rowsPB + r)*64 + ss;
                float* d1 = CF + ((size_t)(nn*HH + hh)*rowsPB + r + 8)*64 + ss;
                *(float2*)d0 = make_float2(c0, c1);
                *(float2*)d1 = make_float2(c2, c3);
            } else {
                *(float2*)(CF + (size_t)rowg*1024 + col)       = make_float2(c0, c1);
                *(float2*)(CF + (size_t)(rowg + 8)*1024 + col) = make_float2(c2, c3);
            }
        }
    }
}

// ---------------- attention: cp.async swizzled pipeline, ldmatrix frags ----------------
#define OFF_LOG  0
#define OFF_TILE 66816
#define OFF_Q    (OFF_TILE + 2*3*128*32*4)      // 165120
#define OFF_MISC (OFF_Q + 4*16*36*4)            // 174336
#define ATTN_SMEM_BYTES (OFF_MISC + 256)

__global__ __launch_bounds__(256) void attn_kernel(
                            const float* __restrict__ Qp, int NQ,
                            const __half* __restrict__ kcHg, const __half* __restrict__ kcLg,
                            const __half* __restrict__ kpHg, const __half* __restrict__ kpLg,
                            const __half* __restrict__ vtHg, const __half* __restrict__ vtLg,
                            const float* __restrict__ segenc,
                            const int* __restrict__ segmat,
                            const float* __restrict__ mask,
                            const float* __restrict__ cb, const float* __restrict__ pb,
                            const float* __restrict__ sb,
                            const int* __restrict__ tpos,
                            __half* outH, __half* outL)
{
    extern __shared__ char asm_[];
    float* logitsF = (float*)(asm_ + OFF_LOG);
    uint32_t* tw  = (uint32_t*)(asm_ + OFF_TILE);     // hi tiles; lo at +12288 words
    uint32_t* qw  = (uint32_t*)(asm_ + OFF_Q);        // qcH, qcL, qpH, qpL each 576 words
    float* seg0 = (float*)(asm_ + OFF_MISC);
    float* seg1 = seg0 + 16;
    int*   qrow = (int*)(seg1 + 16);

    const int n  = blockIdx.z, h = blockIdx.y;
    const int nh = n*HH + h;
    const int q0 = blockIdx.x * QT;
    const int tid = threadIdx.x;
    const int wid = tid >> 5, lane = tid & 31;
    const int g = lane >> 2, t = lane & 3;
    const int m2 = lane >> 3, r8 = lane & 7;
    const uint32_t tbase = smem_u32(asm_ + OFF_TILE);
    const uint32_t qbaseS = smem_u32(qw);
    const uint32_t logb = smem_u32(asm_);

    // ---- QK tile loader: swizzle chunk c ^= r&7 ----
    auto ld_qk = [&](int i, int b){
        const char *sH, *sL;
        if (i < 8) {
            size_t off = ((size_t)nh*1024 + (size_t)i*128) * 128;
            sH = (const char*)kcHg + off; sL = (const char*)kcLg + off;
        } else {
            size_t off = ((size_t)nh*1536 + (size_t)(i-8)*128) * 128;
            sH = (const char*)kpHg + off; sL = (const char*)kpLg + off;
        }
#pragma unroll
        for (int j = 0; j < 8; j++) {
            int grp = j >> 2;
            int c2 = (tid + j*256) & 1023;
            int row = c2 >> 3, c = c2 & 7;
            int cc = c ^ (row & 7);
            uint32_t dst = tbase + (grp*12288 + (b*128 + row)*32 + cc*4)*4;
            cpasync16(dst, (grp ? sL : sH) + row*128 + c*16);
        }
        cpcommit();
    };
    // ---- V tile loader: tile rt -> [64 s][64 w], swizzle c ^= s&7 ----
    auto ld_vt = [&](int rt, int b){
#pragma unroll
        for (int j = 0; j < 8; j++) {
            int grp = j >> 2;
            int c2 = (tid + j*256) & 1023;
            int s = c2 >> 4, c = c2 & 15;
            int cc = c ^ (s & 7);
            uint32_t dst = tbase + (grp*12288 + (b*64 + s)*64 + cc*4)*4;
            const char* src = (grp ? (const char*)vtLg : (const char*)vtHg)
                              + ((size_t)nh*64 + s)*2048 + rt*256 + c*16;
            cpasync16(dst, src);
        }
        cpcommit();
    };

    // ---- init: q tiles -> halves in smem; seg dots; qrow ----
    const float* qbase = Qp + ((size_t)nh*NQ + q0)*64;
    {
        int l = tid >> 4, s4 = tid & 15;
        float4 qv = *(const float4*)(qbase + l*64 + s4*4);
        float qa[4] = {qv.x, qv.y, qv.z, qv.w};
        float cbv[4], pbv[4];
#pragma unroll
        for (int i = 0; i < 4; i++) { cbv[i] = cb[h*SS + s4*4 + i]; pbv[i] = pb[h*SS + s4*4 + i]; }
        uint32_t* qcH = qw;            uint32_t* qcL = qw + 576;
        uint32_t* qpH = qw + 1152;     uint32_t* qpL = qw + 1728;
#pragma unroll
        for (int i = 0; i < 2; i++) {
            float a0 = qa[2*i] + cbv[2*i], a1 = qa[2*i+1] + cbv[2*i+1];
            float p0 = qa[2*i] + pbv[2*i], p1 = qa[2*i+1] + pbv[2*i+1];
            qcH[l*36 + s4*2 + i] = pack2(a0, a1, false);
            qcL[l*36 + s4*2 + i] = pack2(a0, a1, true);
            qpH[l*36 + s4*2 + i] = pack2(p0, p1, false);
            qpL[l*36 + s4*2 + i] = pack2(p0, p1, true);
        }
    }
    if (tid < QT) qrow[tid] = tpos ? tpos[n*PPQ + q0 + tid] : (q0 + tid);
    if (tid >= 64 && tid < 64 + 2*QT) {
        int i = tid - 64;
        int l = i >> 1, gg = i & 1;
        float acc = 0.f;
        const float* qr = qbase + l*64;
        const float* se = segenc + ((size_t)gg*HH + h)*SS;
        for (int s = 0; s < SS; s++) acc += (qr[s] + sb[h*SS + s]) * se[s];
        if (gg) seg1[l] = acc; else seg0[l] = acc;
    }

    ld_qk(0, 0);
    ld_qk(1, 1);
    __syncthreads();

    const int qp0 = qrow[g], qp1 = qrow[g + 8];

    // ---- QK pipeline: 20 tiles ----
    for (int i = 0; i < 20; i++) {
        int b = i % 3;
        if (i < 19) cpwait<1>(); else cpwait<0>();
        __syncthreads();
        if (i + 2 < 20) ld_qk(i + 2, (i + 2) % 3);

        uint32_t qselH = qbaseS + ((i < 8) ? 0u : 1152u*4);
        float cres[2][4] = {{0,0,0,0},{0,0,0,0}};
#pragma unroll
        for (int ch = 0; ch < 4; ch++) {
            uint32_t aad = qselH + (uint32_t)(((m2 & 1)*8 + r8)*36)*4 + ch*32 + (m2 >> 1)*16;
            uint32_t aH[4], aL[4];
            ldsm4(aH, aad);
            ldsm4(aL, aad + 576u*4);
            int brow = wid*16 + ((lane >> 4) & 1)*8 + r8;
            int bch = (2*ch + ((lane >> 3) & 1)) ^ r8;
            uint32_t bad = tbase + (uint32_t)((b*128 + brow)*32 + bch*4)*4;
            uint32_t bf[4], bl[4];
            ldsm4(bf, bad);
            ldsm4(bl, bad + 12288u*4);
            mma3h(cres[0], aH, aL, bf,     bl);
            mma3h(cres[1], aH, aL, bf + 2, bl + 2);
        }
        if (i < 8) {
#pragma unroll
            for (int j = 0; j < 2; j++) {
                int base = i*128 + wid*16 + j*8 + 2*t;
                logitsF[g*1044 + base]         = cres[j][0];
                logitsF[g*1044 + base + 1]     = cres[j][1];
                logitsF[(g+8)*1044 + base]     = cres[j][2];
                logitsF[(g+8)*1044 + base + 1] = cres[j][3];
            }
        } else {
            int pt = i - 8;
#pragma unroll
            for (int j = 0; j < 2; j++) {
                int pp = pt*128 + wid*16 + j*8 + 2*t;
                int r;
                r = pp     - 512 + qp0; if (r >= 0 && r < RR) logitsF[g*1044 + r]     += cres[j][0];
                r = pp + 1 - 512 + qp0; if (r >= 0 && r < RR) logitsF[g*1044 + r]     += cres[j][1];
                r = pp     - 512 + qp1; if (r >= 0 && r < RR) logitsF[(g+8)*1044 + r] += cres[j][2];
                r = pp + 1 - 512 + qp1; if (r >= 0 && r < RR) logitsF[(g+8)*1044 + r] += cres[j][3];
            }
        }
    }
    __syncthreads();

    // prefetch first two V tiles under softmax/conversion
    ld_vt(0, 0);
    ld_vt(1, 1);

    // ---- softmax ----
    {
        int row = tid >> 4, l16 = tid & 15;
        int qq = qrow[row];
        const float* mrow = mask + ((size_t)n*QQ + qq)*RR;
        const int* srow = segmat + ((size_t)n*QQ + qq)*RR;
        float s1v = seg1[row], s0v = seg0[row];
        float* lrow = logitsF + row*1044;
        float mx = -3.4e38f;
        for (int i = 0; i < 64; i++) {
            int cc = l16 + 16*i;
            float lg = lrow[cc] + (srow[cc] ? s1v : s0v);
            lg = lg * 0.125f + mrow[cc] * (-1e9f);
            lrow[cc] = lg;
            mx = fmaxf(mx, lg);
        }
        for (int o = 8; o; o >>= 1) mx = fmaxf(mx, __shfl_xor_sync(0xffffffffu, mx, o, 16));
        float sum = 0.f;
        for (int i = 0; i < 64; i++) {
            int cc = l16 + 16*i;
            float e = __expf(lrow[cc] - mx);
            lrow[cc] = e;
            sum += e;
        }
        for (int o = 8; o; o >>= 1) sum += __shfl_xor_sync(0xffffffffu, sum, o, 16);
        float inv = __fdividef(1.f, sum);
        for (int i = 0; i < 64; i++) lrow[l16 + 16*i] *= inv;
    }
    __syncthreads();

    // ---- logits fp32 -> halves in place (hi at +0, lo at +2048 B per 4176 B row) ----
    {
        int rsub = tid >> 6;
        int c0 = (tid & 63) * 16;
        for (int p = 0; p < 4; p++) {
            int row = p*4 + rsub;
            const float* src = logitsF + row*1044;
            float v[16];
#pragma unroll
            for (int i = 0; i < 4; i++) {
                float4 f = *(const float4*)(src + c0 + i*4);
                v[4*i] = f.x; v[4*i+1] = f.y; v[4*i+2] = f.z; v[4*i+3] = f.w;
            }
            __syncthreads();
            uint32_t* wh = (uint32_t*)(asm_ + row*4176);
            uint32_t* wl = (uint32_t*)(asm_ + row*4176 + 2048);
#pragma unroll
            for (int i = 0; i < 8; i++) {
                wh[c0/2 + i] = pack2(v[2*i], v[2*i+1], false);
                wl[c0/2 + i] = pack2(v[2*i], v[2*i+1], true);
            }
            __syncthreads();
        }
    }

    // ---- Phase B: out = weights @ V ----
    {
        float ca[4] = {0,0,0,0}, cbn[4] = {0,0,0,0};
        for (int rt = 0; rt < 8; rt++) {
            int b = rt % 3;
            if (rt < 7) cpwait<1>(); else cpwait<0>();
            __syncthreads();
            if (rt + 2 < 8) ld_vt(rt + 2, (rt + 2) % 3);
#pragma unroll
            for (int ch = 0; ch < 8; ch++) {
                int kw = rt*64 + ch*8;
                uint32_t aad = logb + (uint32_t)((m2 & 1)*8 + r8)*4176 + kw*4 + (m2 >> 1)*16;
                uint32_t aH[4], aL[4];
                ldsm4(aH, aad);
                ldsm4(aL, aad + 2048);
                int srow = wid*8 + r8;
                int vch = (2*ch + ((lane >> 3) & 1)) ^ r8;
                uint32_t bad = tbase + (uint32_t)((b*64 + srow)*64 + vch*4)*4;
                uint32_t bH2[2], bL2[2];
                ldsm2(bH2, bad);
                ldsm2(bL2, bad + 12288u*4);
                mma3h((ch & 1) ? cbn : ca, aH, aL, bH2, bL2);
            }
        }
#pragma unroll
        for (int l = 0; l < 4; l++) ca[l] += cbn[l];
        size_t w0 = ((size_t)(n*NQ + q0 + g    ))*512 + h*32 + wid*4 + t;
        size_t w1 = ((size_t)(n*NQ + q0 + g + 8))*512 + h*32 + wid*4 + t;
        ((uint32_t*)outH)[w0] = pack2(ca[0], ca[1], false);
        ((uint32_t*)outL)[w0] = pack2(ca[0], ca[1], true);
        ((uint32_t*)outH)[w1] = pack2(ca[2], ca[3], false);
        ((uint32_t*)outL)[w1] = pack2(ca[2], ca[3], true);
    }
}

// -------------------- launch --------------------
extern "C" void kernel_launch(void* const* d_in, const int* in_sizes, int n_in,
                              void* d_out, int out_size)
{
    const float* content = (const float*)d_in[0];
    const float* query   = (const float*)d_in[1];
    const float* posenc  = (const float*)d_in[2];
    const float* segenc  = (const float*)d_in[3];
    const int*   segmat  = (const int*)d_in[4];
    const float* tmap    = (const float*)d_in[5];
    const float* cmask   = (const float*)d_in[6];
    const float* qmask   = (const float*)d_in[7];
    const float* cb      = (const float*)d_in[8];
    const float* pb      = (const float*)d_in[9];
    const float* sb      = (const float*)d_in[10];
    const float* mems    = (const float*)d_in[11];
    const float* Wq      = (const float*)d_in[12];
    const float* Wkc     = (const float*)d_in[13];
    const float* Wv      = (const float*)d_in[14];
    const float* Wkp     = (const float*)d_in[15];
    const float* Wo      = (const float*)d_in[16];
    float* out = (float*)d_out;

    __half *ctxH, *ctxL, *posH, *posL, *conH, *conL, *qryH, *qryL, *wH, *wL;
    __half *kcH, *kcL, *kpH, *kpL, *vtH, *vtL, *acH, *acL, *aqH, *aqL;
    float *pv, *pqc, *pqq;
    int* ptpos;
    cudaGetSymbolAddress((void**)&ctxH, g_ctxH); cudaGetSymbolAddress((void**)&ctxL, g_ctxL);
    cudaGetSymbolAddress((void**)&posH, g_posH); cudaGetSymbolAddress((void**)&posL, g_posL);
    cudaGetSymbolAddress((void**)&conH, g_conH); cudaGetSymbolAddress((void**)&conL, g_conL);
    cudaGetSymbolAddress((void**)&qryH, g_qryH); cudaGetSymbolAddress((void**)&qryL, g_qryL);
    cudaGetSymbolAddress((void**)&wH,   g_wH);   cudaGetSymbolAddress((void**)&wL,   g_wL);
    cudaGetSymbolAddress((void**)&kcH,  g_kcH);  cudaGetSymbolAddress((void**)&kcL,  g_kcL);
    cudaGetSymbolAddress((void**)&kpH,  g_kpH);  cudaGetSymbolAddress((void**)&kpL,  g_kpL);
    cudaGetSymbolAddress((void**)&vtH,  g_vtH);  cudaGetSymbolAddress((void**)&vtL,  g_vtL);
    cudaGetSymbolAddress((void**)&acH,  g_acH);  cudaGetSymbolAddress((void**)&acL,  g_acL);
    cudaGetSymbolAddress((void**)&aqH,  g_aqH);  cudaGetSymbolAddress((void**)&aqL,  g_aqL);
    cudaGetSymbolAddress((void**)&pv,   g_v);
    cudaGetSymbolAddress((void**)&pqc,  g_qc);
    cudaGetSymbolAddress((void**)&pqq,  g_qq);
    cudaGetSymbolAddress((void**)&ptpos, g_tpos);

    cudaFuncSetAttribute(gemm_h, cudaFuncAttributeMaxDynamicSharedMemorySize, GEMM_SMEM);
    cudaFuncSetAttribute(attn_kernel, cudaFuncAttributeMaxDynamicSharedMemorySize, ATTN_SMEM_BYTES);

    // converts
    build_ctx_split<<<4096, 256>>>(mems, content);
    split_k<<<6144, 256>>>(posenc,  posH, posL, BB*RP*HID/4);
    split_k<<<2048, 256>>>(content, conH, conL, BB*QQ*HID/4);
    split_k<<<512,  256>>>(query,   qryH, qryL, BB*PPQ*HID/4);
    dim3 wtb(32, 8), wtg(32, 32);
    wtrans<<<wtg, wtb>>>(Wq,  wH + 0*(size_t)HID*HID, wL + 0*(size_t)HID*HID);
    wtrans<<<wtg, wtb>>>(Wkc, wH + 1*(size_t)HID*HID, wL + 1*(size_t)HID*HID);
    wtrans<<<wtg, wtb>>>(Wv,  wH + 2*(size_t)HID*HID, wL + 2*(size_t)HID*HID);
    wtrans<<<wtg, wtb>>>(Wkp, wH + 3*(size_t)HID*HID, wL + 3*(size_t)HID*HID);
    wtrans<<<wtg, wtb>>>(Wo,  wH + 4*(size_t)HID*HID, wL + 4*(size_t)HID*HID);
    find_tpos<<<1, 512>>>(tmap);

    __half* wq_H = wH + 0*(size_t)HID*HID; __half* wq_L = wL + 0*(size_t)HID*HID;
    __half* wkcH = wH + 1*(size_t)HID*HID; __half* wkcL = wL + 1*(size_t)HID*HID;
    __half* wv_H = wH + 2*(size_t)HID*HID; __half* wv_L = wL + 2*(size_t)HID*HID;
    __half* wkpH = wH + 3*(size_t)HID*HID; __half* wkpL = wL + 3*(size_t)HID*HID;
    __half* wo_H = wH + 4*(size_t)HID*HID; __half* wo_L = wL + 4*(size_t)HID*HID;

    gemm_h<<<dim3(8, 32), 256, GEMM_SMEM>>>(ctxH, ctxL, wkcH, wkcL, nullptr, kcH, kcL, RR,  2);
    gemm_h<<<dim3(8, 32), 256, GEMM_SMEM>>>(ctxH, ctxL, wv_H, wv_L, pv, nullptr, nullptr, RR, 1);
    gemm_h<<<dim3(8, 48), 256, GEMM_SMEM>>>(posH, posL, wkpH, wkpL, nullptr, kpH, kpL, RP,  2);
    gemm_h<<<dim3(8, 16), 256, GEMM_SMEM>>>(conH, conL, wq_H, wq_L, pqc, nullptr, nullptr, QQ, 1);
    gemm_h<<<dim3(8, 4),  256, GEMM_SMEM>>>(qryH, qryL, wq_H, wq_L, pqq, nullptr, nullptr, PPQ, 1);
    vtrans<<<NHDIM*8, 256>>>();

    dim3 gac(QQ/QT, HH, BB);
    attn_kernel<<<gac, 256, ATTN_SMEM_BYTES>>>(pqc, QQ, kcH, kcL, kpH, kpL, vtH, vtL,
                                               segenc, segmat, cmask, cb, pb, sb, nullptr, acH, acL);
    dim3 gaq(PPQ/QT, HH, BB);
    attn_kernel<<<gaq, 256, ATTN_SMEM_BYTES>>>(pqq, PPQ, kcH, kcL, kpH, kpL, vtH, vtL,
                                               segenc, segmat, qmask, cb, pb, sb, ptpos, aqH, aqL);

    gemm_h<<<dim3(8, 16), 256, GEMM_SMEM>>>(acH, acL, wo_H, wo_L, out, nullptr, nullptr, 0, 0);
    gemm_h<<<dim3(8, 4),  256, GEMM_SMEM>>>(aqH, aqL, wo_H, wo_L, out + (size_t)BB*QQ*HID, nullptr, nullptr, 0, 0);
}

// round 14
// speedup vs baseline: 1.5200x; 1.0619x over previous
#include <cuda_runtime.h>
#include <cuda_fp16.h>
#include <cstdint>

#define BB  4
#define QQ  512
#define MM  512
#define PPQ 128
#define HID 1024
#define HH  16
#define SS  64
#define RR  1024
#define RP  1536
#define QT  32
#define NHDIM (BB*HH)

// ---------------- global scratch (halves pre-split hi/lo) ----------------
__device__ __align__(16) __half g_ctxH[BB*RR*HID],  g_ctxL[BB*RR*HID];
__device__ __align__(16) __half g_posH[BB*RP*HID],  g_posL[BB*RP*HID];
__device__ __align__(16) __half g_conH[BB*QQ*HID],  g_conL[BB*QQ*HID];
__device__ __align__(16) __half g_qryH[BB*PPQ*HID], g_qryL[BB*PPQ*HID];
__device__ __align__(16) __half g_wH[5*HID*HID],    g_wL[5*HID*HID];   // transposed [n][k-pairs]
__device__ __align__(16) __half g_kcH[BB*RR*HID],   g_kcL[BB*RR*HID];  // [nh][r][64]
__device__ __align__(16) __half g_kpH[BB*RP*HID],   g_kpL[BB*RP*HID];  // [nh][p][64]
__device__ __align__(16) __half g_vtH[BB*RR*HID],   g_vtL[BB*RR*HID];  // [nh][s][r-pairs]
__device__ __align__(16) __half g_acH[BB*QQ*HID],   g_acL[BB*QQ*HID];
__device__ __align__(16) __half g_aqH[BB*PPQ*HID],  g_aqL[BB*PPQ*HID];
__device__ float g_v [BB*RR*HID];    // fp32 [nh][r][64] (for V transpose)
__device__ float g_qc[BB*QQ*HID];    // fp32 [nh][q][64]
__device__ float g_qq[BB*PPQ*HID];
__device__ int   g_tpos[BB*PPQ];

// ---------------- helpers ----------------
__device__ __forceinline__ uint32_t smem_u32(const void* p){
    uint32_t a;
    asm("{ .reg .u64 t; cvta.to.shared.u64 t, %1; cvt.u32.u64 %0, t; }" : "=r"(a) : "l"(p));
    return a;
}
__device__ __forceinline__ void cpasync16(uint32_t s, const void* g){
    asm volatile("cp.async.cg.shared.global [%0], [%1], 16;" :: "r"(s), "l"(g));
}
__device__ __forceinline__ void cpcommit(){ asm volatile("cp.async.commit_group;" ::: "memory"); }
template<int N> __device__ __forceinline__ void cpwait(){ asm volatile("cp.async.wait_group %0;" :: "n"(N) : "memory"); }

__device__ __forceinline__ void ldsm4(uint32_t* r, uint32_t addr){
    asm volatile("ldmatrix.sync.aligned.m8n8.x4.shared.b16 {%0,%1,%2,%3}, [%4];"
        : "=r"(r[0]),"=r"(r[1]),"=r"(r[2]),"=r"(r[3]) : "r"(addr));
}
__device__ __forceinline__ void ldsm2(uint32_t* r, uint32_t addr){
    asm volatile("ldmatrix.sync.aligned.m8n8.x2.shared.b16 {%0,%1}, [%2];"
        : "=r"(r[0]),"=r"(r[1]) : "r"(addr));
}

__device__ __forceinline__ void split_h(float x, __half& h, __half& l){
    h = __float2half_rn(x);
    l = __float2half_rn(x - __half2float(h));
}
__device__ __forceinline__ uint32_t pack2(float a, float b, bool lo){
    __half ha, la, hb, lb;
    split_h(a, ha, la); split_h(b, hb, lb);
    __half2 v = lo ? __halves2half2(la, lb) : __halves2half2(ha, hb);
    return *(uint32_t*)&v;
}
__device__ __forceinline__ void mma_h(float* c, const uint32_t* a, const uint32_t* b){
    asm volatile("mma.sync.aligned.m16n8k16.row.col.f32.f16.f16.f32 "
        "{%0,%1,%2,%3}, {%4,%5,%6,%7}, {%8,%9}, {%0,%1,%2,%3};"
        : "+f"(c[0]),"+f"(c[1]),"+f"(c[2]),"+f"(c[3])
        : "r"(a[0]),"r"(a[1]),"r"(a[2]),"r"(a[3]), "r"(b[0]),"r"(b[1]));
}
__device__ __forceinline__ void mma3h(float* c, const uint32_t* aH, const uint32_t* aL,
                                      const uint32_t* bH, const uint32_t* bL){
    mma_h(c, aH, bH);
    mma_h(c, aH, bL);
    mma_h(c, aL, bH);
}

// ---------------- converts ----------------
__global__ void build_ctx_split(const float* __restrict__ mems, const float* __restrict__ content)
{
    int idx = blockIdx.x * blockDim.x + threadIdx.x;      // float4 index
    const int total = BB*RR*HID/4;
    if (idx >= total) return;
    int d4  = idx & 255;
    int row = idx >> 8;
    int n = row >> 10, r = row & 1023;
    const float* src = (r < MM) ? (mems + ((size_t)n*MM + r)*HID)
                                : (content + ((size_t)n*QQ + (r-MM))*HID);
    float4 v = ((const float4*)src)[d4];
    uint32_t* wh = (uint32_t*)g_ctxH;
    uint32_t* wl = (uint32_t*)g_ctxL;
    wh[idx*2]   = pack2(v.x, v.y, false);
    wh[idx*2+1] = pack2(v.z, v.w, false);
    wl[idx*2]   = pack2(v.x, v.y, true);
    wl[idx*2+1] = pack2(v.z, v.w, true);
}

__global__ void split_k(const float* __restrict__ src, __half* dstH, __half* dstL, int n4)
{
    int idx = blockIdx.x * blockDim.x + threadIdx.x;
    if (idx >= n4) return;
    float4 v = ((const float4*)src)[idx];
    ((uint32_t*)dstH)[idx*2]   = pack2(v.x, v.y, false);
    ((uint32_t*)dstH)[idx*2+1] = pack2(v.z, v.w, false);
    ((uint32_t*)dstL)[idx*2]   = pack2(v.x, v.y, true);
    ((uint32_t*)dstL)[idx*2+1] = pack2(v.z, v.w, true);
}

// W [k][n] -> WT halves [n][k-pairs]
__global__ void wtrans(const float* __restrict__ W, __half* dstH, __half* dstL)
{
    __shared__ float sm[32][33];
    int n0 = blockIdx.x*32, k0 = blockIdx.y*32;
    int tx = threadIdx.x, ty = threadIdx.y;          // (32, 8)
#pragma unroll
    for (int i = 0; i < 4; i++)
        sm[ty + 8*i][tx] = W[(size_t)(k0 + ty + 8*i)*1024 + n0 + tx];
    __syncthreads();
    int tid = ty*32 + tx;
    int w = tid & 15;
#pragma unroll
    for (int p = 0; p < 2; p++) {
        int nn = p*16 + (tid >> 4);
        float a = sm[2*w][nn], b = sm[2*w+1][nn];
        size_t o = (size_t)(n0 + nn)*512 + (k0 >> 1) + w;
        ((uint32_t*)dstH)[o] = pack2(a, b, false);
        ((uint32_t*)dstL)[o] = pack2(a, b, true);
    }
}

// g_v fp32 [nh][r][64] -> vt halves [nh][s][r-pairs]
__global__ void vtrans()
{
    __shared__ float vs[128][65];
    int nh = blockIdx.x >> 3, rc = blockIdx.x & 7;
    int tid = threadIdx.x;
    const float* src = g_v + ((size_t)nh*1024 + rc*128)*64;
#pragma unroll
    for (int i = 0; i < 8; i++) {
        int idx = tid + i*256;
        int r = idx >> 4, f4 = idx & 15;
        float4 v = ((const float4*)(src + (size_t)r*64))[f4];
        vs[r][f4*4] = v.x; vs[r][f4*4+1] = v.y; vs[r][f4*4+2] = v.z; vs[r][f4*4+3] = v.w;
    }
    __syncthreads();
#pragma unroll
    for (int i = 0; i < 16; i++) {
        int idx = tid + i*256;
        int s = idx >> 6, w = idx & 63;
        float a = vs[2*w][s], b = vs[2*w+1][s];
        size_t o = ((size_t)nh*64 + s)*512 + rc*64 + w;
        ((uint32_t*)g_vtH)[o] = pack2(a, b, false);
        ((uint32_t*)g_vtL)[o] = pack2(a, b, true);
    }
}

__global__ void find_tpos(const float* __restrict__ tm)
{
    int i = threadIdx.x;
    const float* row = tm + (size_t)i * QQ;
    int q = 0;
    for (int j = 0; j < QQ; j++) if (row[j] > 0.5f) q = j;
    g_tpos[i] = q;
}

// ---------------- half-split GEMM, cp.async 3-stage, ldmatrix frags ----------------
#define GPW 12
#define G_AH 0
#define G_AL (3*128*GPW)
#define G_BH (2*3*128*GPW)
#define G_BL (3*3*128*GPW)
#define GEMM_SMEM (4*3*128*GPW*4)

__global__ __launch_bounds__(256, 2) void gemm_h(
        const __half* __restrict__ AHg, const __half* __restrict__ ALg,
        const __half* __restrict__ BHg, const __half* __restrict__ BLg,
        float* CF, __half* CHp, __half* CLp, int rowsPB, int mode)
{
    extern __shared__ uint32_t gsm[];
    const uint32_t sbase = smem_u32(gsm);
    const int tid  = threadIdx.x;
    const int wid  = tid >> 5, lane = tid & 31;
    const int wm   = wid & 3,  wn   = wid >> 2;
    const int g    = lane >> 2, t   = lane & 3;
    const int m0   = blockIdx.y * 128;
    const int n0   = blockIdx.x * 128;
    const int m2   = lane >> 3, r8 = lane & 7;

    float c[2][8][4];
#pragma unroll
    for (int i = 0; i < 2; i++)
#pragma unroll
        for (int j = 0; j < 8; j++)
#pragma unroll
            for (int l = 0; l < 4; l++) c[i][j][l] = 0.f;

    const int lrow = tid >> 1, lc = tid & 1;
    auto ldtile = [&](int kt, int b){
        const char* srcs[4] = {
            (const char*)AHg + (size_t)(m0 + lrow)*2048 + kt*32 + lc*16,
            (const char*)ALg + (size_t)(m0 + lrow)*2048 + kt*32 + lc*16,
            (const char*)BHg + (size_t)(n0 + lrow)*2048 + kt*32 + lc*16,
            (const char*)BLg + (size_t)(n0 + lrow)*2048 + kt*32 + lc*16 };
        const int bases[4] = {G_AH, G_AL, G_BH, G_BL};
#pragma unroll
        for (int i = 0; i < 4; i++)
            cpasync16(sbase + (bases[i] + (b*128 + lrow)*GPW + lc*4)*4, srcs[i]);
        cpcommit();
    };

    ldtile(0, 0);
    ldtile(1, 1);

    for (int kt = 0; kt < 64; kt++) {
        int b = kt % 3;
        if (kt < 63) cpwait<1>(); else cpwait<0>();
        __syncthreads();
        if (kt + 2 < 64) ldtile(kt + 2, (kt + 2) % 3);

        uint32_t aH[2][4], aL[2][4];
#pragma unroll
        for (int mt = 0; mt < 2; mt++) {
            int row = wm*32 + mt*16 + (m2 & 1)*8 + r8;
            uint32_t ad = sbase + (uint32_t)(G_AH + (b*128 + row)*GPW)*4 + (m2 >> 1)*16;
            ldsm4(aH[mt], ad);
            ldsm4(aL[mt], ad + (uint32_t)(G_AL - G_AH)*4);
        }
#pragma unroll
        for (int p = 0; p < 4; p++) {
            int brow = wn*64 + p*16 + ((lane >> 4) & 1)*8 + r8;
            uint32_t bd = sbase + (uint32_t)(G_BH + (b*128 + brow)*GPW)*4 + ((lane >> 3) & 1)*16;
            uint32_t bf[4], bl[4];
            ldsm4(bf, bd);
            ldsm4(bl, bd + (uint32_t)(G_BL - G_BH)*4);
#pragma unroll
            for (int mt = 0; mt < 2; mt++) {
                mma3h(c[mt][2*p],     aH[mt], aL[mt], bf,     bl);
                mma3h(c[mt][2*p + 1], aH[mt], aL[mt], bf + 2, bl + 2);
            }
        }
    }

#pragma unroll
    for (int mt = 0; mt < 2; mt++) {
        int rowg = m0 + wm*32 + mt*16 + g;
#pragma unroll
        for (int nt = 0; nt < 8; nt++) {
            int col = n0 + wn*64 + nt*8 + 2*t;
            float c0 = c[mt][nt][0], c1 = c[mt][nt][1], c2 = c[mt][nt][2], c3 = c[mt][nt][3];
            if (mode == 2) {
                int nn = rowg / rowsPB, r = rowg % rowsPB;
                int hh = col >> 6, ss = col & 63;
                size_t w0 = ((size_t)(nn*HH + hh)*rowsPB + r)*32 + (ss >> 1);
                size_t w1 = w0 + 8*32;
                ((uint32_t*)CHp)[w0] = pack2(c0, c1, false);
                ((uint32_t*)CLp)[w0] = pack2(c0, c1, true);
                ((uint32_t*)CHp)[w1] = pack2(c2, c3, false);
                ((uint32_t*)CLp)[w1] = pack2(c2, c3, true);
            } else if (mode == 1) {
                int nn = rowg / rowsPB, r = rowg % rowsPB;
                int hh = col >> 6, ss = col & 63;
                float* d0 = CF + ((size_t)(nn*HH + hh)*rowsPB + r)*64 + ss;
                float* d1 = CF + ((size_t)(nn*HH + hh)*rowsPB + r + 8)*64 + ss;
                *(float2*)d0 = make_float2(c0, c1);
                *(float2*)d1 = make_float2(c2, c3);
            } else {
                *(float2*)(CF + (size_t)rowg*1024 + col)       = make_float2(c0, c1);
                *(float2*)(CF + (size_t)(rowg + 8)*1024 + col) = make_float2(c2, c3);
            }
        }
    }
}

// ---------------- attention: QT=32, 512 threads, 2-stage cp.async, ldmatrix ----------------
// smem: logits fp32 [32][1044] (halves in place after softmax, hi +0 / lo +2048 per 4176B row)
//       tiles: hi [2][128][32w] + lo [2][128][32w] (V overlays [2][64][64w])
//       q halves: qcH,qcL,qpH,qpL each [32][36w]
#define OFF_LOG  0
#define OFF_TILE (32*1044*4)                    // 133632
#define OFF_Q    (OFF_TILE + 2*2*128*32*4)      // 199168
#define OFF_MISC (OFF_Q + 4*32*36*4)            // 217600
#define ATTN_SMEM_BYTES (OFF_MISC + 384)

__global__ __launch_bounds__(512) void attn_kernel(
                            const float* __restrict__ Qp, int NQ,
                            const __half* __restrict__ kcHg, const __half* __restrict__ kcLg,
                            const __half* __restrict__ kpHg, const __half* __restrict__ kpLg,
                            const __half* __restrict__ vtHg, const __half* __restrict__ vtLg,
                            const float* __restrict__ segenc,
                            const int* __restrict__ segmat,
                            const float* __restrict__ mask,
                            const float* __restrict__ cb, const float* __restrict__ pb,
                            const float* __restrict__ sb,
                            const int* __restrict__ tpos,
                            __half* outH, __half* outL)
{
    extern __shared__ char asm_[];
    float* logitsF = (float*)(asm_ + OFF_LOG);
    uint32_t* qw  = (uint32_t*)(asm_ + OFF_Q);        // qcH, qcL, qpH, qpL each 1152 words
    float* seg0 = (float*)(asm_ + OFF_MISC);          // 32
    float* seg1 = seg0 + 32;                          // 32
    int*   qrow = (int*)(seg1 + 32);                  // 32

    const int n  = blockIdx.z, h = blockIdx.y;
    const int nh = n*HH + h;
    const int q0 = blockIdx.x * QT;
    const int tid = threadIdx.x;
    const int wid = tid >> 5, lane = tid & 31;
    const int g = lane >> 2, t = lane & 3;
    const int m2 = lane >> 3, r8 = lane & 7;
    const int wq = wid >> 3;                          // 0/1: q subgroup
    const int wr = wid & 7;                           // r-range (QK) / s-range (AV)
    const uint32_t tbase = smem_u32(asm_ + OFF_TILE);
    const uint32_t qbaseS = smem_u32(qw);
    const uint32_t logb = smem_u32(asm_);

    // ---- QK tile loader: 2 stages; lo at +8192 words; swizzle chunk c ^= r&7 ----
    auto ld_qk = [&](int i, int b){
        const char *sH, *sL;
        if (i < 8) {
            size_t off = ((size_t)nh*1024 + (size_t)i*128) * 128;
            sH = (const char*)kcHg + off; sL = (const char*)kcLg + off;
        } else {
            size_t off = ((size_t)nh*1536 + (size_t)(i-8)*128) * 128;
            sH = (const char*)kpHg + off; sL = (const char*)kpLg + off;
        }
#pragma unroll
        for (int j = 0; j < 4; j++) {
            int idx = tid + j*512;
            int grp = idx >> 10;
            int c2 = idx & 1023;
            int row = c2 >> 3, c = c2 & 7;
            int cc = c ^ (row & 7);
            uint32_t dst = tbase + (grp*8192 + (b*128 + row)*32 + cc*4)*4;
            cpasync16(dst, (grp ? sL : sH) + row*128 + c*16);
        }
        cpcommit();
    };
    // ---- V tile loader: [64 s][64 w] per stage; swizzle c ^= s&7 ----
    auto ld_vt = [&](int rt, int b){
#pragma unroll
        for (int j = 0; j < 4; j++) {
            int idx = tid + j*512;
            int grp = idx >> 10;
            int c2 = idx & 1023;
            int s = c2 >> 4, c = c2 & 15;
            int cc = c ^ (s & 7);
            uint32_t dst = tbase + (grp*8192 + (b*64 + s)*64 + cc*4)*4;
            const char* src = (grp ? (const char*)vtLg : (const char*)vtHg)
                              + ((size_t)nh*64 + s)*2048 + rt*256 + c*16;
            cpasync16(dst, src);
        }
        cpcommit();
    };

    // ---- init: q tiles -> halves in smem; seg dots; qrow ----
    const float* qbase = Qp + ((size_t)nh*NQ + q0)*64;
    {
        int l = tid >> 4, s4 = tid & 15;      // 512 threads: 32 rows x 16 float4
        float4 qv = *(const float4*)(qbase + l*64 + s4*4);
        float qa[4] = {qv.x, qv.y, qv.z, qv.w};
        float cbv[4], pbv[4];
#pragma unroll
        for (int i = 0; i < 4; i++) { cbv[i] = cb[h*SS + s4*4 + i]; pbv[i] = pb[h*SS + s4*4 + i]; }
        uint32_t* qcH = qw;             uint32_t* qcL = qw + 1152;
        uint32_t* qpH = qw + 2304;      uint32_t* qpL = qw + 3456;
#pragma unroll
        for (int i = 0; i < 2; i++) {
            float a0 = qa[2*i] + cbv[2*i], a1 = qa[2*i+1] + cbv[2*i+1];
            float p0 = qa[2*i] + pbv[2*i], p1 = qa[2*i+1] + pbv[2*i+1];
            qcH[l*36 + s4*2 + i] = pack2(a0, a1, false);
            qcL[l*36 + s4*2 + i] = pack2(a0, a1, true);
            qpH[l*36 + s4*2 + i] = pack2(p0, p1, false);
            qpL[l*36 + s4*2 + i] = pack2(p0, p1, true);
        }
    }
    if (tid < QT) qrow[tid] = tpos ? tpos[n*PPQ + q0 + tid] : (q0 + tid);
    if (tid >= 64 && tid < 64 + 2*QT) {
        int i = tid - 64;
        int l = i >> 1, gg = i & 1;
        float acc = 0.f;
        const float* qr = qbase + l*64;
        const float* se = segenc + ((size_t)gg*HH + h)*SS;
        for (int s = 0; s < SS; s++) acc += (qr[s] + sb[h*SS + s]) * se[s];
        if (gg) seg1[l] = acc; else seg0[l] = acc;
    }

    ld_qk(0, 0);
    __syncthreads();     // q smem + qrow + seg visible

    const int qp0 = qrow[wq*16 + g], qp1 = qrow[wq*16 + g + 8];

    // ---- QK pipeline: 20 tiles, 2-stage, prefetch depth 1 ----
    for (int i = 0; i < 20; i++) {
        int b = i & 1;
        if (i + 1 < 20) { ld_qk(i + 1, (i + 1) & 1); cpwait<1>(); }
        else            { cpwait<0>(); }
        __syncthreads();

        uint32_t qsel = qbaseS + ((i < 8) ? 0u : 2304u*4);
        float cres[2][4] = {{0,0,0,0},{0,0,0,0}};
#pragma unroll
        for (int ch = 0; ch < 4; ch++) {
            uint32_t aad = qsel + (uint32_t)((wq*16 + (m2 & 1)*8 + r8)*36)*4 + ch*32 + (m2 >> 1)*16;
            uint32_t aH[4], aL[4];
            ldsm4(aH, aad);
            ldsm4(aL, aad + 1152u*4);
            int brow = wr*16 + ((lane >> 4) & 1)*8 + r8;
            int bch = (2*ch + ((lane >> 3) & 1)) ^ r8;
            uint32_t bad = tbase + (uint32_t)((b*128 + brow)*32 + bch*4)*4;
            uint32_t bf[4], bl[4];
            ldsm4(bf, bad);
            ldsm4(bl, bad + 8192u*4);
            mma3h(cres[0], aH, aL, bf,     bl);
            mma3h(cres[1], aH, aL, bf + 2, bl + 2);
        }
        if (i < 8) {
#pragma unroll
            for (int j = 0; j < 2; j++) {
                int base = i*128 + wr*16 + j*8 + 2*t;
                logitsF[(wq*16 + g    )*1044 + base]     = cres[j][0];
                logitsF[(wq*16 + g    )*1044 + base + 1] = cres[j][1];
                logitsF[(wq*16 + g + 8)*1044 + base]     = cres[j][2];
                logitsF[(wq*16 + g + 8)*1044 + base + 1] = cres[j][3];
            }
        } else {
            int pt = i - 8;
#pragma unroll
            for (int j = 0; j < 2; j++) {
                int pp = pt*128 + wr*16 + j*8 + 2*t;
                int r;
                r = pp     - 512 + qp0; if (r >= 0 && r < RR) logitsF[(wq*16 + g    )*1044 + r] += cres[j][0];
                r = pp + 1 - 512 + qp0; if (r >= 0 && r < RR) logitsF[(wq*16 + g    )*1044 + r] += cres[j][1];
                r = pp     - 512 + qp1; if (r >= 0 && r < RR) logitsF[(wq*16 + g + 8)*1044 + r] += cres[j][2];
                r = pp + 1 - 512 + qp1; if (r >= 0 && r < RR) logitsF[(wq*16 + g + 8)*1044 + r] += cres[j][3];
            }
        }
        __syncthreads();
    }

    // prefetch first V tile under softmax/conversion
    ld_vt(0, 0);

    // ---- softmax: 16 threads per row, 32 rows ----
    {
        int row = tid >> 4, l16 = tid & 15;
        int qq = qrow[row];
        const float* mrow = mask + ((size_t)n*QQ + qq)*RR;
        const int* srow = segmat + ((size_t)n*QQ + qq)*RR;
        float s1v = seg1[row], s0v = seg0[row];
        float* lrow = logitsF + row*1044;
        float mx = -3.4e38f;
        for (int i = 0; i < 64; i++) {
            int cc = l16 + 16*i;
            float lg = lrow[cc] + (srow[cc] ? s1v : s0v);
            lg = lg * 0.125f + mrow[cc] * (-1e9f);
            lrow[cc] = lg;
            mx = fmaxf(mx, lg);
        }
        for (int o = 8; o; o >>= 1) mx = fmaxf(mx, __shfl_xor_sync(0xffffffffu, mx, o, 16));
        float sum = 0.f;
        for (int i = 0; i < 64; i++) {
            int cc = l16 + 16*i;
            float e = __expf(lrow[cc] - mx);
            lrow[cc] = e;
            sum += e;
        }
        for (int o = 8; o; o >>= 1) sum += __shfl_xor_sync(0xffffffffu, sum, o, 16);
        float inv = __fdividef(1.f, sum);
        for (int i = 0; i < 64; i++) lrow[l16 + 16*i] *= inv;
    }
    __syncthreads();

    // ---- logits fp32 -> halves in place (hi +0, lo +2048 per 4176 B row) ----
    {
        int rsub = tid >> 6;                 // 0..7
        int c0 = (tid & 63) * 16;
        for (int p = 0; p < 4; p++) {
            int row = p*8 + rsub;
            const float* src = logitsF + row*1044;
            float v[16];
#pragma unroll
            for (int i = 0; i < 4; i++) {
                float4 f = *(const float4*)(src + c0 + i*4);
                v[4*i] = f.x; v[4*i+1] = f.y; v[4*i+2] = f.z; v[4*i+3] = f.w;
            }
            __syncthreads();
            uint32_t* wh = (uint32_t*)(asm_ + row*4176);
            uint32_t* wl = (uint32_t*)(asm_ + row*4176 + 2048);
#pragma unroll
            for (int i = 0; i < 8; i++) {
                wh[c0/2 + i] = pack2(v[2*i], v[2*i+1], false);
                wl[c0/2 + i] = pack2(v[2*i], v[2*i+1], true);
            }
            __syncthreads();
        }
    }

    // ---- Phase B: out = weights @ V, 2-stage over 8 tiles ----
    {
        float ca[4] = {0,0,0,0}, cbn[4] = {0,0,0,0};
        for (int rt = 0; rt < 8; rt++) {
            int b = rt & 1;
            if (rt + 1 < 8) { ld_vt(rt + 1, (rt + 1) & 1); cpwait<1>(); }
            else            { cpwait<0>(); }
            __syncthreads();
#pragma unroll
            for (int ch = 0; ch < 8; ch++) {
                int kw = rt*64 + ch*8;
                uint32_t aad = logb + (uint32_t)((wq*16 + (m2 & 1)*8 + r8)*4176) + kw*4 + (m2 >> 1)*16;
                uint32_t aH[4], aL[4];
                ldsm4(aH, aad);
                ldsm4(aL, aad + 2048);
                int srow = wr*8 + r8;
                int vch = (2*ch + ((lane >> 3) & 1)) ^ r8;
                uint32_t bad = tbase + (uint32_t)((b*64 + srow)*64 + vch*4)*4;
                uint32_t bH2[2], bL2[2];
                ldsm2(bH2, bad);
                ldsm2(bL2, bad + 8192u*4);
                mma3h((ch & 1) ? cbn : ca, aH, aL, bH2, bL2);
            }
            __syncthreads();
        }
#pragma unroll
        for (int l = 0; l < 4; l++) ca[l] += cbn[l];
        size_t w0 = ((size_t)(n*NQ + q0 + wq*16 + g    ))*512 + h*32 + wr*4 + t;
        size_t w1 = ((size_t)(n*NQ + q0 + wq*16 + g + 8))*512 + h*32 + wr*4 + t;
        ((uint32_t*)outH)[w0] = pack2(ca[0], ca[1], false);
        ((uint32_t*)outL)[w0] = pack2(ca[0], ca[1], true);
        ((uint32_t*)outH)[w1] = pack2(ca[2], ca[3], false);
        ((uint32_t*)outL)[w1] = pack2(ca[2], ca[3], true);
    }
}

// -------------------- launch --------------------
extern "C" void kernel_launch(void* const* d_in, const int* in_sizes, int n_in,
                              void* d_out, int out_size)
{
    const float* content = (const float*)d_in[0];
    const float* query   = (const float*)d_in[1];
    const float* posenc  = (const float*)d_in[2];
    const float* segenc  = (const float*)d_in[3];
    const int*   segmat  = (const int*)d_in[4];
    const float* tmap    = (const float*)d_in[5];
    const float* cmask   = (const float*)d_in[6];
    const float* qmask   = (const float*)d_in[7];
    const float* cb      = (const float*)d_in[8];
    const float* pb      = (const float*)d_in[9];
    const float* sb      = (const float*)d_in[10];
    const float* mems    = (const float*)d_in[11];
    const float* Wq      = (const float*)d_in[12];
    const float* Wkc     = (const float*)d_in[13];
    const float* Wv      = (const float*)d_in[14];
    const float* Wkp     = (const float*)d_in[15];
    const float* Wo      = (const float*)d_in[16];
    float* out = (float*)d_out;

    __half *ctxH, *ctxL, *posH, *posL, *conH, *conL, *qryH, *qryL, *wH, *wL;
    __half *kcH, *kcL, *kpH, *kpL, *vtH, *vtL, *acH, *acL, *aqH, *aqL;
    float *pv, *pqc, *pqq;
    int* ptpos;
    cudaGetSymbolAddress((void**)&ctxH, g_ctxH); cudaGetSymbolAddress((void**)&ctxL, g_ctxL);
    cudaGetSymbolAddress((void**)&posH, g_posH); cudaGetSymbolAddress((void**)&posL, g_posL);
    cudaGetSymbolAddress((void**)&conH, g_conH); cudaGetSymbolAddress((void**)&conL, g_conL);
    cudaGetSymbolAddress((void**)&qryH, g_qryH); cudaGetSymbolAddress((void**)&qryL, g_qryL);
    cudaGetSymbolAddress((void**)&wH,   g_wH);   cudaGetSymbolAddress((void**)&wL,   g_wL);
    cudaGetSymbolAddress((void**)&kcH,  g_kcH);  cudaGetSymbolAddress((void**)&kcL,  g_kcL);
    cudaGetSymbolAddress((void**)&kpH,  g_kpH);  cudaGetSymbolAddress((void**)&kpL,  g_kpL);
    cudaGetSymbolAddress((void**)&vtH,  g_vtH);  cudaGetSymbolAddress((void**)&vtL,  g_vtL);
    cudaGetSymbolAddress((void**)&acH,  g_acH);  cudaGetSymbolAddress((void**)&acL,  g_acL);
    cudaGetSymbolAddress((void**)&aqH,  g_aqH);  cudaGetSymbolAddress((void**)&aqL,  g_aqL);
    cudaGetSymbolAddress((void**)&pv,   g_v);
    cudaGetSymbolAddress((void**)&pqc,  g_qc);
    cudaGetSymbolAddress((void**)&pqq,  g_qq);
    cudaGetSymbolAddress((void**)&ptpos, g_tpos);

    cudaFuncSetAttribute(gemm_h, cudaFuncAttributeMaxDynamicSharedMemorySize, GEMM_SMEM);
    cudaFuncSetAttribute(attn_kernel, cudaFuncAttributeMaxDynamicSharedMemorySize, ATTN_SMEM_BYTES);

    // converts
    build_ctx_split<<<4096, 256>>>(mems, content);
    split_k<<<6144, 256>>>(posenc,  posH, posL, BB*RP*HID/4);
    split_k<<<2048, 256>>>(content, conH, conL, BB*QQ*HID/4);
    split_k<<<512,  256>>>(query,   qryH, qryL, BB*PPQ*HID/4);
    dim3 wtb(32, 8), wtg(32, 32);
    wtrans<<<wtg, wtb>>>(Wq,  wH + 0*(size_t)HID*HID, wL + 0*(size_t)HID*HID);
    wtrans<<<wtg, wtb>>>(Wkc, wH + 1*(size_t)HID*HID, wL + 1*(size_t)HID*HID);
    wtrans<<<wtg, wtb>>>(Wv,  wH + 2*(size_t)HID*HID, wL + 2*(size_t)HID*HID);
    wtrans<<<wtg, wtb>>>(Wkp, wH + 3*(size_t)HID*HID, wL + 3*(size_t)HID*HID);
    wtrans<<<wtg, wtb>>>(Wo,  wH + 4*(size_t)HID*HID, wL + 4*(size_t)HID*HID);
    find_tpos<<<1, 512>>>(tmap);

    __half* wq_H = wH + 0*(size_t)HID*HID; __half* wq_L = wL + 0*(size_t)HID*HID;
    __half* wkcH = wH + 1*(size_t)HID*HID; __half* wkcL = wL + 1*(size_t)HID*HID;
    __half* wv_H = wH + 2*(size_t)HID*HID; __half* wv_L = wL + 2*(size_t)HID*HID;
    __half* wkpH = wH + 3*(size_t)HID*HID; __half* wkpL = wL + 3*(size_t)HID*HID;
    __half* wo_H = wH + 4*(size_t)HID*HID; __half* wo_L = wL + 4*(size_t)HID*HID;

    gemm_h<<<dim3(8, 32), 256, GEMM_SMEM>>>(ctxH, ctxL, wkcH, wkcL, nullptr, kcH, kcL, RR,  2);
    gemm_h<<<dim3(8, 32), 256, GEMM_SMEM>>>(ctxH, ctxL, wv_H, wv_L, pv, nullptr, nullptr, RR, 1);
    gemm_h<<<dim3(8, 48), 256, GEMM_SMEM>>>(posH, posL, wkpH, wkpL, nullptr, kpH, kpL, RP,  2);
    gemm_h<<<dim3(8, 16), 256, GEMM_SMEM>>>(conH, conL, wq_H, wq_L, pqc, nullptr, nullptr, QQ, 1);
    gemm_h<<<dim3(8, 4),  256, GEMM_SMEM>>>(qryH, qryL, wq_H, wq_L, pqq, nullptr, nullptr, PPQ, 1);
    vtrans<<<NHDIM*8, 256>>>();

    dim3 gac(QQ/QT, HH, BB);
    attn_kernel<<<gac, 512, ATTN_SMEM_BYTES>>>(pqc, QQ, kcH, kcL, kpH, kpL, vtH, vtL,
                                               segenc, segmat, cmask, cb, pb, sb, nullptr, acH, acL);
    dim3 gaq(PPQ/QT, HH, BB);
    attn_kernel<<<gaq, 512, ATTN_SMEM_BYTES>>>(pqq, PPQ, kcH, kcL, kpH, kpL, vtH, vtL,
                                               segenc, segmat, qmask, cb, pb, sb, ptpos, aqH, aqL);

    gemm_h<<<dim3(8, 16), 256, GEMM_SMEM>>>(acH, acL, wo_H, wo_L, out, nullptr, nullptr, 0, 0);
    gemm_h<<<dim3(8, 4),  256, GEMM_SMEM>>>(aqH, aqL, wo_H, wo_L, out + (size_t)BB*QQ*HID, nullptr, nullptr, 0, 0);
}

// round 15
// speedup vs baseline: 1.6120x; 1.0605x over previous
#include <cuda_runtime.h>
#include <cuda_fp16.h>
#include <cstdint>

#define BB  4
#define QQ  512
#define MM  512
#define PPQ 128
#define HID 1024
#define HH  16
#define SS  64
#define RR  1024
#define RP  1536
#define QT  32
#define NHDIM (BB*HH)

// ---------------- global scratch (halves pre-split hi/lo) ----------------
__device__ __align__(16) __half g_ctxH[BB*RR*HID],  g_ctxL[BB*RR*HID];
__device__ __align__(16) __half g_posH[BB*RP*HID],  g_posL[BB*RP*HID];
__device__ __align__(16) __half g_conH[BB*QQ*HID],  g_conL[BB*QQ*HID];
__device__ __align__(16) __half g_qryH[BB*PPQ*HID], g_qryL[BB*PPQ*HID];
__device__ __align__(16) __half g_wH[5*HID*HID],    g_wL[5*HID*HID];   // transposed [n][k-pairs]
__device__ __align__(16) __half g_kcH[BB*RR*HID],   g_kcL[BB*RR*HID];  // [nh][r][64]
__device__ __align__(16) __half g_kpH[BB*RP*HID],   g_kpL[BB*RP*HID];  // [nh][p][64]
__device__ __align__(16) __half g_vtH[BB*RR*HID],   g_vtL[BB*RR*HID];  // [nh][s][r-pairs]
__device__ __align__(16) __half g_acH[BB*QQ*HID],   g_acL[BB*QQ*HID];
__device__ __align__(16) __half g_aqH[BB*PPQ*HID],  g_aqL[BB*PPQ*HID];
__device__ float g_v [BB*RR*HID];    // fp32 [nh][r][64] (for V transpose)
__device__ float g_qc[BB*QQ*HID];    // fp32 [nh][q][64]
__device__ float g_qq[BB*PPQ*HID];
__device__ int   g_tpos[BB*PPQ];

// ---------------- helpers ----------------
__device__ __forceinline__ uint32_t smem_u32(const void* p){
    uint32_t a;
    asm("{ .reg .u64 t; cvta.to.shared.u64 t, %1; cvt.u32.u64 %0, t; }" : "=r"(a) : "l"(p));
    return a;
}
__device__ __forceinline__ void cpasync16(uint32_t s, const void* g){
    asm volatile("cp.async.cg.shared.global [%0], [%1], 16;" :: "r"(s), "l"(g));
}
__device__ __forceinline__ void cpcommit(){ asm volatile("cp.async.commit_group;" ::: "memory"); }
template<int N> __device__ __forceinline__ void cpwait(){ asm volatile("cp.async.wait_group %0;" :: "n"(N) : "memory"); }

__device__ __forceinline__ void ldsm4(uint32_t* r, uint32_t addr){
    asm volatile("ldmatrix.sync.aligned.m8n8.x4.shared.b16 {%0,%1,%2,%3}, [%4];"
        : "=r"(r[0]),"=r"(r[1]),"=r"(r[2]),"=r"(r[3]) : "r"(addr));
}
__device__ __forceinline__ void ldsm2(uint32_t* r, uint32_t addr){
    asm volatile("ldmatrix.sync.aligned.m8n8.x2.shared.b16 {%0,%1}, [%2];"
        : "=r"(r[0]),"=r"(r[1]) : "r"(addr));
}

__device__ __forceinline__ void split_h(float x, __half& h, __half& l){
    h = __float2half_rn(x);
    l = __float2half_rn(x - __half2float(h));
}
__device__ __forceinline__ uint32_t pack2(float a, float b, bool lo){
    __half ha, la, hb, lb;
    split_h(a, ha, la); split_h(b, hb, lb);
    __half2 v = lo ? __halves2half2(la, lb) : __halves2half2(ha, hb);
    return *(uint32_t*)&v;
}
__device__ __forceinline__ void mma_h(float* c, const uint32_t* a, const uint32_t* b){
    asm volatile("mma.sync.aligned.m16n8k16.row.col.f32.f16.f16.f32 "
        "{%0,%1,%2,%3}, {%4,%5,%6,%7}, {%8,%9}, {%0,%1,%2,%3};"
        : "+f"(c[0]),"+f"(c[1]),"+f"(c[2]),"+f"(c[3])
        : "r"(a[0]),"r"(a[1]),"r"(a[2]),"r"(a[3]), "r"(b[0]),"r"(b[1]));
}
__device__ __forceinline__ void mma3h(float* c, const uint32_t* aH, const uint32_t* aL,
                                      const uint32_t* bH, const uint32_t* bL){
    mma_h(c, aH, bH);
    mma_h(c, aH, bL);
    mma_h(c, aL, bH);
}

// ---------------- converts ----------------
__global__ void build_ctx_split(const float* __restrict__ mems, const float* __restrict__ content)
{
    int idx = blockIdx.x * blockDim.x + threadIdx.x;      // float4 index
    const int total = BB*RR*HID/4;
    if (idx >= total) return;
    int d4  = idx & 255;
    int row = idx >> 8;
    int n = row >> 10, r = row & 1023;
    const float* src = (r < MM) ? (mems + ((size_t)n*MM + r)*HID)
                                : (content + ((size_t)n*QQ + (r-MM))*HID);
    float4 v = ((const float4*)src)[d4];
    uint32_t* wh = (uint32_t*)g_ctxH;
    uint32_t* wl = (uint32_t*)g_ctxL;
    wh[idx*2]   = pack2(v.x, v.y, false);
    wh[idx*2+1] = pack2(v.z, v.w, false);
    wl[idx*2]   = pack2(v.x, v.y, true);
    wl[idx*2+1] = pack2(v.z, v.w, true);
}

__global__ void split_k(const float* __restrict__ src, __half* dstH, __half* dstL, int n4)
{
    int idx = blockIdx.x * blockDim.x + threadIdx.x;
    if (idx >= n4) return;
    float4 v = ((const float4*)src)[idx];
    ((uint32_t*)dstH)[idx*2]   = pack2(v.x, v.y, false);
    ((uint32_t*)dstH)[idx*2+1] = pack2(v.z, v.w, false);
    ((uint32_t*)dstL)[idx*2]   = pack2(v.x, v.y, true);
    ((uint32_t*)dstL)[idx*2+1] = pack2(v.z, v.w, true);
}

// W [k][n] -> WT halves [n][k-pairs]
__global__ void wtrans(const float* __restrict__ W, __half* dstH, __half* dstL)
{
    __shared__ float sm[32][33];
    int n0 = blockIdx.x*32, k0 = blockIdx.y*32;
    int tx = threadIdx.x, ty = threadIdx.y;          // (32, 8)
#pragma unroll
    for (int i = 0; i < 4; i++)
        sm[ty + 8*i][tx] = W[(size_t)(k0 + ty + 8*i)*1024 + n0 + tx];
    __syncthreads();
    int tid = ty*32 + tx;
    int w = tid & 15;
#pragma unroll
    for (int p = 0; p < 2; p++) {
        int nn = p*16 + (tid >> 4);
        float a = sm[2*w][nn], b = sm[2*w+1][nn];
        size_t o = (size_t)(n0 + nn)*512 + (k0 >> 1) + w;
        ((uint32_t*)dstH)[o] = pack2(a, b, false);
        ((uint32_t*)dstL)[o] = pack2(a, b, true);
    }
}

// g_v fp32 [nh][r][64] -> vt halves [nh][s][r-pairs]
__global__ void vtrans()
{
    __shared__ float vs[128][65];
    int nh = blockIdx.x >> 3, rc = blockIdx.x & 7;
    int tid = threadIdx.x;
    const float* src = g_v + ((size_t)nh*1024 + rc*128)*64;
#pragma unroll
    for (int i = 0; i < 8; i++) {
        int idx = tid + i*256;
        int r = idx >> 4, f4 = idx & 15;
        float4 v = ((const float4*)(src + (size_t)r*64))[f4];
        vs[r][f4*4] = v.x; vs[r][f4*4+1] = v.y; vs[r][f4*4+2] = v.z; vs[r][f4*4+3] = v.w;
    }
    __syncthreads();
#pragma unroll
    for (int i = 0; i < 16; i++) {
        int idx = tid + i*256;
        int s = idx >> 6, w = idx & 63;
        float a = vs[2*w][s], b = vs[2*w+1][s];
        size_t o = ((size_t)nh*64 + s)*512 + rc*64 + w;
        ((uint32_t*)g_vtH)[o] = pack2(a, b, false);
        ((uint32_t*)g_vtL)[o] = pack2(a, b, true);
    }
}

__global__ void find_tpos(const float* __restrict__ tm)
{
    int i = threadIdx.x;
    const float* row = tm + (size_t)i * QQ;
    int q = 0;
    for (int j = 0; j < QQ; j++) if (row[j] > 0.5f) q = j;
    g_tpos[i] = q;
}

// ---------------- half-split GEMM, cp.async 3-stage, ldmatrix frags ----------------
#define GPW 12
#define G_AH 0
#define G_AL (3*128*GPW)
#define G_BH (2*3*128*GPW)
#define G_BL (3*3*128*GPW)
#define GEMM_SMEM (4*3*128*GPW*4)

__global__ __launch_bounds__(256, 2) void gemm_h(
        const __half* __restrict__ AHg, const __half* __restrict__ ALg,
        const __half* __restrict__ BHg, const __half* __restrict__ BLg,
        float* CF, __half* CHp, __half* CLp, int rowsPB, int mode)
{
    extern __shared__ uint32_t gsm[];
    const uint32_t sbase = smem_u32(gsm);
    const int tid  = threadIdx.x;
    const int wid  = tid >> 5, lane = tid & 31;
    const int wm   = wid & 3,  wn   = wid >> 2;
    const int g    = lane >> 2, t   = lane & 3;
    const int m0   = blockIdx.y * 128;
    const int n0   = blockIdx.x * 128;
    const int m2   = lane >> 3, r8 = lane & 7;

    float c[2][8][4];
#pragma unroll
    for (int i = 0; i < 2; i++)
#pragma unroll
        for (int j = 0; j < 8; j++)
#pragma unroll
            for (int l = 0; l < 4; l++) c[i][j][l] = 0.f;

    const int lrow = tid >> 1, lc = tid & 1;
    auto ldtile = [&](int kt, int b){
        const char* srcs[4] = {
            (const char*)AHg + (size_t)(m0 + lrow)*2048 + kt*32 + lc*16,
            (const char*)ALg + (size_t)(m0 + lrow)*2048 + kt*32 + lc*16,
            (const char*)BHg + (size_t)(n0 + lrow)*2048 + kt*32 + lc*16,
            (const char*)BLg + (size_t)(n0 + lrow)*2048 + kt*32 + lc*16 };
        const int bases[4] = {G_AH, G_AL, G_BH, G_BL};
#pragma unroll
        for (int i = 0; i < 4; i++)
            cpasync16(sbase + (bases[i] + (b*128 + lrow)*GPW + lc*4)*4, srcs[i]);
        cpcommit();
    };

    ldtile(0, 0);
    ldtile(1, 1);

    for (int kt = 0; kt < 64; kt++) {
        int b = kt % 3;
        if (kt < 63) cpwait<1>(); else cpwait<0>();
        __syncthreads();
        if (kt + 2 < 64) ldtile(kt + 2, (kt + 2) % 3);

        uint32_t aH[2][4], aL[2][4];
#pragma unroll
        for (int mt = 0; mt < 2; mt++) {
            int row = wm*32 + mt*16 + (m2 & 1)*8 + r8;
            uint32_t ad = sbase + (uint32_t)(G_AH + (b*128 + row)*GPW)*4 + (m2 >> 1)*16;
            ldsm4(aH[mt], ad);
            ldsm4(aL[mt], ad + (uint32_t)(G_AL - G_AH)*4);
        }
#pragma unroll
        for (int p = 0; p < 4; p++) {
            int brow = wn*64 + p*16 + ((lane >> 4) & 1)*8 + r8;
            uint32_t bd = sbase + (uint32_t)(G_BH + (b*128 + brow)*GPW)*4 + ((lane >> 3) & 1)*16;
            uint32_t bf[4], bl[4];
            ldsm4(bf, bd);
            ldsm4(bl, bd + (uint32_t)(G_BL - G_BH)*4);
#pragma unroll
            for (int mt = 0; mt < 2; mt++) {
                mma3h(c[mt][2*p],     aH[mt], aL[mt], bf,     bl);
                mma3h(c[mt][2*p + 1], aH[mt], aL[mt], bf + 2, bl + 2);
            }
        }
    }

#pragma unroll
    for (int mt = 0; mt < 2; mt++) {
        int rowg = m0 + wm*32 + mt*16 + g;
#pragma unroll
        for (int nt = 0; nt < 8; nt++) {
            int col = n0 + wn*64 + nt*8 + 2*t;
            float c0 = c[mt][nt][0], c1 = c[mt][nt][1], c2 = c[mt][nt][2], c3 = c[mt][nt][3];
            if (mode == 2) {
                int nn = rowg / rowsPB, r = rowg % rowsPB;
                int hh = col >> 6, ss = col & 63;
                size_t w0 = ((size_t)(nn*HH + hh)*rowsPB + r)*32 + (ss >> 1);
                size_t w1 = w0 + 8*32;
                ((uint32_t*)CHp)[w0] = pack2(c0, c1, false);
                ((uint32_t*)CLp)[w0] = pack2(c0, c1, true);
                ((uint32_t*)CHp)[w1] = pack2(c2, c3, false);
                ((uint32_t*)CLp)[w1] = pack2(c2, c3, true);
            } else if (mode == 1) {
                int nn = rowg / rowsPB, r = rowg % rowsPB;
                int hh = col >> 6, ss = col & 63;
                float* d0 = CF + ((size_t)(nn*HH + hh)*rowsPB + r)*64 + ss;
                float* d1 = CF + ((size_t)(nn*HH + hh)*rowsPB + r + 8)*64 + ss;
                *(float2*)d0 = make_float2(c0, c1);
                *(float2*)d1 = make_float2(c2, c3);
            } else {
                *(float2*)(CF + (size_t)rowg*1024 + col)       = make_float2(c0, c1);
                *(float2*)(CF + (size_t)(rowg + 8)*1024 + col) = make_float2(c2, c3);
            }
        }
    }
}

// ---------------- attention: QT=32, 512 threads, QK hi-only (1 mma), AV 3-mma ----------------
#define OFF_LOG  0
#define OFF_TILE (32*1044*4)                    // 133632
#define OFF_Q    (OFF_TILE + 2*2*128*32*4)      // 199168
#define OFF_MISC (OFF_Q + 4*32*36*4)            // 217600
#define ATTN_SMEM_BYTES (OFF_MISC + 384)

__global__ __launch_bounds__(512) void attn_kernel(
                            const float* __restrict__ Qp, int NQ,
                            const __half* __restrict__ kcHg,
                            const __half* __restrict__ kpHg,
                            const __half* __restrict__ vtHg, const __half* __restrict__ vtLg,
                            const float* __restrict__ segenc,
                            const int* __restrict__ segmat,
                            const float* __restrict__ mask,
                            const float* __restrict__ cb, const float* __restrict__ pb,
                            const float* __restrict__ sb,
                            const int* __restrict__ tpos,
                            __half* outH, __half* outL)
{
    extern __shared__ char asm_[];
    float* logitsF = (float*)(asm_ + OFF_LOG);
    uint32_t* qw  = (uint32_t*)(asm_ + OFF_Q);        // qcH, qpH each 1152 words (hi only used)
    float* seg0 = (float*)(asm_ + OFF_MISC);
    float* seg1 = seg0 + 32;
    int*   qrow = (int*)(seg1 + 32);

    const int n  = blockIdx.z, h = blockIdx.y;
    const int nh = n*HH + h;
    const int q0 = blockIdx.x * QT;
    const int tid = threadIdx.x;
    const int wid = tid >> 5, lane = tid & 31;
    const int g = lane >> 2, t = lane & 3;
    const int m2 = lane >> 3, r8 = lane & 7;
    const int wq = wid >> 3;
    const int wr = wid & 7;
    const uint32_t tbase = smem_u32(asm_ + OFF_TILE);
    const uint32_t qbaseS = smem_u32(qw);
    const uint32_t logb = smem_u32(asm_);

    // ---- QK tile loader: hi only, 1024 chunks; swizzle chunk c ^= r&7 ----
    auto ld_qk = [&](int i, int b){
        const char* sH = (i < 8)
            ? (const char*)kcHg + ((size_t)nh*1024 + (size_t)i*128) * 128
            : (const char*)kpHg + ((size_t)nh*1536 + (size_t)(i-8)*128) * 128;
#pragma unroll
        for (int j = 0; j < 2; j++) {
            int idx = tid + j*512;               // 0..1023
            int row = idx >> 3, c = idx & 7;
            int cc = c ^ (row & 7);
            uint32_t dst = tbase + ((b*128 + row)*32 + cc*4)*4;
            cpasync16(dst, sH + row*128 + c*16);
        }
        cpcommit();
    };
    // ---- V tile loader: hi+lo, [64 s][64 w]; swizzle c ^= s&7 ----
    auto ld_vt = [&](int rt, int b){
#pragma unroll
        for (int j = 0; j < 4; j++) {
            int idx = tid + j*512;
            int grp = idx >> 10;
            int c2 = idx & 1023;
            int s = c2 >> 4, c = c2 & 15;
            int cc = c ^ (s & 7);
            uint32_t dst = tbase + (grp*8192 + (b*64 + s)*64 + cc*4)*4;
            const char* src = (grp ? (const char*)vtLg : (const char*)vtHg)
                              + ((size_t)nh*64 + s)*2048 + rt*256 + c*16;
            cpasync16(dst, src);
        }
        cpcommit();
    };

    // ---- init: q tiles (hi only) in smem; seg dots; qrow ----
    const float* qbase = Qp + ((size_t)nh*NQ + q0)*64;
    {
        int l = tid >> 4, s4 = tid & 15;
        float4 qv = *(const float4*)(qbase + l*64 + s4*4);
        float qa[4] = {qv.x, qv.y, qv.z, qv.w};
        float cbv[4], pbv[4];
#pragma unroll
        for (int i = 0; i < 4; i++) { cbv[i] = cb[h*SS + s4*4 + i]; pbv[i] = pb[h*SS + s4*4 + i]; }
        uint32_t* qcH = qw;
        uint32_t* qpH = qw + 2304;
#pragma unroll
        for (int i = 0; i < 2; i++) {
            float a0 = qa[2*i] + cbv[2*i], a1 = qa[2*i+1] + cbv[2*i+1];
            float p0 = qa[2*i] + pbv[2*i], p1 = qa[2*i+1] + pbv[2*i+1];
            qcH[l*36 + s4*2 + i] = pack2(a0, a1, false);
            qpH[l*36 + s4*2 + i] = pack2(p0, p1, false);
        }
    }
    if (tid < QT) qrow[tid] = tpos ? tpos[n*PPQ + q0 + tid] : (q0 + tid);
    if (tid >= 64 && tid < 64 + 2*QT) {
        int i = tid - 64;
        int l = i >> 1, gg = i & 1;
        float acc = 0.f;
        const float* qr = qbase + l*64;
        const float* se = segenc + ((size_t)gg*HH + h)*SS;
        for (int s = 0; s < SS; s++) acc += (qr[s] + sb[h*SS + s]) * se[s];
        if (gg) seg1[l] = acc; else seg0[l] = acc;
    }

    ld_qk(0, 0);
    __syncthreads();

    const int qp0 = qrow[wq*16 + g], qp1 = qrow[wq*16 + g + 8];

    // ---- QK pipeline: 20 tiles, 2-stage, hi-only mma ----
    for (int i = 0; i < 20; i++) {
        int b = i & 1;
        if (i + 1 < 20) { ld_qk(i + 1, (i + 1) & 1); cpwait<1>(); }
        else            { cpwait<0>(); }
        __syncthreads();

        uint32_t qsel = qbaseS + ((i < 8) ? 0u : 2304u*4);
        float cres[2][4] = {{0,0,0,0},{0,0,0,0}};
#pragma unroll
        for (int ch = 0; ch < 4; ch++) {
            uint32_t aad = qsel + (uint32_t)((wq*16 + (m2 & 1)*8 + r8)*36)*4 + ch*32 + (m2 >> 1)*16;
            uint32_t aH[4];
            ldsm4(aH, aad);
            int brow = wr*16 + ((lane >> 4) & 1)*8 + r8;
            int bch = (2*ch + ((lane >> 3) & 1)) ^ r8;
            uint32_t bad = tbase + (uint32_t)((b*128 + brow)*32 + bch*4)*4;
            uint32_t bf[4];
            ldsm4(bf, bad);
            mma_h(cres[0], aH, bf);
            mma_h(cres[1], aH, bf + 2);
        }
        if (i < 8) {
#pragma unroll
            for (int j = 0; j < 2; j++) {
                int base = i*128 + wr*16 + j*8 + 2*t;
                logitsF[(wq*16 + g    )*1044 + base]     = cres[j][0];
                logitsF[(wq*16 + g    )*1044 + base + 1] = cres[j][1];
                logitsF[(wq*16 + g + 8)*1044 + base]     = cres[j][2];
                logitsF[(wq*16 + g + 8)*1044 + base + 1] = cres[j][3];
            }
        } else {
            int pt = i - 8;
#pragma unroll
            for (int j = 0; j < 2; j++) {
                int pp = pt*128 + wr*16 + j*8 + 2*t;
                int r;
                r = pp     - 512 + qp0; if (r >= 0 && r < RR) logitsF[(wq*16 + g    )*1044 + r] += cres[j][0];
                r = pp + 1 - 512 + qp0; if (r >= 0 && r < RR) logitsF[(wq*16 + g    )*1044 + r] += cres[j][1];
                r = pp     - 512 + qp1; if (r >= 0 && r < RR) logitsF[(wq*16 + g + 8)*1044 + r] += cres[j][2];
                r = pp + 1 - 512 + qp1; if (r >= 0 && r < RR) logitsF[(wq*16 + g + 8)*1044 + r] += cres[j][3];
            }
        }
        __syncthreads();
    }

    // prefetch first V tile under softmax/conversion
    ld_vt(0, 0);

    // ---- softmax: 16 threads per row, 32 rows ----
    {
        int row = tid >> 4, l16 = tid & 15;
        int qq = qrow[row];
        const float* mrow = mask + ((size_t)n*QQ + qq)*RR;
        const int* srow = segmat + ((size_t)n*QQ + qq)*RR;
        float s1v = seg1[row], s0v = seg0[row];
        float* lrow = logitsF + row*1044;
        float mx = -3.4e38f;
        for (int i = 0; i < 64; i++) {
            int cc = l16 + 16*i;
            float lg = lrow[cc] + (srow[cc] ? s1v : s0v);
            lg = lg * 0.125f + mrow[cc] * (-1e9f);
            lrow[cc] = lg;
            mx = fmaxf(mx, lg);
        }
        for (int o = 8; o; o >>= 1) mx = fmaxf(mx, __shfl_xor_sync(0xffffffffu, mx, o, 16));
        float sum = 0.f;
        for (int i = 0; i < 64; i++) {
            int cc = l16 + 16*i;
            float e = __expf(lrow[cc] - mx);
            lrow[cc] = e;
            sum += e;
        }
        for (int o = 8; o; o >>= 1) sum += __shfl_xor_sync(0xffffffffu, sum, o, 16);
        float inv = __fdividef(1.f, sum);
        for (int i = 0; i < 64; i++) lrow[l16 + 16*i] *= inv;
    }
    __syncthreads();

    // ---- logits fp32 -> halves in place (hi +0, lo +2048 per 4176 B row) ----
    {
        int rsub = tid >> 6;
        int c0 = (tid & 63) * 16;
        for (int p = 0; p < 4; p++) {
            int row = p*8 + rsub;
            const float* src = logitsF + row*1044;
            float v[16];
#pragma unroll
            for (int i = 0; i < 4; i++) {
                float4 f = *(const float4*)(src + c0 + i*4);
                v[4*i] = f.x; v[4*i+1] = f.y; v[4*i+2] = f.z; v[4*i+3] = f.w;
            }
            __syncthreads();
            uint32_t* wh = (uint32_t*)(asm_ + row*4176);
            uint32_t* wl = (uint32_t*)(asm_ + row*4176 + 2048);
#pragma unroll
            for (int i = 0; i < 8; i++) {
                wh[c0/2 + i] = pack2(v[2*i], v[2*i+1], false);
                wl[c0/2 + i] = pack2(v[2*i], v[2*i+1], true);
            }
            __syncthreads();
        }
    }

    // ---- Phase B: out = weights @ V, 2-stage over 8 tiles, 3-mma ----
    {
        float ca[4] = {0,0,0,0}, cbn[4] = {0,0,0,0};
        for (int rt = 0; rt < 8; rt++) {
            int b = rt & 1;
            if (rt + 1 < 8) { ld_vt(rt + 1, (rt + 1) & 1); cpwait<1>(); }
            else            { cpwait<0>(); }
            __syncthreads();
#pragma unroll
            for (int ch = 0; ch < 8; ch++) {
                int kw = rt*64 + ch*8;
                uint32_t aad = logb + (uint32_t)((wq*16 + (m2 & 1)*8 + r8)*4176) + kw*4 + (m2 >> 1)*16;
                uint32_t aH[4], aL[4];
                ldsm4(aH, aad);
                ldsm4(aL, aad + 2048);
                int srow = wr*8 + r8;
                int vch = (2*ch + ((lane >> 3) & 1)) ^ r8;
                uint32_t bad = tbase + (uint32_t)((b*64 + srow)*64 + vch*4)*4;
                uint32_t bH2[2], bL2[2];
                ldsm2(bH2, bad);
                ldsm2(bL2, bad + 8192u*4);
                mma3h((ch & 1) ? cbn : ca, aH, aL, bH2, bL2);
            }
            __syncthreads();
        }
#pragma unroll
        for (int l = 0; l < 4; l++) ca[l] += cbn[l];
        size_t w0 = ((size_t)(n*NQ + q0 + wq*16 + g    ))*512 + h*32 + wr*4 + t;
        size_t w1 = ((size_t)(n*NQ + q0 + wq*16 + g + 8))*512 + h*32 + wr*4 + t;
        ((uint32_t*)outH)[w0] = pack2(ca[0], ca[1], false);
        ((uint32_t*)outL)[w0] = pack2(ca[0], ca[1], true);
        ((uint32_t*)outH)[w1] = pack2(ca[2], ca[3], false);
        ((uint32_t*)outL)[w1] = pack2(ca[2], ca[3], true);
    }
}

// -------------------- launch --------------------
extern "C" void kernel_launch(void* const* d_in, const int* in_sizes, int n_in,
                              void* d_out, int out_size)
{
    const float* content = (const float*)d_in[0];
    const float* query   = (const float*)d_in[1];
    const float* posenc  = (const float*)d_in[2];
    const float* segenc  = (const float*)d_in[3];
    const int*   segmat  = (const int*)d_in[4];
    const float* tmap    = (const float*)d_in[5];
    const float* cmask   = (const float*)d_in[6];
    const float* qmask   = (const float*)d_in[7];
    const float* cb      = (const float*)d_in[8];
    const float* pb      = (const float*)d_in[9];
    const float* sb      = (const float*)d_in[10];
    const float* mems    = (const float*)d_in[11];
    const float* Wq      = (const float*)d_in[12];
    const float* Wkc     = (const float*)d_in[13];
    const float* Wv      = (const float*)d_in[14];
    const float* Wkp     = (const float*)d_in[15];
    const float* Wo      = (const float*)d_in[16];
    float* out = (float*)d_out;

    __half *ctxH, *ctxL, *posH, *posL, *conH, *conL, *qryH, *qryL, *wH, *wL;
    __half *kcH, *kcL, *kpH, *kpL, *vtH, *vtL, *acH, *acL, *aqH, *aqL;
    float *pv, *pqc, *pqq;
    int* ptpos;
    cudaGetSymbolAddress((void**)&ctxH, g_ctxH); cudaGetSymbolAddress((void**)&ctxL, g_ctxL);
    cudaGetSymbolAddress((void**)&posH, g_posH); cudaGetSymbolAddress((void**)&posL, g_posL);
    cudaGetSymbolAddress((void**)&conH, g_conH); cudaGetSymbolAddress((void**)&conL, g_conL);
    cudaGetSymbolAddress((void**)&qryH, g_qryH); cudaGetSymbolAddress((void**)&qryL, g_qryL);
    cudaGetSymbolAddress((void**)&wH,   g_wH);   cudaGetSymbolAddress((void**)&wL,   g_wL);
    cudaGetSymbolAddress((void**)&kcH,  g_kcH);  cudaGetSymbolAddress((void**)&kcL,  g_kcL);
    cudaGetSymbolAddress((void**)&kpH,  g_kpH);  cudaGetSymbolAddress((void**)&kpL,  g_kpL);
    cudaGetSymbolAddress((void**)&vtH,  g_vtH);  cudaGetSymbolAddress((void**)&vtL,  g_vtL);
    cudaGetSymbolAddress((void**)&acH,  g_acH);  cudaGetSymbolAddress((void**)&acL,  g_acL);
    cudaGetSymbolAddress((void**)&aqH,  g_aqH);  cudaGetSymbolAddress((void**)&aqL,  g_aqL);
    cudaGetSymbolAddress((void**)&pv,   g_v);
    cudaGetSymbolAddress((void**)&pqc,  g_qc);
    cudaGetSymbolAddress((void**)&pqq,  g_qq);
    cudaGetSymbolAddress((void**)&ptpos, g_tpos);

    cudaFuncSetAttribute(gemm_h, cudaFuncAttributeMaxDynamicSharedMemorySize, GEMM_SMEM);
    cudaFuncSetAttribute(attn_kernel, cudaFuncAttributeMaxDynamicSharedMemorySize, ATTN_SMEM_BYTES);

    // converts
    build_ctx_split<<<4096, 256>>>(mems, content);
    split_k<<<6144, 256>>>(posenc,  posH, posL, BB*RP*HID/4);
    split_k<<<2048, 256>>>(content, conH, conL, BB*QQ*HID/4);
    split_k<<<512,  256>>>(query,   qryH, qryL, BB*PPQ*HID/4);
    dim3 wtb(32, 8), wtg(32, 32);
    wtrans<<<wtg, wtb>>>(Wq,  wH + 0*(size_t)HID*HID, wL + 0*(size_t)HID*HID);
    wtrans<<<wtg, wtb>>>(Wkc, wH + 1*(size_t)HID*HID, wL + 1*(size_t)HID*HID);
    wtrans<<<wtg, wtb>>>(Wv,  wH + 2*(size_t)HID*HID, wL + 2*(size_t)HID*HID);
    wtrans<<<wtg, wtb>>>(Wkp, wH + 3*(size_t)HID*HID, wL + 3*(size_t)HID*HID);
    wtrans<<<wtg, wtb>>>(Wo,  wH + 4*(size_t)HID*HID, wL + 4*(size_t)HID*HID);
    find_tpos<<<1, 512>>>(tmap);

    __half* wq_H = wH + 0*(size_t)HID*HID; __half* wq_L = wL + 0*(size_t)HID*HID;
    __half* wkcH = wH + 1*(size_t)HID*HID; __half* wkcL = wL + 1*(size_t)HID*HID;
    __half* wv_H = wH + 2*(size_t)HID*HID; __half* wv_L = wL + 2*(size_t)HID*HID;
    __half* wkpH = wH + 3*(size_t)HID*HID; __half* wkpL = wL + 3*(size_t)HID*HID;
    __half* wo_H = wH + 4*(size_t)HID*HID; __half* wo_L = wL + 4*(size_t)HID*HID;

    gemm_h<<<dim3(8, 32), 256, GEMM_SMEM>>>(ctxH, ctxL, wkcH, wkcL, nullptr, kcH, kcL, RR,  2);
    gemm_h<<<dim3(8, 32), 256, GEMM_SMEM>>>(ctxH, ctxL, wv_H, wv_L, pv, nullptr, nullptr, RR, 1);
    gemm_h<<<dim3(8, 48), 256, GEMM_SMEM>>>(posH, posL, wkpH, wkpL, nullptr, kpH, kpL, RP,  2);
    gemm_h<<<dim3(8, 16), 256, GEMM_SMEM>>>(conH, conL, wq_H, wq_L, pqc, nullptr, nullptr, QQ, 1);
    gemm_h<<<dim3(8, 4),  256, GEMM_SMEM>>>(qryH, qryL, wq_H, wq_L, pqq, nullptr, nullptr, PPQ, 1);
    vtrans<<<NHDIM*8, 256>>>();

    dim3 gac(QQ/QT, HH, BB);
    attn_kernel<<<gac, 512, ATTN_SMEM_BYTES>>>(pqc, QQ, kcH, kpH, vtH, vtL,
                                               segenc, segmat, cmask, cb, pb, sb, nullptr, acH, acL);
    dim3 gaq(PPQ/QT, HH, BB);
    attn_kernel<<<gaq, 512, ATTN_SMEM_BYTES>>>(pqq, PPQ, kcH, kpH, vtH, vtL,
                                               segenc, segmat, qmask, cb, pb, sb, ptpos, aqH, aqL);

    gemm_h<<<dim3(8, 16), 256, GEMM_SMEM>>>(acH, acL, wo_H, wo_L, out, nullptr, nullptr, 0, 0);
    gemm_h<<<dim3(8, 4),  256, GEMM_SMEM>>>(aqH, aqL, wo_H, wo_L, out + (size_t)BB*QQ*HID, nullptr, nullptr, 0, 0);
}